// round 1
// baseline (speedup 1.0000x reference)
#include <cuda_runtime.h>
#include <math.h>

// ---------------------------------------------------------------------------
// AFNO2D: out = x + fuse_w @ (x + irfft2(D)),   D = masked_MLP(Z) - Z on the
// 64x33 low-frequency region of Z = rfft2(x, ortho).  Everything outside the
// mask cancels by linearity of irfft2.
// Shapes: x (4,512,128,128) fp32.  Blocks: 8 x 64 channels.
// ---------------------------------------------------------------------------

#define BB   4
#define CC   512
#define HH   128
#define WW   128
#define MH   64          // masked rows  (k)
#define MW   33          // masked cols  (m)
#define NPOS (MH*MW)     // 2112 frequency positions per batch
#define NBQ  8
#define BSQ  64
#define LAMBDA 0.01f
#define TWO_PI 6.28318530717958647692f

// Scratch (allocation-free rule: device globals)
__device__ float g_Zr[(size_t)BB*NPOS*CC];
__device__ float g_Zi[(size_t)BB*NPOS*CC];
__device__ float g_Dr[(size_t)BB*NPOS*CC];
__device__ float g_Di[(size_t)BB*NPOS*CC];
__device__ float g_u [(size_t)BB*CC*HH*WW];

// ---------------------------------------------------------------------------
// K1: forward restricted rfft2 per image -> Z on 64x33 region, scaled 1/128
// Row stage: mid[h][m] = sum_x img[h][x] e^{-2pi i x m/128}, m<33
// Col stage: Z[k][m]   = sum_h mid[h][m] e^{-2pi i h k/128}, k<64
// ---------------------------------------------------------------------------
__global__ __launch_bounds__(512) void k_fwd(const float* __restrict__ x)
{
    extern __shared__ float sm[];
    float* img  = sm;                 // 16384
    float* midr = img  + 16384;       // 4224 (128*33)
    float* midi = midr + 4224;        // 4224
    float* ct   = midi + 4224;        // 128
    float* st   = ct   + 128;         // 128

    const int t      = threadIdx.x;
    const int img_id = blockIdx.x;
    const int b      = img_id >> 9;
    const int c      = img_id & 511;
    const float* src = x + (size_t)img_id * 16384;

    for (int i = t; i < 16384; i += 512) img[i] = src[i];
    if (t < 128) {
        float sv, cv;
        sincosf(TWO_PI * (float)t * (1.0f/128.0f), &sv, &cv);
        ct[t] = cv; st[t] = sv;
    }
    __syncthreads();

    // row stage: twiddle via register rotation recurrence (no smem gathers)
    for (int o = t; o < 4224; o += 512) {
        const int h = o / 33;
        const int m = o - h*33;
        const float* row = img + (h << 7);
        const float cm = ct[m], smv = st[m];      // rotate by e^{-2pi i m/128}
        float cc = 1.0f, ss = 0.0f;               // current e^{-2pi i m x/128}: (Re,Im)
        float ar = 0.0f, ai = 0.0f;
        #pragma unroll 8
        for (int xx = 0; xx < 128; ++xx) {
            float v = row[xx];
            ar = fmaf(v, cc, ar);
            ai = fmaf(v, ss, ai);
            float nc = fmaf(cc, cm,  ss*smv);     // (cc+i ss)*(cm - i smv)
            float ns = fmaf(ss, cm, -cc*smv);
            cc = nc; ss = ns;
        }
        midr[o] = ar; midi[o] = ai;
    }
    __syncthreads();

    // column stage: table lookups broadcast across the warp (index depends on k,h only)
    const size_t base = ((size_t)b * NPOS) * CC + c;
    for (int o = t; o < NPOS; o += 512) {
        const int k = o / 33;
        const int m = o - k*33;
        float ar = 0.0f, ai = 0.0f;
        int idx = 0;
        #pragma unroll 8
        for (int h = 0; h < 128; ++h) {
            float mr = midr[h*33 + m];
            float mi = midi[h*33 + m];
            float cc = ct[idx], ss = st[idx];     // e^{-i th}: (cc, -ss)
            ar = fmaf(mr, cc, fmaf( mi, ss, ar));
            ai = fmaf(mi, cc, fmaf(-mr, ss, ai));
            idx = (idx + k) & 127;
        }
        g_Zr[base + (size_t)o * CC] = ar * (1.0f/128.0f);
        g_Zi[base + (size_t)o * CC] = ai * (1.0f/128.0f);
    }
}

// ---------------------------------------------------------------------------
// K2: block-diagonal complex MLP per frequency position.
// grid (264 tiles of 32 positions, 8 blocks). Weights resident in smem.
// ---------------------------------------------------------------------------
__global__ __launch_bounds__(512) void k_mlp(
    const float* __restrict__ w1r_g, const float* __restrict__ w1i_g,
    const float* __restrict__ b1r_g, const float* __restrict__ b1i_g,
    const float* __restrict__ w2r_g, const float* __restrict__ w2i_g,
    const float* __restrict__ b2r_g, const float* __restrict__ b2i_g)
{
    extern __shared__ float sm[];
    float* w1r = sm;             // 4096 each
    float* w1i = w1r + 4096;
    float* w2r = w1i + 4096;
    float* w2i = w2r + 4096;
    float* zr  = w2i + 4096;     // 2048 each (32 pos x 64)
    float* zi  = zr  + 2048;
    float* hr  = zi  + 2048;
    float* hi  = hr  + 2048;
    float* bbv = hi  + 2048;     // 256: b1r,b1i,b2r,b2i

    const int t  = threadIdx.x;
    const int n  = blockIdx.y;
    const int P0 = blockIdx.x * 32;

    for (int i = t; i < 4096; i += 512) {
        w1r[i] = w1r_g[n*4096 + i];
        w1i[i] = w1i_g[n*4096 + i];
        w2r[i] = w2r_g[n*4096 + i];
        w2i[i] = w2i_g[n*4096 + i];
    }
    if (t < 64) {
        bbv[t]       = b1r_g[n*64 + t];
        bbv[64 + t]  = b1i_g[n*64 + t];
        bbv[128 + t] = b2r_g[n*64 + t];
        bbv[192 + t] = b2i_g[n*64 + t];
    }
    for (int idx = t; idx < 2048; idx += 512) {
        int p = idx >> 6, i = idx & 63;
        int P = P0 + p;
        int b = P / NPOS;
        int pos = P - b * NPOS;
        size_t g = ((size_t)b * NPOS + pos) * CC + n*64 + i;
        zr[idx] = g_Zr[g];
        zi[idx] = g_Zi[g];
    }
    __syncthreads();

    const int j  = t & 63;
    const int pb = t >> 6;   // 0..7

    // layer 1 + exact gelu
    for (int r = 0; r < 4; ++r) {
        int p = pb + (r << 3);
        const float* zpr = zr + (p << 6);
        const float* zpi = zi + (p << 6);
        float ar = bbv[j], ai = bbv[64 + j];
        #pragma unroll 8
        for (int i = 0; i < 64; ++i) {
            float a = zpr[i], bq = zpi[i];
            float wr = w1r[(i << 6) + j], wi = w1i[(i << 6) + j];
            ar = fmaf(a, wr, fmaf(-bq, wi, ar));
            ai = fmaf(a, wi, fmaf( bq, wr, ai));
        }
        ar = 0.5f * ar * (1.0f + erff(ar * 0.70710678118654752f));
        ai = 0.5f * ai * (1.0f + erff(ai * 0.70710678118654752f));
        hr[(p << 6) + j] = ar;
        hi[(p << 6) + j] = ai;
    }
    __syncthreads();

    // layer 2 + softshrink + D = y - z
    for (int r = 0; r < 4; ++r) {
        int p = pb + (r << 3);
        const float* hpr = hr + (p << 6);
        const float* hpi = hi + (p << 6);
        float ar = bbv[128 + j], ai = bbv[192 + j];
        #pragma unroll 8
        for (int i = 0; i < 64; ++i) {
            float a = hpr[i], bq = hpi[i];
            float wr = w2r[(i << 6) + j], wi = w2i[(i << 6) + j];
            ar = fmaf(a, wr, fmaf(-bq, wi, ar));
            ai = fmaf(a, wi, fmaf( bq, wr, ai));
        }
        float sr = fabsf(ar) - LAMBDA; ar = (sr > 0.0f) ? copysignf(sr, ar) : 0.0f;
        float si = fabsf(ai) - LAMBDA; ai = (si > 0.0f) ? copysignf(si, ai) : 0.0f;

        int P = P0 + p;
        int b = P / NPOS;
        int pos = P - b * NPOS;
        size_t g = ((size_t)b * NPOS + pos) * CC + n*64 + j;
        g_Dr[g] = ar - zr[(p << 6) + j];
        g_Di[g] = ai - zi[(p << 6) + j];
    }
}

// ---------------------------------------------------------------------------
// K3: u = x + irfft2_ortho(D) per image.
// Stage 1: G[h][m] = sum_{k<64} D[k][m] e^{+2pi i k h/128}   (D[:,0] pre-halved)
// Stage 2: u[h][x] = x[h][x] + (2/128) sum_{m<33} Re(G[h][m] e^{+2pi i m x/128})
// ---------------------------------------------------------------------------
__global__ __launch_bounds__(512) void k_inv(const float* __restrict__ x)
{
    extern __shared__ float sm[];
    float* dr = sm;              // 2112
    float* di = dr + 2112;       // 2112
    float* Gr = di + 2112;       // 4224
    float* Gi = Gr + 4224;       // 4224
    float* ct = Gi + 4224;       // 128
    float* st = ct + 128;        // 128

    const int t      = threadIdx.x;
    const int img_id = blockIdx.x;
    const int b      = img_id >> 9;
    const int c      = img_id & 511;

    if (t < 128) {
        float sv, cv;
        sincosf(TWO_PI * (float)t * (1.0f/128.0f), &sv, &cv);
        ct[t] = cv; st[t] = sv;
    }
    const size_t base = ((size_t)b * NPOS) * CC + c;
    for (int o = t; o < NPOS; o += 512) {
        float a  = g_Dr[base + (size_t)o * CC];
        float bq = g_Di[base + (size_t)o * CC];
        int m = o % 33;
        if (m == 0) { a *= 0.5f; bq *= 0.5f; }   // DC column counted once
        dr[o] = a; di[o] = bq;
    }
    __syncthreads();

    for (int o = t; o < 4224; o += 512) {
        const int h = o / 33;
        const int m = o - h*33;
        float gr = 0.0f, gi = 0.0f;
        int idx = 0;
        #pragma unroll 8
        for (int k = 0; k < 64; ++k) {
            float ar = dr[k*33 + m];
            float ai = di[k*33 + m];
            float cc = ct[idx], ss = st[idx];    // e^{+i th}
            gr = fmaf(ar, cc, fmaf(-ai, ss, gr));
            gi = fmaf(ar, ss, fmaf( ai, cc, gi));
            idx = (idx + h) & 127;
        }
        Gr[o] = gr; Gi[o] = gi;
    }
    __syncthreads();

    const float* xim = x   + (size_t)img_id * 16384;
    float*       uim = g_u + (size_t)img_id * 16384;
    for (int o = t; o < 16384; o += 512) {
        const int h  = o >> 7;
        const int xx = o & 127;
        const float* gpr = Gr + h*33;
        const float* gpi = Gi + h*33;
        const float cx = ct[xx], sx = st[xx];    // rotate by e^{+2pi i xx/128}
        float cc = 1.0f, ss = 0.0f;
        float acc = 0.0f;
        #pragma unroll
        for (int m = 0; m < 33; ++m) {
            acc = fmaf(gpr[m], cc, fmaf(-gpi[m], ss, acc));
            float nc = fmaf(cc, cx, -ss*sx);
            float ns = fmaf(ss, cx,  cc*sx);
            cc = nc; ss = ns;
        }
        uim[o] = xim[o] + acc * (2.0f/128.0f);
    }
}

// ---------------------------------------------------------------------------
// K4: out[b][o][s] = x[b][o][s] + sum_c fuse_w[o][c] * u[b][c][s]
// Classic 128x128 tiled fp32 SGEMM, 256 threads, 8x8 per thread, BK=8.
// ---------------------------------------------------------------------------
#define GBM 128
#define GBN 128
#define GBK 8
__global__ __launch_bounds__(256) void k_gemm(
    const float* __restrict__ fw, const float* __restrict__ x,
    float* __restrict__ out)
{
    __shared__ float As[GBK][GBM];   // As[k][m] = fw[m0+m][k0+k]
    __shared__ float Bs[GBK][GBN];   // Bs[k][n] = u[b][k0+k][n0+n]

    const int t  = threadIdx.x;
    const int b  = blockIdx.z;
    const int m0 = blockIdx.y * GBM;
    const int n0 = blockIdx.x * GBN;
    const float* Bbase = g_u + ((size_t)b * CC) * 16384;

    const int arow = t >> 1;
    const int ak4  = (t & 1) * 4;
    const int bkr  = t >> 5;
    const int bn4  = (t & 31) * 4;
    const int tm0  = (t >> 4) * 8;
    const int tn0  = (t & 15) * 8;

    float acc[8][8];
    #pragma unroll
    for (int i = 0; i < 8; ++i)
        #pragma unroll
        for (int j = 0; j < 8; ++j) acc[i][j] = 0.0f;

    for (int k0 = 0; k0 < CC; k0 += GBK) {
        float4 av = *(const float4*)(fw    + (size_t)(m0 + arow) * CC    + k0 + ak4);
        float4 bv = *(const float4*)(Bbase + (size_t)(k0 + bkr) * 16384 + n0 + bn4);
        __syncthreads();
        As[ak4 + 0][arow] = av.x;
        As[ak4 + 1][arow] = av.y;
        As[ak4 + 2][arow] = av.z;
        As[ak4 + 3][arow] = av.w;
        *(float4*)&Bs[bkr][bn4] = bv;
        __syncthreads();
        #pragma unroll
        for (int kk = 0; kk < GBK; ++kk) {
            float a[8], bq[8];
            *(float4*)(a)      = *(const float4*)&As[kk][tm0];
            *(float4*)(a + 4)  = *(const float4*)&As[kk][tm0 + 4];
            *(float4*)(bq)     = *(const float4*)&Bs[kk][tn0];
            *(float4*)(bq + 4) = *(const float4*)&Bs[kk][tn0 + 4];
            #pragma unroll
            for (int i = 0; i < 8; ++i)
                #pragma unroll
                for (int j = 0; j < 8; ++j)
                    acc[i][j] = fmaf(a[i], bq[j], acc[i][j]);
        }
    }

    #pragma unroll
    for (int i = 0; i < 8; ++i) {
        size_t ro = ((size_t)(b * CC) + m0 + tm0 + i) * 16384 + n0 + tn0;
        float4 x0 = *(const float4*)(x + ro);
        float4 x1 = *(const float4*)(x + ro + 4);
        float4 o0 = { x0.x + acc[i][0], x0.y + acc[i][1],
                      x0.z + acc[i][2], x0.w + acc[i][3] };
        float4 o1 = { x1.x + acc[i][4], x1.y + acc[i][5],
                      x1.z + acc[i][6], x1.w + acc[i][7] };
        *(float4*)(out + ro)     = o0;
        *(float4*)(out + ro + 4) = o1;
    }
}

// ---------------------------------------------------------------------------
#define SMEM_FWD ((16384 + 2*4224 + 256) * 4)   // 100352
#define SMEM_MLP ((4*4096 + 4*2048 + 256) * 4)  // 99328
#define SMEM_INV ((2*2112 + 2*4224 + 256) * 4)  // 51712

extern "C" void kernel_launch(void* const* d_in, const int* in_sizes, int n_in,
                              void* d_out, int out_size)
{
    const float* x   = (const float*)d_in[0];
    const float* w1r = (const float*)d_in[1];
    const float* w1i = (const float*)d_in[2];
    const float* b1r = (const float*)d_in[3];
    const float* b1i = (const float*)d_in[4];
    const float* w2r = (const float*)d_in[5];
    const float* w2i = (const float*)d_in[6];
    const float* b2r = (const float*)d_in[7];
    const float* b2i = (const float*)d_in[8];
    const float* fw  = (const float*)d_in[9];
    float* out = (float*)d_out;

    cudaFuncSetAttribute(k_fwd, cudaFuncAttributeMaxDynamicSharedMemorySize, SMEM_FWD);
    cudaFuncSetAttribute(k_mlp, cudaFuncAttributeMaxDynamicSharedMemorySize, SMEM_MLP);
    cudaFuncSetAttribute(k_inv, cudaFuncAttributeMaxDynamicSharedMemorySize, SMEM_INV);

    k_fwd<<<BB*CC, 512, SMEM_FWD>>>(x);

    dim3 g2((BB * NPOS) / 32, NBQ);
    k_mlp<<<g2, 512, SMEM_MLP>>>(w1r, w1i, b1r, b1i, w2r, w2i, b2r, b2i);

    k_inv<<<BB*CC, 512, SMEM_INV>>>(x);

    dim3 g4(16384 / GBN, CC / GBM, BB);
    k_gemm<<<g4, 256>>>(fw, x, out);
}

// round 3
// speedup vs baseline: 1.9841x; 1.9841x over previous
#include <cuda_runtime.h>
#include <cuda_bf16.h>
#include <math.h>
#include <stdint.h>

// ---------------------------------------------------------------------------
// AFNO2D: out = x + fuse_w @ (x + irfft2(D)),   D = masked_MLP(Z) - Z on the
// 64x33 low-frequency region of Z = rfft2(x, ortho).
// K1 fwd restricted DFT -> K2 block MLP -> K3 inv DFT (emits u as bf16 hi/lo)
// -> K4 HMMA (mma.sync bf16) GEMM with hi/lo compensation, fused +x residual.
// (tcgen05 unavailable: harness PTX target is plain sm_103.)
// ---------------------------------------------------------------------------

#define BB   4
#define CC   512
#define HH   128
#define WW   128
#define MH   64
#define MW   33
#define NPOS (MH*MW)
#define NBQ  8
#define LAMBDA 0.01f
#define TWO_PI 6.28318530717958647692f

// Scratch (allocation-free rule: device globals)
__device__ float g_Zr[(size_t)BB*NPOS*CC];
__device__ float g_Zi[(size_t)BB*NPOS*CC];
__device__ float g_Dr[(size_t)BB*NPOS*CC];
__device__ float g_Di[(size_t)BB*NPOS*CC];
__device__ __nv_bfloat16 g_uh[(size_t)BB*CC*HH*WW];   // u hi  [b][c][s]
__device__ __nv_bfloat16 g_ul[(size_t)BB*CC*HH*WW];   // u lo  [b][c][s]
__device__ __nv_bfloat16 g_fwh[(size_t)CC*CC];        // fw hi [o][c]
__device__ __nv_bfloat16 g_fwl[(size_t)CC*CC];        // fw lo [o][c]

// ======================= helpers =============================
__device__ __forceinline__ uint32_t smem_u32(const void* p) {
    uint32_t a;
    asm("{ .reg .u64 t; cvta.to.shared.u64 t, %1; cvt.u32.u64 %0, t; }"
        : "=r"(a) : "l"(p));
    return a;
}
#define CP16(dst, src) \
    asm volatile("cp.async.cg.shared.global [%0], [%1], 16;" \
        :: "r"(dst), "l"(src) : "memory")
#define CP_COMMIT() asm volatile("cp.async.commit_group;" ::: "memory")
#define CP_WAIT(n)  asm volatile("cp.async.wait_group %0;" :: "n"(n) : "memory")

#define LDSM4(R, a) \
    asm volatile("ldmatrix.sync.aligned.m8n8.x4.shared.b16 {%0,%1,%2,%3}, [%4];" \
        : "=r"((R)[0]), "=r"((R)[1]), "=r"((R)[2]), "=r"((R)[3]) : "r"(a))
#define LDSM4T(R, a) \
    asm volatile("ldmatrix.sync.aligned.m8n8.x4.trans.shared.b16 {%0,%1,%2,%3}, [%4];" \
        : "=r"((R)[0]), "=r"((R)[1]), "=r"((R)[2]), "=r"((R)[3]) : "r"(a))
#define MMA_BF16(C, A, B0, B1) \
    asm volatile("mma.sync.aligned.m16n8k16.row.col.f32.bf16.bf16.f32 " \
        "{%0,%1,%2,%3},{%4,%5,%6,%7},{%8,%9},{%0,%1,%2,%3};" \
        : "+f"((C)[0]), "+f"((C)[1]), "+f"((C)[2]), "+f"((C)[3]) \
        : "r"((A)[0]), "r"((A)[1]), "r"((A)[2]), "r"((A)[3]), "r"(B0), "r"(B1))

// ---------------------------------------------------------------------------
// K1: forward restricted rfft2 per image -> Z on 64x33 region, scaled 1/128
// ---------------------------------------------------------------------------
__global__ __launch_bounds__(512) void k_fwd(const float* __restrict__ x)
{
    extern __shared__ float sm[];
    float* img  = sm;
    float* midr = img  + 16384;
    float* midi = midr + 4224;
    float* ct   = midi + 4224;
    float* st   = ct   + 128;

    const int t      = threadIdx.x;
    const int img_id = blockIdx.x;
    const int b      = img_id >> 9;
    const int c      = img_id & 511;
    const float* src = x + (size_t)img_id * 16384;

    for (int i = t; i < 16384; i += 512) img[i] = src[i];
    if (t < 128) {
        float sv, cv;
        sincosf(TWO_PI * (float)t * (1.0f/128.0f), &sv, &cv);
        ct[t] = cv; st[t] = sv;
    }
    __syncthreads();

    for (int o = t; o < 4224; o += 512) {
        const int h = o / 33;
        const int m = o - h*33;
        const float* row = img + (h << 7);
        const float cm = ct[m], smv = st[m];
        float cc = 1.0f, ss = 0.0f;
        float ar = 0.0f, ai = 0.0f;
        #pragma unroll 8
        for (int xx = 0; xx < 128; ++xx) {
            float v = row[xx];
            ar = fmaf(v, cc, ar);
            ai = fmaf(v, ss, ai);
            float nc = fmaf(cc, cm,  ss*smv);
            float ns = fmaf(ss, cm, -cc*smv);
            cc = nc; ss = ns;
        }
        midr[o] = ar; midi[o] = ai;
    }
    __syncthreads();

    const size_t base = ((size_t)b * NPOS) * CC + c;
    for (int o = t; o < NPOS; o += 512) {
        const int k = o / 33;
        const int m = o - k*33;
        float ar = 0.0f, ai = 0.0f;
        int idx = 0;
        #pragma unroll 8
        for (int h = 0; h < 128; ++h) {
            float mr = midr[h*33 + m];
            float mi = midi[h*33 + m];
            float cc = ct[idx], ss = st[idx];
            ar = fmaf(mr, cc, fmaf( mi, ss, ar));
            ai = fmaf(mi, cc, fmaf(-mr, ss, ai));
            idx = (idx + k) & 127;
        }
        g_Zr[base + (size_t)o * CC] = ar * (1.0f/128.0f);
        g_Zi[base + (size_t)o * CC] = ai * (1.0f/128.0f);
    }
}

// ---------------------------------------------------------------------------
// K2: block-diagonal complex MLP per frequency position.
// ---------------------------------------------------------------------------
__global__ __launch_bounds__(512) void k_mlp(
    const float* __restrict__ w1r_g, const float* __restrict__ w1i_g,
    const float* __restrict__ b1r_g, const float* __restrict__ b1i_g,
    const float* __restrict__ w2r_g, const float* __restrict__ w2i_g,
    const float* __restrict__ b2r_g, const float* __restrict__ b2i_g)
{
    extern __shared__ float sm[];
    float* w1r = sm;
    float* w1i = w1r + 4096;
    float* w2r = w1i + 4096;
    float* w2i = w2r + 4096;
    float* zr  = w2i + 4096;
    float* zi  = zr  + 2048;
    float* hr  = zi  + 2048;
    float* hi  = hr  + 2048;
    float* bbv = hi  + 2048;

    const int t  = threadIdx.x;
    const int n  = blockIdx.y;
    const int P0 = blockIdx.x * 32;

    for (int i = t; i < 4096; i += 512) {
        w1r[i] = w1r_g[n*4096 + i];
        w1i[i] = w1i_g[n*4096 + i];
        w2r[i] = w2r_g[n*4096 + i];
        w2i[i] = w2i_g[n*4096 + i];
    }
    if (t < 64) {
        bbv[t]       = b1r_g[n*64 + t];
        bbv[64 + t]  = b1i_g[n*64 + t];
        bbv[128 + t] = b2r_g[n*64 + t];
        bbv[192 + t] = b2i_g[n*64 + t];
    }
    for (int idx = t; idx < 2048; idx += 512) {
        int p = idx >> 6, i = idx & 63;
        int P = P0 + p;
        int b = P / NPOS;
        int pos = P - b * NPOS;
        size_t g = ((size_t)b * NPOS + pos) * CC + n*64 + i;
        zr[idx] = g_Zr[g];
        zi[idx] = g_Zi[g];
    }
    __syncthreads();

    const int j  = t & 63;
    const int pb = t >> 6;

    for (int r = 0; r < 4; ++r) {
        int p = pb + (r << 3);
        const float* zpr = zr + (p << 6);
        const float* zpi = zi + (p << 6);
        float ar = bbv[j], ai = bbv[64 + j];
        #pragma unroll 8
        for (int i = 0; i < 64; ++i) {
            float a = zpr[i], bq = zpi[i];
            float wr = w1r[(i << 6) + j], wi = w1i[(i << 6) + j];
            ar = fmaf(a, wr, fmaf(-bq, wi, ar));
            ai = fmaf(a, wi, fmaf( bq, wr, ai));
        }
        ar = 0.5f * ar * (1.0f + erff(ar * 0.70710678118654752f));
        ai = 0.5f * ai * (1.0f + erff(ai * 0.70710678118654752f));
        hr[(p << 6) + j] = ar;
        hi[(p << 6) + j] = ai;
    }
    __syncthreads();

    for (int r = 0; r < 4; ++r) {
        int p = pb + (r << 3);
        const float* hpr = hr + (p << 6);
        const float* hpi = hi + (p << 6);
        float ar = bbv[128 + j], ai = bbv[192 + j];
        #pragma unroll 8
        for (int i = 0; i < 64; ++i) {
            float a = hpr[i], bq = hpi[i];
            float wr = w2r[(i << 6) + j], wi = w2i[(i << 6) + j];
            ar = fmaf(a, wr, fmaf(-bq, wi, ar));
            ai = fmaf(a, wi, fmaf( bq, wr, ai));
        }
        float sr = fabsf(ar) - LAMBDA; ar = (sr > 0.0f) ? copysignf(sr, ar) : 0.0f;
        float si = fabsf(ai) - LAMBDA; ai = (si > 0.0f) ? copysignf(si, ai) : 0.0f;

        int P = P0 + p;
        int b = P / NPOS;
        int pos = P - b * NPOS;
        size_t g = ((size_t)b * NPOS + pos) * CC + n*64 + j;
        g_Dr[g] = ar - zr[(p << 6) + j];
        g_Di[g] = ai - zi[(p << 6) + j];
    }
}

// ---------------------------------------------------------------------------
// K3: u = x + irfft2_ortho(D) per image -> bf16 hi/lo directly.
// ---------------------------------------------------------------------------
__global__ __launch_bounds__(512) void k_inv(const float* __restrict__ x)
{
    extern __shared__ float sm[];
    float* dr = sm;
    float* di = dr + 2112;
    float* Gr = di + 2112;
    float* Gi = Gr + 4224;
    float* ct = Gi + 4224;
    float* st = ct + 128;

    const int t      = threadIdx.x;
    const int img_id = blockIdx.x;
    const int b      = img_id >> 9;
    const int c      = img_id & 511;

    if (t < 128) {
        float sv, cv;
        sincosf(TWO_PI * (float)t * (1.0f/128.0f), &sv, &cv);
        ct[t] = cv; st[t] = sv;
    }
    const size_t base = ((size_t)b * NPOS) * CC + c;
    for (int o = t; o < NPOS; o += 512) {
        float a  = g_Dr[base + (size_t)o * CC];
        float bq = g_Di[base + (size_t)o * CC];
        int m = o % 33;
        if (m == 0) { a *= 0.5f; bq *= 0.5f; }
        dr[o] = a; di[o] = bq;
    }
    __syncthreads();

    for (int o = t; o < 4224; o += 512) {
        const int h = o / 33;
        const int m = o - h*33;
        float gr = 0.0f, gi = 0.0f;
        int idx = 0;
        #pragma unroll 8
        for (int k = 0; k < 64; ++k) {
            float ar = dr[k*33 + m];
            float ai = di[k*33 + m];
            float cc = ct[idx], ss = st[idx];
            gr = fmaf(ar, cc, fmaf(-ai, ss, gr));
            gi = fmaf(ar, ss, fmaf( ai, cc, gi));
            idx = (idx + h) & 127;
        }
        Gr[o] = gr; Gi[o] = gi;
    }
    __syncthreads();

    const float* xim = x + (size_t)img_id * 16384;
    __nv_bfloat16* uh = g_uh + (size_t)img_id * 16384;
    __nv_bfloat16* ul = g_ul + (size_t)img_id * 16384;
    for (int o = t; o < 16384; o += 512) {
        const int h  = o >> 7;
        const int xx = o & 127;
        const float* gpr = Gr + h*33;
        const float* gpi = Gi + h*33;
        const float cx = ct[xx], sx = st[xx];
        float cc = 1.0f, ss = 0.0f;
        float acc = 0.0f;
        #pragma unroll
        for (int m = 0; m < 33; ++m) {
            acc = fmaf(gpr[m], cc, fmaf(-gpi[m], ss, acc));
            float nc = fmaf(cc, cx, -ss*sx);
            float ns = fmaf(ss, cx,  cc*sx);
            cc = nc; ss = ns;
        }
        float val = xim[o] + acc * (2.0f/128.0f);
        __nv_bfloat16 hv = __float2bfloat16(val);
        uh[o] = hv;
        ul[o] = __float2bfloat16(val - __bfloat162float(hv));
    }
}

// ---------------------------------------------------------------------------
// K_fc: fw fp32 -> hi/lo bf16
// ---------------------------------------------------------------------------
__global__ __launch_bounds__(1024) void k_fwconv(const float* __restrict__ fw)
{
    int i = blockIdx.x * 1024 + threadIdx.x;
    float v = fw[i];
    __nv_bfloat16 hv = __float2bfloat16(v);
    g_fwh[i] = hv;
    g_fwl[i] = __float2bfloat16(v - __bfloat162float(hv));
}

// ---------------------------------------------------------------------------
// K4: HMMA bf16 GEMM with hi/lo compensation.
// C[o][s] = fw[o][:] . u[:][s] (K=512);  out = x + C.
// CTA: 128(M) x 128(N), 8 warps (warp 32x64), K-chunk 32, cp.async 2 stages.
// A smem tile [128][32] bf16 (64B rows, unit swizzle u^((r>>1)&3)).
// B smem tile [32][128] bf16 (256B rows, unit swizzle u^(r&7)), ldmatrix.trans.
// ---------------------------------------------------------------------------
#define STG_B 32768
#define OFF_AH 0
#define OFF_AL 8192
#define OFF_BH 16384
#define OFF_BL 24576

__global__ __launch_bounds__(256) void k_gemm_mma(
    const float* __restrict__ x, float* __restrict__ out)
{
    extern __shared__ char smc[];
    const uint32_t sb = smem_u32(smc);
    const int t    = threadIdx.x;
    const int lane = t & 31;
    const int wid  = t >> 5;
    const int wm   = wid >> 1;       // 0..3
    const int wn   = wid & 1;        // 0..1
    const int m0   = blockIdx.x * 128;
    const int n0g  = blockIdx.y * 128;
    const int bimg = n0g >> 14;
    const int s0   = n0g & 16383;

    const char* pAh = (const char*)g_fwh;
    const char* pAl = (const char*)g_fwl;
    const char* pBh = (const char*)g_uh;
    const char* pBl = (const char*)g_ul;

    // cp.async chunk coords (2 chunks per thread per tile)
    int ar0 = (t + 0)   >> 2, au0 = (t + 0)   & 3;
    int ar1 = (t + 256) >> 2, au1 = (t + 256) & 3;
    uint32_t adst0 = (uint32_t)(ar0*64 + ((au0 ^ ((ar0>>1)&3)) << 4));
    uint32_t adst1 = (uint32_t)(ar1*64 + ((au1 ^ ((ar1>>1)&3)) << 4));
    int br0 = (t + 0)   >> 4, bu0 = (t + 0)   & 15;
    int br1 = (t + 256) >> 4, bu1 = (t + 256) & 15;
    uint32_t bdst0 = (uint32_t)(br0*256 + ((bu0 ^ (br0&7)) << 4));
    uint32_t bdst1 = (uint32_t)(br1*256 + ((bu1 ^ (br1&7)) << 4));

    float c[2][8][4];
    #pragma unroll
    for (int i = 0; i < 2; ++i)
        #pragma unroll
        for (int j = 0; j < 8; ++j) {
            c[i][j][0] = 0.f; c[i][j][1] = 0.f; c[i][j][2] = 0.f; c[i][j][3] = 0.f;
        }

    // ldmatrix per-thread source coords
    const int lrow8 = (lane & 7) + 8*((lane >> 3) & 1);   // 0..15
    const int lsel  = lane >> 4;                          // 0..1

    #define ISSUE_STAGE(kc, buf) do { \
        uint32_t st_ = sb + (buf)*STG_B; \
        { size_t so = ((size_t)(m0 + ar0)*512 + (kc)*32 + au0*8)*2; \
          CP16(st_ + OFF_AH + adst0, pAh + so); \
          CP16(st_ + OFF_AL + adst0, pAl + so); } \
        { size_t so = ((size_t)(m0 + ar1)*512 + (kc)*32 + au1*8)*2; \
          CP16(st_ + OFF_AH + adst1, pAh + so); \
          CP16(st_ + OFF_AL + adst1, pAl + so); } \
        { size_t so = ((size_t)(bimg*512 + (kc)*32 + br0)*16384 + s0 + bu0*8)*2; \
          CP16(st_ + OFF_BH + bdst0, pBh + so); \
          CP16(st_ + OFF_BL + bdst0, pBl + so); } \
        { size_t so = ((size_t)(bimg*512 + (kc)*32 + br1)*16384 + s0 + bu1*8)*2; \
          CP16(st_ + OFF_BH + bdst1, pBh + so); \
          CP16(st_ + OFF_BL + bdst1, pBl + so); } \
        CP_COMMIT(); \
    } while (0)

    ISSUE_STAGE(0, 0);
    ISSUE_STAGE(1, 1);

    for (int kc = 0; kc < 16; ++kc) {
        const int buf = kc & 1;
        if (kc < 14) { CP_WAIT(1); } else { CP_WAIT(0); }
        __syncthreads();

        const uint32_t st = sb + buf*STG_B;
        #pragma unroll
        for (int ks = 0; ks < 2; ++ks) {
            uint32_t ah[2][4], al[2][4], bh[4][4], bl[4][4];
            #pragma unroll
            for (int mt = 0; mt < 2; ++mt) {
                int row  = wm*32 + mt*16 + lrow8;
                int unit = ks*2 + lsel;
                uint32_t off = (uint32_t)(row*64 + ((unit ^ ((row>>1)&3)) << 4));
                LDSM4(ah[mt], st + OFF_AH + off);
                LDSM4(al[mt], st + OFF_AL + off);
            }
            #pragma unroll
            for (int nq = 0; nq < 4; ++nq) {
                int krow = ks*16 + lrow8;
                int unit = wn*8 + nq*2 + lsel;
                uint32_t off = (uint32_t)(krow*256 + ((unit ^ (krow&7)) << 4));
                LDSM4T(bh[nq], st + OFF_BH + off);
                LDSM4T(bl[nq], st + OFF_BL + off);
            }
            #pragma unroll
            for (int mt = 0; mt < 2; ++mt)
                #pragma unroll
                for (int nt = 0; nt < 8; ++nt) {
                    const int nq = nt >> 1, hb = (nt & 1) * 2;
                    MMA_BF16(c[mt][nt], ah[mt], bh[nq][hb], bh[nq][hb+1]);
                    MMA_BF16(c[mt][nt], ah[mt], bl[nq][hb], bl[nq][hb+1]);
                    MMA_BF16(c[mt][nt], al[mt], bh[nq][hb], bh[nq][hb+1]);
                }
        }
        __syncthreads();
        if (kc + 2 < 16) ISSUE_STAGE(kc + 2, buf);
    }

    // epilogue: direct float2 stores fused with +x
    const int g  = lane >> 2;
    const int tq = lane & 3;
    const size_t obase = (size_t)(bimg * 512);
    #pragma unroll
    for (int mt = 0; mt < 2; ++mt)
        #pragma unroll
        for (int nt = 0; nt < 8; ++nt) {
            int row0 = m0 + wm*32 + mt*16 + g;
            int col  = s0 + wn*64 + nt*8 + tq*2;
            size_t go = (obase + row0)*16384 + col;
            float2 xv = *(const float2*)(x + go);
            float2 ov = { c[mt][nt][0] + xv.x, c[mt][nt][1] + xv.y };
            *(float2*)(out + go) = ov;
            go += (size_t)8 * 16384;
            xv = *(const float2*)(x + go);
            float2 ov2 = { c[mt][nt][2] + xv.x, c[mt][nt][3] + xv.y };
            *(float2*)(out + go) = ov2;
        }
}

// ---------------------------------------------------------------------------
#define SMEM_FWD ((16384 + 2*4224 + 256) * 4)
#define SMEM_MLP ((4*4096 + 4*2048 + 256) * 4)
#define SMEM_INV ((2*2112 + 2*4224 + 256) * 4)
#define SMEM_GMM (2 * STG_B)

extern "C" void kernel_launch(void* const* d_in, const int* in_sizes, int n_in,
                              void* d_out, int out_size)
{
    const float* x   = (const float*)d_in[0];
    const float* w1r = (const float*)d_in[1];
    const float* w1i = (const float*)d_in[2];
    const float* b1r = (const float*)d_in[3];
    const float* b1i = (const float*)d_in[4];
    const float* w2r = (const float*)d_in[5];
    const float* w2i = (const float*)d_in[6];
    const float* b2r = (const float*)d_in[7];
    const float* b2i = (const float*)d_in[8];
    const float* fw  = (const float*)d_in[9];
    float* out = (float*)d_out;

    cudaFuncSetAttribute(k_fwd,      cudaFuncAttributeMaxDynamicSharedMemorySize, SMEM_FWD);
    cudaFuncSetAttribute(k_mlp,      cudaFuncAttributeMaxDynamicSharedMemorySize, SMEM_MLP);
    cudaFuncSetAttribute(k_inv,      cudaFuncAttributeMaxDynamicSharedMemorySize, SMEM_INV);
    cudaFuncSetAttribute(k_gemm_mma, cudaFuncAttributeMaxDynamicSharedMemorySize, SMEM_GMM);

    k_fwconv<<<256, 1024>>>(fw);

    k_fwd<<<BB*CC, 512, SMEM_FWD>>>(x);

    dim3 g2((BB * NPOS) / 32, NBQ);
    k_mlp<<<g2, 512, SMEM_MLP>>>(w1r, w1i, b1r, b1i, w2r, w2i, b2r, b2i);

    k_inv<<<BB*CC, 512, SMEM_INV>>>(x);

    dim3 gg(4, BB*16384/128);   // x = m-block (A reuse in L2), y = n-block
    k_gemm_mma<<<gg, 256, SMEM_GMM>>>(x, out);
}

// round 4
// speedup vs baseline: 3.9657x; 1.9987x over previous
#include <cuda_runtime.h>
#include <cuda_bf16.h>
#include <math.h>
#include <stdint.h>

// ---------------------------------------------------------------------------
// AFNO2D: out = x + fuse_w @ (x + irfft2(D)),   D = masked_MLP(Z) - Z on the
// 64x33 low-frequency region of Z = rfft2(x, ortho).
// All DFT stages are 128x128x128 GEMMs against fixed zero-padded twiddle
// matrices -> HMMA bf16 hi/lo (3-term compensated). MLP scalar (next target).
// ---------------------------------------------------------------------------

#define BB   4
#define CC   512
#define NPOS (64*33)
#define NBQ  8
#define LAMBDA 0.01f
#define TWO_PI 6.28318530717958647692f

// Scratch (allocation-free rule: device globals)
__device__ float g_Zr[(size_t)BB*NPOS*CC];
__device__ float g_Zi[(size_t)BB*NPOS*CC];
__device__ float g_Dr[(size_t)BB*NPOS*CC];
__device__ float g_Di[(size_t)BB*NPOS*CC];
__device__ __nv_bfloat16 g_uh[(size_t)BB*CC*128*128];  // u hi [b][c][s]
__device__ __nv_bfloat16 g_ul[(size_t)BB*CC*128*128];  // u lo [b][c][s]
__device__ __nv_bfloat16 g_fwh[(size_t)CC*CC];
__device__ __nv_bfloat16 g_fwl[(size_t)CC*CC];
// twiddle matrices, PRE-SWIZZLED smem layout (B-operand): 4 mats x 128x128 bf16
__device__ __align__(16) __nv_bfloat16 g_TWh[4][16384];
__device__ __align__(16) __nv_bfloat16 g_TWl[4][16384];

// ======================= helpers =============================
__device__ __forceinline__ uint32_t smem_u32(const void* p) {
    uint32_t a;
    asm("{ .reg .u64 t; cvta.to.shared.u64 t, %1; cvt.u32.u64 %0, t; }"
        : "=r"(a) : "l"(p));
    return a;
}
#define CP16(dst, src) \
    asm volatile("cp.async.cg.shared.global [%0], [%1], 16;" \
        :: "r"(dst), "l"(src) : "memory")
#define CP_COMMIT() asm volatile("cp.async.commit_group;" ::: "memory")
#define CP_WAIT(n)  asm volatile("cp.async.wait_group %0;" :: "n"(n) : "memory")

#define LDSM4(R, a) \
    asm volatile("ldmatrix.sync.aligned.m8n8.x4.shared.b16 {%0,%1,%2,%3}, [%4];" \
        : "=r"((R)[0]), "=r"((R)[1]), "=r"((R)[2]), "=r"((R)[3]) : "r"(a))
#define LDSM4T(R, a) \
    asm volatile("ldmatrix.sync.aligned.m8n8.x4.trans.shared.b16 {%0,%1,%2,%3}, [%4];" \
        : "=r"((R)[0]), "=r"((R)[1]), "=r"((R)[2]), "=r"((R)[3]) : "r"(a))
#define MMA_BF16(C, A, B0, B1) \
    asm volatile("mma.sync.aligned.m16n8k16.row.col.f32.bf16.bf16.f32 " \
        "{%0,%1,%2,%3},{%4,%5,%6,%7},{%8,%9},{%0,%1,%2,%3};" \
        : "+f"((C)[0]), "+f"((C)[1]), "+f"((C)[2]), "+f"((C)[3]) \
        : "r"((A)[0]), "r"((A)[1]), "r"((A)[2]), "r"((A)[3]), "r"(B0), "r"(B1))

__device__ __forceinline__ uint32_t bf2_pack(float a, float b) {
    uint16_t ua = __bfloat16_as_ushort(__float2bfloat16(a));
    uint16_t ub = __bfloat16_as_ushort(__float2bfloat16(b));
    return (uint32_t)ua | ((uint32_t)ub << 16);
}
__device__ __forceinline__ float bf_hi(float v) {
    return __bfloat162float(__float2bfloat16(v));
}

// smem layout of the DFT kernels (bytes):
#define A_OFF_H 0
#define A_OFF_L 32768
#define B_OFF_H 69632
#define B_OFF_L 102400
#define SMEM_FI 135168
// fp32 stage buffer (fwd only) overlaps A region, stride 132 floats (67584B)

// element address inside a 128x128 bf16 swizzled tile
__device__ __forceinline__ uint32_t sw_addr(int r, int c) {
    return (uint32_t)(r*256 + ((((c>>3) ^ (r&7)))<<4) + ((c&7)<<1));
}
// write one value (hi+lo) into A tile
__device__ __forceinline__ void wrA(char* smc, int r, int c, float v) {
    uint32_t off = sw_addr(r, c);
    __nv_bfloat16 hb = __float2bfloat16(v);
    *(__nv_bfloat16*)(smc + A_OFF_H + off) = hb;
    *(__nv_bfloat16*)(smc + A_OFF_L + off) = __float2bfloat16(v - __bfloat162float(hb));
}

// C = A @ B, 128x128x128, A/B bf16 hi/lo swizzled in smem, 16 warps.
__device__ __forceinline__ void gemm128(
    uint32_t sb, float c[2][4][4], int lane, int wm, int wn)
{
    const int lrow8 = (lane & 7) + 8*((lane >> 3) & 1);
    const int lsel  = lane >> 4;
    #pragma unroll
    for (int kc = 0; kc < 8; ++kc) {
        uint32_t ah[2][4], al[2][4], bh[2][4], bl[2][4];
        #pragma unroll
        for (int mt = 0; mt < 2; ++mt) {
            int row  = wm*32 + mt*16 + lrow8;
            int unit = kc*2 + lsel;
            uint32_t off = (uint32_t)(row*256 + ((unit ^ (row&7))<<4));
            LDSM4(ah[mt], sb + A_OFF_H + off);
            LDSM4(al[mt], sb + A_OFF_L + off);
        }
        #pragma unroll
        for (int nq = 0; nq < 2; ++nq) {
            int krow = kc*16 + lrow8;
            int unit = wn*4 + nq*2 + lsel;
            uint32_t off = (uint32_t)(krow*256 + ((unit ^ (krow&7))<<4));
            LDSM4T(bh[nq], sb + B_OFF_H + off);
            LDSM4T(bl[nq], sb + B_OFF_L + off);
        }
        #pragma unroll
        for (int mt = 0; mt < 2; ++mt)
            #pragma unroll
            for (int nt = 0; nt < 4; ++nt) {
                int nq = nt >> 1, hb = (nt & 1)*2;
                MMA_BF16(c[mt][nt], ah[mt], bh[nq][hb], bh[nq][hb+1]);
                MMA_BF16(c[mt][nt], ah[mt], bl[nq][hb], bl[nq][hb+1]);
                MMA_BF16(c[mt][nt], al[mt], bh[nq][hb], bh[nq][hb+1]);
            }
    }
}

__device__ __forceinline__ void copy_tw(char* smc, int mat, int t) {
    const uint4* sh = (const uint4*)g_TWh[mat];
    const uint4* sl = (const uint4*)g_TWl[mat];
    uint4* dh = (uint4*)(smc + B_OFF_H);
    uint4* dl = (uint4*)(smc + B_OFF_L);
    for (int i = t; i < 2048; i += 512) { dh[i] = sh[i]; dl[i] = sl[i]; }
}

// ---------------------------------------------------------------------------
// twiddle init: 4 matrices, pre-swizzled, hi/lo bf16
//  mat0 B1[xx][j]: j<33 cos(2pi xx j/128); 64<=j<97: -sin(2pi xx (j-64)/128)
//  mat1 B2[h][c]:  c<64 cos(2pi h c/128); c>=64: sin(2pi h (c-64)/128)
//  mat2 B3[kk][h]: kk<64 cos(2pi kk h/128); kk>=64: -sin(2pi (kk-64) h/128)
//  mat3 B4[kk][xx]: kk<33 cos; 64<=kk<97: -sin((kk-64) xx)
// ---------------------------------------------------------------------------
__global__ __launch_bounds__(256) void k_twiddle(void)
{
    int idx = blockIdx.x*256 + threadIdx.x;      // 0..65535
    int mat = idx >> 14;
    int r   = (idx >> 7) & 127;
    int cq  = idx & 127;
    float v = 0.0f;
    int p; float sv, cv;
    const float W = TWO_PI / 128.0f;
    if (mat == 0) {
        if (cq < 33)                  { p = (r*cq) & 127;      v =  cosf(W*p); }
        else if (cq >= 64 && cq < 97) { p = (r*(cq-64)) & 127; v = -sinf(W*p); }
    } else if (mat == 1) {
        if (cq < 64) { p = (r*cq) & 127;      v = cosf(W*p); }
        else         { p = (r*(cq-64)) & 127; v = sinf(W*p); }
    } else if (mat == 2) {
        if (r < 64)  { p = (r*cq) & 127;      v =  cosf(W*p); }
        else         { p = ((r-64)*cq) & 127; v = -sinf(W*p); }
    } else {
        if (r < 33)                 { p = (r*cq) & 127;      v =  cosf(W*p); }
        else if (r >= 64 && r < 97) { p = ((r-64)*cq) & 127; v = -sinf(W*p); }
    }
    (void)sv; (void)cv;
    uint32_t ei = sw_addr(r, cq) >> 1;
    __nv_bfloat16 hb = __float2bfloat16(v);
    g_TWh[mat][ei] = hb;
    g_TWl[mat][ei] = __float2bfloat16(v - __bfloat162float(hb));
}

// ---------------------------------------------------------------------------
// K1: forward restricted rfft2 per image via 2 HMMA GEMMs.
// ---------------------------------------------------------------------------
__global__ __launch_bounds__(512) void k_fwd_mma(const float* __restrict__ x)
{
    extern __shared__ char smc[];
    const uint32_t sb = smem_u32(smc);
    const int t = threadIdx.x, lane = t & 31, wid = t >> 5;
    const int wm = wid >> 2, wn = wid & 3;
    const int g = lane >> 2, tq = lane & 3;
    const int img = blockIdx.x, bimg = img >> 9, ch = img & 511;
    const float* src = x + (size_t)img * 16384;

    // load X -> A hi/lo
    for (int i = t*4; i < 16384; i += 2048) {
        float4 v = *(const float4*)(src + i);
        int r = i >> 7, c0 = i & 127;
        uint32_t off = sw_addr(r, c0);
        float hx = bf_hi(v.x), hy = bf_hi(v.y), hz = bf_hi(v.z), hw = bf_hi(v.w);
        uint2 hh = { bf2_pack(v.x, v.y), bf2_pack(v.z, v.w) };
        uint2 ll = { bf2_pack(v.x-hx, v.y-hy), bf2_pack(v.z-hz, v.w-hw) };
        *(uint2*)(smc + A_OFF_H + off) = hh;
        *(uint2*)(smc + A_OFF_L + off) = ll;
    }
    copy_tw(smc, 0, t);
    __syncthreads();

    float c[2][4][4];
    #pragma unroll
    for (int i = 0; i < 2; ++i)
        #pragma unroll
        for (int j = 0; j < 4; ++j)
            { c[i][j][0]=0.f; c[i][j][1]=0.f; c[i][j][2]=0.f; c[i][j][3]=0.f; }
    gemm128(sb, c, lane, wm, wn);          // mid = X @ B1
    __syncthreads();

    // transpose-store mid -> A (bf16 hi/lo), load B2
    #pragma unroll
    for (int mt = 0; mt < 2; ++mt)
        #pragma unroll
        for (int nt = 0; nt < 4; ++nt) {
            int r0 = wm*32 + mt*16 + g, cb = wn*32 + nt*8 + tq*2;
            wrA(smc, cb,   r0,   c[mt][nt][0]);
            wrA(smc, cb+1, r0,   c[mt][nt][1]);
            wrA(smc, cb,   r0+8, c[mt][nt][2]);
            wrA(smc, cb+1, r0+8, c[mt][nt][3]);
        }
    copy_tw(smc, 1, t);
    __syncthreads();

    #pragma unroll
    for (int i = 0; i < 2; ++i)
        #pragma unroll
        for (int j = 0; j < 4; ++j)
            { c[i][j][0]=0.f; c[i][j][1]=0.f; c[i][j][2]=0.f; c[i][j][3]=0.f; }
    gemm128(sb, c, lane, wm, wn);          // out = midT @ B2
    __syncthreads();

    // stage fp32 into buf (stride 132), then combine + scatter store
    float* fbuf = (float*)smc;
    #pragma unroll
    for (int mt = 0; mt < 2; ++mt)
        #pragma unroll
        for (int nt = 0; nt < 4; ++nt) {
            int r0 = wm*32 + mt*16 + g, cb = wn*32 + nt*8 + tq*2;
            fbuf[r0*132 + cb]       = c[mt][nt][0];
            fbuf[r0*132 + cb + 1]   = c[mt][nt][1];
            fbuf[(r0+8)*132 + cb]   = c[mt][nt][2];
            fbuf[(r0+8)*132 + cb+1] = c[mt][nt][3];
        }
    __syncthreads();

    for (int o = t; o < NPOS; o += 512) {
        int k = o / 33, m = o - k*33;
        float zr = (fbuf[m*132 + k] + fbuf[(m+64)*132 + 64 + k]) * 0.0078125f;
        float zi = (fbuf[(m+64)*132 + k] - fbuf[m*132 + 64 + k]) * 0.0078125f;
        size_t gidx = ((size_t)bimg*NPOS + o)*CC + ch;
        g_Zr[gidx] = zr;
        g_Zi[gidx] = zi;
    }
}

// ---------------------------------------------------------------------------
// K3: u = x + irfft2_ortho(D) per image via 2 HMMA GEMMs -> bf16 hi/lo out.
// ---------------------------------------------------------------------------
__global__ __launch_bounds__(512) void k_inv_mma(const float* __restrict__ x)
{
    extern __shared__ char smc[];
    const uint32_t sb = smem_u32(smc);
    const int t = threadIdx.x, lane = t & 31, wid = t >> 5;
    const int wm = wid >> 2, wn = wid & 3;
    const int g = lane >> 2, tq = lane & 3;
    const int img = blockIdx.x, bimg = img >> 9, ch = img & 511;

    // zero A (hi+lo = 64KB)
    {
        uint4 z = {0,0,0,0};
        uint4* pa = (uint4*)(smc + A_OFF_H);
        for (int i = t; i < 4096; i += 512) pa[i] = z;
    }
    __syncthreads();

    // gather D -> A rows: [m: dr|di], [m+64: di|-dr]
    for (int o = t; o < NPOS; o += 512) {
        int k = o / 33, m = o - k*33;
        size_t gidx = ((size_t)bimg*NPOS + o)*CC + ch;
        float a = g_Dr[gidx], b = g_Di[gidx];
        if (m == 0) { a *= 0.5f; b *= 0.5f; }
        wrA(smc, m,    k,    a);
        wrA(smc, m,    64+k, b);
        wrA(smc, m+64, k,    b);
        wrA(smc, m+64, 64+k, -a);
    }
    copy_tw(smc, 2, t);
    __syncthreads();

    float c[2][4][4];
    #pragma unroll
    for (int i = 0; i < 2; ++i)
        #pragma unroll
        for (int j = 0; j < 4; ++j)
            { c[i][j][0]=0.f; c[i][j][1]=0.f; c[i][j][2]=0.f; c[i][j][3]=0.f; }
    gemm128(sb, c, lane, wm, wn);          // Gpack = dpack @ B3
    __syncthreads();

    #pragma unroll
    for (int mt = 0; mt < 2; ++mt)
        #pragma unroll
        for (int nt = 0; nt < 4; ++nt) {
            int r0 = wm*32 + mt*16 + g, cb = wn*32 + nt*8 + tq*2;
            wrA(smc, cb,   r0,   c[mt][nt][0]);
            wrA(smc, cb+1, r0,   c[mt][nt][1]);
            wrA(smc, cb,   r0+8, c[mt][nt][2]);
            wrA(smc, cb+1, r0+8, c[mt][nt][3]);
        }
    copy_tw(smc, 3, t);
    __syncthreads();

    #pragma unroll
    for (int i = 0; i < 2; ++i)
        #pragma unroll
        for (int j = 0; j < 4; ++j)
            { c[i][j][0]=0.f; c[i][j][1]=0.f; c[i][j][2]=0.f; c[i][j][3]=0.f; }
    gemm128(sb, c, lane, wm, wn);          // u = Gt @ B4

    // epilogue: u = x + acc*(2/128) -> bf16 hi/lo
    const float* xim = x + (size_t)img * 16384;
    __nv_bfloat16* uh = g_uh + (size_t)img * 16384;
    __nv_bfloat16* ul = g_ul + (size_t)img * 16384;
    #pragma unroll
    for (int mt = 0; mt < 2; ++mt)
        #pragma unroll
        for (int nt = 0; nt < 4; ++nt) {
            int r0 = wm*32 + mt*16 + g, cb = wn*32 + nt*8 + tq*2;
            #pragma unroll
            for (int hrow = 0; hrow < 2; ++hrow) {
                int r = r0 + hrow*8;
                float v0 = c[mt][nt][hrow*2 + 0];
                float v1 = c[mt][nt][hrow*2 + 1];
                int o = r*128 + cb;
                float2 xv = *(const float2*)(xim + o);
                float a = fmaf(v0, 0.015625f, xv.x);
                float b = fmaf(v1, 0.015625f, xv.y);
                float ha = bf_hi(a), hb = bf_hi(b);
                *(uint32_t*)(uh + o) = bf2_pack(a, b);
                *(uint32_t*)(ul + o) = bf2_pack(a - ha, b - hb);
            }
        }
}

// ---------------------------------------------------------------------------
// K2: block-diagonal complex MLP per frequency position (unchanged).
// ---------------------------------------------------------------------------
__global__ __launch_bounds__(512) void k_mlp(
    const float* __restrict__ w1r_g, const float* __restrict__ w1i_g,
    const float* __restrict__ b1r_g, const float* __restrict__ b1i_g,
    const float* __restrict__ w2r_g, const float* __restrict__ w2i_g,
    const float* __restrict__ b2r_g, const float* __restrict__ b2i_g)
{
    extern __shared__ float sm[];
    float* w1r = sm;
    float* w1i = w1r + 4096;
    float* w2r = w1i + 4096;
    float* w2i = w2r + 4096;
    float* zr  = w2i + 4096;
    float* zi  = zr  + 2048;
    float* hr  = zi  + 2048;
    float* hi  = hr  + 2048;
    float* bbv = hi  + 2048;

    const int t  = threadIdx.x;
    const int n  = blockIdx.y;
    const int P0 = blockIdx.x * 32;

    for (int i = t; i < 4096; i += 512) {
        w1r[i] = w1r_g[n*4096 + i];
        w1i[i] = w1i_g[n*4096 + i];
        w2r[i] = w2r_g[n*4096 + i];
        w2i[i] = w2i_g[n*4096 + i];
    }
    if (t < 64) {
        bbv[t]       = b1r_g[n*64 + t];
        bbv[64 + t]  = b1i_g[n*64 + t];
        bbv[128 + t] = b2r_g[n*64 + t];
        bbv[192 + t] = b2i_g[n*64 + t];
    }
    for (int idx = t; idx < 2048; idx += 512) {
        int p = idx >> 6, i = idx & 63;
        int P = P0 + p;
        int b = P / NPOS;
        int pos = P - b * NPOS;
        size_t gg = ((size_t)b * NPOS + pos) * CC + n*64 + i;
        zr[idx] = g_Zr[gg];
        zi[idx] = g_Zi[gg];
    }
    __syncthreads();

    const int j  = t & 63;
    const int pb = t >> 6;

    for (int r = 0; r < 4; ++r) {
        int p = pb + (r << 3);
        const float* zpr = zr + (p << 6);
        const float* zpi = zi + (p << 6);
        float ar = bbv[j], ai = bbv[64 + j];
        #pragma unroll 8
        for (int i = 0; i < 64; ++i) {
            float a = zpr[i], bq = zpi[i];
            float wr = w1r[(i << 6) + j], wi = w1i[(i << 6) + j];
            ar = fmaf(a, wr, fmaf(-bq, wi, ar));
            ai = fmaf(a, wi, fmaf( bq, wr, ai));
        }
        ar = 0.5f * ar * (1.0f + erff(ar * 0.70710678118654752f));
        ai = 0.5f * ai * (1.0f + erff(ai * 0.70710678118654752f));
        hr[(p << 6) + j] = ar;
        hi[(p << 6) + j] = ai;
    }
    __syncthreads();

    for (int r = 0; r < 4; ++r) {
        int p = pb + (r << 3);
        const float* hpr = hr + (p << 6);
        const float* hpi = hi + (p << 6);
        float ar = bbv[128 + j], ai = bbv[192 + j];
        #pragma unroll 8
        for (int i = 0; i < 64; ++i) {
            float a = hpr[i], bq = hpi[i];
            float wr = w2r[(i << 6) + j], wi = w2i[(i << 6) + j];
            ar = fmaf(a, wr, fmaf(-bq, wi, ar));
            ai = fmaf(a, wi, fmaf( bq, wr, ai));
        }
        float sr = fabsf(ar) - LAMBDA; ar = (sr > 0.0f) ? copysignf(sr, ar) : 0.0f;
        float si = fabsf(ai) - LAMBDA; ai = (si > 0.0f) ? copysignf(si, ai) : 0.0f;

        int P = P0 + p;
        int b = P / NPOS;
        int pos = P - b * NPOS;
        size_t gg = ((size_t)b * NPOS + pos) * CC + n*64 + j;
        g_Dr[gg] = ar - zr[(p << 6) + j];
        g_Di[gg] = ai - zi[(p << 6) + j];
    }
}

// ---------------------------------------------------------------------------
// K_fc: fw fp32 -> hi/lo bf16
// ---------------------------------------------------------------------------
__global__ __launch_bounds__(1024) void k_fwconv(const float* __restrict__ fw)
{
    int i = blockIdx.x * 1024 + threadIdx.x;
    float v = fw[i];
    __nv_bfloat16 hv = __float2bfloat16(v);
    g_fwh[i] = hv;
    g_fwl[i] = __float2bfloat16(v - __bfloat162float(hv));
}

// ---------------------------------------------------------------------------
// K4: HMMA bf16 GEMM with hi/lo compensation (unchanged from round 3).
// ---------------------------------------------------------------------------
#define STG_B 32768
#define OFF_AH 0
#define OFF_AL 8192
#define OFF_BH 16384
#define OFF_BL 24576

__global__ __launch_bounds__(256) void k_gemm_mma(
    const float* __restrict__ x, float* __restrict__ out)
{
    extern __shared__ char smc[];
    const uint32_t sb = smem_u32(smc);
    const int t    = threadIdx.x;
    const int lane = t & 31;
    const int wid  = t >> 5;
    const int wm   = wid >> 1;
    const int wn   = wid & 1;
    const int m0   = blockIdx.x * 128;
    const int n0g  = blockIdx.y * 128;
    const int bimg = n0g >> 14;
    const int s0   = n0g & 16383;

    const char* pAh = (const char*)g_fwh;
    const char* pAl = (const char*)g_fwl;
    const char* pBh = (const char*)g_uh;
    const char* pBl = (const char*)g_ul;

    int ar0 = (t + 0)   >> 2, au0 = (t + 0)   & 3;
    int ar1 = (t + 256) >> 2, au1 = (t + 256) & 3;
    uint32_t adst0 = (uint32_t)(ar0*64 + ((au0 ^ ((ar0>>1)&3)) << 4));
    uint32_t adst1 = (uint32_t)(ar1*64 + ((au1 ^ ((ar1>>1)&3)) << 4));
    int br0 = (t + 0)   >> 4, bu0 = (t + 0)   & 15;
    int br1 = (t + 256) >> 4, bu1 = (t + 256) & 15;
    uint32_t bdst0 = (uint32_t)(br0*256 + ((bu0 ^ (br0&7)) << 4));
    uint32_t bdst1 = (uint32_t)(br1*256 + ((bu1 ^ (br1&7)) << 4));

    float c[2][8][4];
    #pragma unroll
    for (int i = 0; i < 2; ++i)
        #pragma unroll
        for (int j = 0; j < 8; ++j) {
            c[i][j][0] = 0.f; c[i][j][1] = 0.f; c[i][j][2] = 0.f; c[i][j][3] = 0.f;
        }

    const int lrow8 = (lane & 7) + 8*((lane >> 3) & 1);
    const int lsel  = lane >> 4;

    #define ISSUE_STAGE(kc, buf) do { \
        uint32_t st_ = sb + (buf)*STG_B; \
        { size_t so = ((size_t)(m0 + ar0)*512 + (kc)*32 + au0*8)*2; \
          CP16(st_ + OFF_AH + adst0, pAh + so); \
          CP16(st_ + OFF_AL + adst0, pAl + so); } \
        { size_t so = ((size_t)(m0 + ar1)*512 + (kc)*32 + au1*8)*2; \
          CP16(st_ + OFF_AH + adst1, pAh + so); \
          CP16(st_ + OFF_AL + adst1, pAl + so); } \
        { size_t so = ((size_t)(bimg*512 + (kc)*32 + br0)*16384 + s0 + bu0*8)*2; \
          CP16(st_ + OFF_BH + bdst0, pBh + so); \
          CP16(st_ + OFF_BL + bdst0, pBl + so); } \
        { size_t so = ((size_t)(bimg*512 + (kc)*32 + br1)*16384 + s0 + bu1*8)*2; \
          CP16(st_ + OFF_BH + bdst1, pBh + so); \
          CP16(st_ + OFF_BL + bdst1, pBl + so); } \
        CP_COMMIT(); \
    } while (0)

    ISSUE_STAGE(0, 0);
    ISSUE_STAGE(1, 1);

    for (int kc = 0; kc < 16; ++kc) {
        const int buf = kc & 1;
        if (kc < 14) { CP_WAIT(1); } else { CP_WAIT(0); }
        __syncthreads();

        const uint32_t st = sb + buf*STG_B;
        #pragma unroll
        for (int ks = 0; ks < 2; ++ks) {
            uint32_t ah[2][4], al[2][4], bh[4][4], bl[4][4];
            #pragma unroll
            for (int mt = 0; mt < 2; ++mt) {
                int row  = wm*32 + mt*16 + lrow8;
                int unit = ks*2 + lsel;
                uint32_t off = (uint32_t)(row*64 + ((unit ^ ((row>>1)&3)) << 4));
                LDSM4(ah[mt], st + OFF_AH + off);
                LDSM4(al[mt], st + OFF_AL + off);
            }
            #pragma unroll
            for (int nq = 0; nq < 4; ++nq) {
                int krow = ks*16 + lrow8;
                int unit = wn*8 + nq*2 + lsel;
                uint32_t off = (uint32_t)(krow*256 + ((unit ^ (krow&7)) << 4));
                LDSM4T(bh[nq], st + OFF_BH + off);
                LDSM4T(bl[nq], st + OFF_BL + off);
            }
            #pragma unroll
            for (int mt = 0; mt < 2; ++mt)
                #pragma unroll
                for (int nt = 0; nt < 8; ++nt) {
                    const int nq = nt >> 1, hb = (nt & 1) * 2;
                    MMA_BF16(c[mt][nt], ah[mt], bh[nq][hb], bh[nq][hb+1]);
                    MMA_BF16(c[mt][nt], ah[mt], bl[nq][hb], bl[nq][hb+1]);
                    MMA_BF16(c[mt][nt], al[mt], bh[nq][hb], bh[nq][hb+1]);
                }
        }
        __syncthreads();
        if (kc + 2 < 16) ISSUE_STAGE(kc + 2, buf);
    }

    const int g  = lane >> 2;
    const int tq = lane & 3;
    const size_t obase = (size_t)(bimg * 512);
    #pragma unroll
    for (int mt = 0; mt < 2; ++mt)
        #pragma unroll
        for (int nt = 0; nt < 8; ++nt) {
            int row0 = m0 + wm*32 + mt*16 + g;
            int col  = s0 + wn*64 + nt*8 + tq*2;
            size_t go = (obase + row0)*16384 + col;
            float2 xv = *(const float2*)(x + go);
            float2 ov = { c[mt][nt][0] + xv.x, c[mt][nt][1] + xv.y };
            *(float2*)(out + go) = ov;
            go += (size_t)8 * 16384;
            xv = *(const float2*)(x + go);
            float2 ov2 = { c[mt][nt][2] + xv.x, c[mt][nt][3] + xv.y };
            *(float2*)(out + go) = ov2;
        }
}

// ---------------------------------------------------------------------------
#define SMEM_MLP ((4*4096 + 4*2048 + 256) * 4)
#define SMEM_GMM (2 * STG_B)

extern "C" void kernel_launch(void* const* d_in, const int* in_sizes, int n_in,
                              void* d_out, int out_size)
{
    const float* x   = (const float*)d_in[0];
    const float* w1r = (const float*)d_in[1];
    const float* w1i = (const float*)d_in[2];
    const float* b1r = (const float*)d_in[3];
    const float* b1i = (const float*)d_in[4];
    const float* w2r = (const float*)d_in[5];
    const float* w2i = (const float*)d_in[6];
    const float* b2r = (const float*)d_in[7];
    const float* b2i = (const float*)d_in[8];
    const float* fw  = (const float*)d_in[9];
    float* out = (float*)d_out;

    cudaFuncSetAttribute(k_fwd_mma, cudaFuncAttributeMaxDynamicSharedMemorySize, SMEM_FI);
    cudaFuncSetAttribute(k_inv_mma, cudaFuncAttributeMaxDynamicSharedMemorySize, SMEM_FI);
    cudaFuncSetAttribute(k_mlp,     cudaFuncAttributeMaxDynamicSharedMemorySize, SMEM_MLP);
    cudaFuncSetAttribute(k_gemm_mma,cudaFuncAttributeMaxDynamicSharedMemorySize, SMEM_GMM);

    k_twiddle<<<256, 256>>>();
    k_fwconv<<<256, 1024>>>(fw);

    k_fwd_mma<<<BB*CC, 512, SMEM_FI>>>(x);

    dim3 g2((BB * NPOS) / 32, NBQ);
    k_mlp<<<g2, 512, SMEM_MLP>>>(w1r, w1i, b1r, b1i, w2r, w2i, b2r, b2i);

    k_inv_mma<<<BB*CC, 512, SMEM_FI>>>(x);

    dim3 gg(4, BB*16384/128);
    k_gemm_mma<<<gg, 256, SMEM_GMM>>>(x, out);
}

// round 5
// speedup vs baseline: 4.5308x; 1.1425x over previous
#include <cuda_runtime.h>
#include <cuda_bf16.h>
#include <math.h>
#include <stdint.h>

// ---------------------------------------------------------------------------
// AFNO2D: out = x + fuse_w @ (x + irfft2(D)),   D = masked_MLP(Z) - Z on the
// 64x33 low-frequency region of Z = rfft2(x, ortho).
// Every dense stage (DFTs, block MLP, 1x1 conv) runs on HMMA bf16 with
// hi/lo 3-term compensation.
// ---------------------------------------------------------------------------

#define BB   4
#define CC   512
#define NPOS (64*33)
#define NBQ  8
#define LAMBDA 0.01f
#define TWO_PI 6.28318530717958647692f

// Scratch (allocation-free rule: device globals)
__device__ float g_Zr[(size_t)BB*NPOS*CC];
__device__ float g_Zi[(size_t)BB*NPOS*CC];
__device__ float g_Dr[(size_t)BB*NPOS*CC];
__device__ float g_Di[(size_t)BB*NPOS*CC];
__device__ __nv_bfloat16 g_uh[(size_t)BB*CC*128*128];  // u hi [b][c][s]
__device__ __nv_bfloat16 g_ul[(size_t)BB*CC*128*128];  // u lo [b][c][s]
__device__ __nv_bfloat16 g_fwh[(size_t)CC*CC];
__device__ __nv_bfloat16 g_fwl[(size_t)CC*CC];
// twiddle matrices, PRE-SWIZZLED smem layout (B-operand): 4 mats x 128x128 bf16
__device__ __align__(16) __nv_bfloat16 g_TWh[4][16384];
__device__ __align__(16) __nv_bfloat16 g_TWl[4][16384];
// packed complex MLP weights, PRE-SWIZZLED, per block: [[wr, wi], [-wi, wr]]
__device__ __align__(16) __nv_bfloat16 g_W1h[NBQ][16384];
__device__ __align__(16) __nv_bfloat16 g_W1l[NBQ][16384];
__device__ __align__(16) __nv_bfloat16 g_W2h[NBQ][16384];
__device__ __align__(16) __nv_bfloat16 g_W2l[NBQ][16384];
__device__ float g_Bp[NBQ][256];   // [b1r|b1i | b2r|b2i] packed

// ======================= helpers =============================
__device__ __forceinline__ uint32_t smem_u32(const void* p) {
    uint32_t a;
    asm("{ .reg .u64 t; cvta.to.shared.u64 t, %1; cvt.u32.u64 %0, t; }"
        : "=r"(a) : "l"(p));
    return a;
}
#define CP16(dst, src) \
    asm volatile("cp.async.cg.shared.global [%0], [%1], 16;" \
        :: "r"(dst), "l"(src) : "memory")
#define CP_COMMIT() asm volatile("cp.async.commit_group;" ::: "memory")
#define CP_WAIT(n)  asm volatile("cp.async.wait_group %0;" :: "n"(n) : "memory")

#define LDSM4(R, a) \
    asm volatile("ldmatrix.sync.aligned.m8n8.x4.shared.b16 {%0,%1,%2,%3}, [%4];" \
        : "=r"((R)[0]), "=r"((R)[1]), "=r"((R)[2]), "=r"((R)[3]) : "r"(a))
#define LDSM4T(R, a) \
    asm volatile("ldmatrix.sync.aligned.m8n8.x4.trans.shared.b16 {%0,%1,%2,%3}, [%4];" \
        : "=r"((R)[0]), "=r"((R)[1]), "=r"((R)[2]), "=r"((R)[3]) : "r"(a))
#define MMA_BF16(C, A, B0, B1) \
    asm volatile("mma.sync.aligned.m16n8k16.row.col.f32.bf16.bf16.f32 " \
        "{%0,%1,%2,%3},{%4,%5,%6,%7},{%8,%9},{%0,%1,%2,%3};" \
        : "+f"((C)[0]), "+f"((C)[1]), "+f"((C)[2]), "+f"((C)[3]) \
        : "r"((A)[0]), "r"((A)[1]), "r"((A)[2]), "r"((A)[3]), "r"(B0), "r"(B1))

__device__ __forceinline__ uint32_t bf2_pack(float a, float b) {
    uint16_t ua = __bfloat16_as_ushort(__float2bfloat16(a));
    uint16_t ub = __bfloat16_as_ushort(__float2bfloat16(b));
    return (uint32_t)ua | ((uint32_t)ub << 16);
}
__device__ __forceinline__ float bf_hi(float v) {
    return __bfloat162float(__float2bfloat16(v));
}

// smem layout of the 128x128 GEMM kernels (bytes):
#define A_OFF_H 0
#define A_OFF_L 32768
#define BIAS_OFF 65536           // 1KB bias slot (MLP only)
#define B_OFF_H 69632
#define B_OFF_L 102400
#define SMEM_FI 135168

// element address inside a 128x128 bf16 swizzled tile
__device__ __forceinline__ uint32_t sw_addr(int r, int c) {
    return (uint32_t)(r*256 + ((((c>>3) ^ (r&7)))<<4) + ((c&7)<<1));
}
// write one value (hi+lo) into A tile
__device__ __forceinline__ void wrA(char* smc, int r, int c, float v) {
    uint32_t off = sw_addr(r, c);
    __nv_bfloat16 hb = __float2bfloat16(v);
    *(__nv_bfloat16*)(smc + A_OFF_H + off) = hb;
    *(__nv_bfloat16*)(smc + A_OFF_L + off) = __float2bfloat16(v - __bfloat162float(hb));
}

// C = A @ B, 128x128x128, A/B bf16 hi/lo swizzled in smem, 16 warps.
__device__ __forceinline__ void gemm128(
    uint32_t sb, float c[2][4][4], int lane, int wm, int wn)
{
    const int lrow8 = (lane & 7) + 8*((lane >> 3) & 1);
    const int lsel  = lane >> 4;
    #pragma unroll
    for (int kc = 0; kc < 8; ++kc) {
        uint32_t ah[2][4], al[2][4], bh[2][4], bl[2][4];
        #pragma unroll
        for (int mt = 0; mt < 2; ++mt) {
            int row  = wm*32 + mt*16 + lrow8;
            int unit = kc*2 + lsel;
            uint32_t off = (uint32_t)(row*256 + ((unit ^ (row&7))<<4));
            LDSM4(ah[mt], sb + A_OFF_H + off);
            LDSM4(al[mt], sb + A_OFF_L + off);
        }
        #pragma unroll
        for (int nq = 0; nq < 2; ++nq) {
            int krow = kc*16 + lrow8;
            int unit = wn*4 + nq*2 + lsel;
            uint32_t off = (uint32_t)(krow*256 + ((unit ^ (krow&7))<<4));
            LDSM4T(bh[nq], sb + B_OFF_H + off);
            LDSM4T(bl[nq], sb + B_OFF_L + off);
        }
        #pragma unroll
        for (int mt = 0; mt < 2; ++mt)
            #pragma unroll
            for (int nt = 0; nt < 4; ++nt) {
                int nq = nt >> 1, hb = (nt & 1)*2;
                MMA_BF16(c[mt][nt], ah[mt], bh[nq][hb], bh[nq][hb+1]);
                MMA_BF16(c[mt][nt], ah[mt], bl[nq][hb], bl[nq][hb+1]);
                MMA_BF16(c[mt][nt], al[mt], bh[nq][hb], bh[nq][hb+1]);
            }
    }
}

__device__ __forceinline__ void copy_pair(
    char* smc, const __nv_bfloat16* srcH, const __nv_bfloat16* srcL, int t)
{
    const uint4* sh = (const uint4*)srcH;
    const uint4* sl = (const uint4*)srcL;
    uint4* dh = (uint4*)(smc + B_OFF_H);
    uint4* dl = (uint4*)(smc + B_OFF_L);
    for (int i = t; i < 2048; i += 512) { dh[i] = sh[i]; dl[i] = sl[i]; }
}

// ---------------------------------------------------------------------------
// twiddle init: 4 matrices, pre-swizzled, hi/lo bf16
// ---------------------------------------------------------------------------
__global__ __launch_bounds__(256) void k_twiddle(void)
{
    int idx = blockIdx.x*256 + threadIdx.x;      // 0..65535
    int mat = idx >> 14;
    int r   = (idx >> 7) & 127;
    int cq  = idx & 127;
    float v = 0.0f;
    int p;
    const float W = TWO_PI / 128.0f;
    if (mat == 0) {
        if (cq < 33)                  { p = (r*cq) & 127;      v =  cosf(W*p); }
        else if (cq >= 64 && cq < 97) { p = (r*(cq-64)) & 127; v = -sinf(W*p); }
    } else if (mat == 1) {
        if (cq < 64) { p = (r*cq) & 127;      v = cosf(W*p); }
        else         { p = (r*(cq-64)) & 127; v = sinf(W*p); }
    } else if (mat == 2) {
        if (r < 64)  { p = (r*cq) & 127;      v =  cosf(W*p); }
        else         { p = ((r-64)*cq) & 127; v = -sinf(W*p); }
    } else {
        if (r < 33)                 { p = (r*cq) & 127;      v =  cosf(W*p); }
        else if (r >= 64 && r < 97) { p = ((r-64)*cq) & 127; v = -sinf(W*p); }
    }
    uint32_t ei = sw_addr(r, cq) >> 1;
    __nv_bfloat16 hb = __float2bfloat16(v);
    g_TWh[mat][ei] = hb;
    g_TWl[mat][ei] = __float2bfloat16(v - __bfloat162float(hb));
}

// ---------------------------------------------------------------------------
// pack MLP weights: W = [[wr, wi], [-wi, wr]] per block, pre-swizzled hi/lo;
// plus bias pack.
// ---------------------------------------------------------------------------
__global__ __launch_bounds__(256) void k_wpack(
    const float* __restrict__ w1r, const float* __restrict__ w1i,
    const float* __restrict__ w2r, const float* __restrict__ w2i,
    const float* __restrict__ b1r, const float* __restrict__ b1i,
    const float* __restrict__ b2r, const float* __restrict__ b2i)
{
    int idx = blockIdx.x*256 + threadIdx.x;      // 0..262143
    int l   = idx >> 17;
    int rem = idx & 131071;
    int n   = rem >> 14;
    int r   = (rem >> 7) & 127;
    int cq  = rem & 127;
    const float* wr = l ? w2r : w2i;   // placeholder; set below
    const float* wi;
    if (l == 0) { wr = w1r; wi = w1i; } else { wr = w2r; wi = w2i; }
    float v;
    if (r < 64) v = (cq < 64) ?  wr[n*4096 + r*64 + cq]
                              :  wi[n*4096 + r*64 + (cq-64)];
    else        v = (cq < 64) ? -wi[n*4096 + (r-64)*64 + cq]
                              :  wr[n*4096 + (r-64)*64 + (cq-64)];
    uint32_t ei = sw_addr(r, cq) >> 1;
    __nv_bfloat16 hb = __float2bfloat16(v);
    if (l == 0) { g_W1h[n][ei] = hb; g_W1l[n][ei] = __float2bfloat16(v - __bfloat162float(hb)); }
    else        { g_W2h[n][ei] = hb; g_W2l[n][ei] = __float2bfloat16(v - __bfloat162float(hb)); }

    if (idx < NBQ*256) {
        int bn = idx >> 8, j = idx & 255;
        float bv;
        if      (j < 64)  bv = b1r[bn*64 + j];
        else if (j < 128) bv = b1i[bn*64 + j - 64];
        else if (j < 192) bv = b2r[bn*64 + j - 128];
        else              bv = b2i[bn*64 + j - 192];
        g_Bp[bn][j] = bv;
    }
}

// ---------------------------------------------------------------------------
// K1: forward restricted rfft2 per image via 2 HMMA GEMMs.
// ---------------------------------------------------------------------------
__global__ __launch_bounds__(512) void k_fwd_mma(const float* __restrict__ x)
{
    extern __shared__ char smc[];
    const uint32_t sb = smem_u32(smc);
    const int t = threadIdx.x, lane = t & 31, wid = t >> 5;
    const int wm = wid >> 2, wn = wid & 3;
    const int g = lane >> 2, tq = lane & 3;
    const int img = blockIdx.x, bimg = img >> 9, ch = img & 511;
    const float* src = x + (size_t)img * 16384;

    for (int i = t*4; i < 16384; i += 2048) {
        float4 v = *(const float4*)(src + i);
        int r = i >> 7, c0 = i & 127;
        uint32_t off = sw_addr(r, c0);
        float hx = bf_hi(v.x), hy = bf_hi(v.y), hz = bf_hi(v.z), hw = bf_hi(v.w);
        uint2 hh = { bf2_pack(v.x, v.y), bf2_pack(v.z, v.w) };
        uint2 ll = { bf2_pack(v.x-hx, v.y-hy), bf2_pack(v.z-hz, v.w-hw) };
        *(uint2*)(smc + A_OFF_H + off) = hh;
        *(uint2*)(smc + A_OFF_L + off) = ll;
    }
    copy_pair(smc, g_TWh[0], g_TWl[0], t);
    __syncthreads();

    float c[2][4][4];
    #pragma unroll
    for (int i = 0; i < 2; ++i)
        #pragma unroll
        for (int j = 0; j < 4; ++j)
            { c[i][j][0]=0.f; c[i][j][1]=0.f; c[i][j][2]=0.f; c[i][j][3]=0.f; }
    gemm128(sb, c, lane, wm, wn);          // mid = X @ B1
    __syncthreads();

    #pragma unroll
    for (int mt = 0; mt < 2; ++mt)
        #pragma unroll
        for (int nt = 0; nt < 4; ++nt) {
            int r0 = wm*32 + mt*16 + g, cb = wn*32 + nt*8 + tq*2;
            wrA(smc, cb,   r0,   c[mt][nt][0]);
            wrA(smc, cb+1, r0,   c[mt][nt][1]);
            wrA(smc, cb,   r0+8, c[mt][nt][2]);
            wrA(smc, cb+1, r0+8, c[mt][nt][3]);
        }
    copy_pair(smc, g_TWh[1], g_TWl[1], t);
    __syncthreads();

    #pragma unroll
    for (int i = 0; i < 2; ++i)
        #pragma unroll
        for (int j = 0; j < 4; ++j)
            { c[i][j][0]=0.f; c[i][j][1]=0.f; c[i][j][2]=0.f; c[i][j][3]=0.f; }
    gemm128(sb, c, lane, wm, wn);          // out = midT @ B2
    __syncthreads();

    float* fbuf = (float*)smc;
    #pragma unroll
    for (int mt = 0; mt < 2; ++mt)
        #pragma unroll
        for (int nt = 0; nt < 4; ++nt) {
            int r0 = wm*32 + mt*16 + g, cb = wn*32 + nt*8 + tq*2;
            fbuf[r0*132 + cb]       = c[mt][nt][0];
            fbuf[r0*132 + cb + 1]   = c[mt][nt][1];
            fbuf[(r0+8)*132 + cb]   = c[mt][nt][2];
            fbuf[(r0+8)*132 + cb+1] = c[mt][nt][3];
        }
    __syncthreads();

    for (int o = t; o < NPOS; o += 512) {
        int k = o / 33, m = o - k*33;
        float zr = (fbuf[m*132 + k] + fbuf[(m+64)*132 + 64 + k]) * 0.0078125f;
        float zi = (fbuf[(m+64)*132 + k] - fbuf[m*132 + 64 + k]) * 0.0078125f;
        size_t gidx = ((size_t)bimg*NPOS + o)*CC + ch;
        g_Zr[gidx] = zr;
        g_Zi[gidx] = zi;
    }
}

// ---------------------------------------------------------------------------
// K2: block-diagonal complex MLP via 2 HMMA GEMMs per (pos-tile, block).
// A rows = 128 positions, cols = [zr(64) | zi(64)].  W packed 128x128.
// ---------------------------------------------------------------------------
__global__ __launch_bounds__(512) void k_mlp_mma(void)
{
    extern __shared__ char smc[];
    const uint32_t sb = smem_u32(smc);
    const int t = threadIdx.x, lane = t & 31, wid = t >> 5;
    const int wm = wid >> 2, wn = wid & 3;
    const int g = lane >> 2, tq = lane & 3;
    const int n  = blockIdx.y;
    const int p0 = blockIdx.x * 128;
    float* bias = (float*)(smc + BIAS_OFF);

    // load z pack -> A hi/lo
    for (int i = t*4; i < 16384; i += 2048) {
        int r = i >> 7, c0 = i & 127;
        int P = p0 + r, b = P / NPOS, pos = P - b*NPOS;
        const float* srcp = (c0 < 64 ? g_Zr : g_Zi)
                          + ((size_t)b*NPOS + pos)*CC + n*64 + (c0 & 63);
        float4 v = *(const float4*)srcp;
        uint32_t off = sw_addr(r, c0);
        float hx = bf_hi(v.x), hy = bf_hi(v.y), hz = bf_hi(v.z), hw = bf_hi(v.w);
        uint2 hh = { bf2_pack(v.x, v.y), bf2_pack(v.z, v.w) };
        uint2 ll = { bf2_pack(v.x-hx, v.y-hy), bf2_pack(v.z-hz, v.w-hw) };
        *(uint2*)(smc + A_OFF_H + off) = hh;
        *(uint2*)(smc + A_OFF_L + off) = ll;
    }
    copy_pair(smc, g_W1h[n], g_W1l[n], t);
    if (t < 256) bias[t] = g_Bp[n][t];
    __syncthreads();

    float c[2][4][4];
    #pragma unroll
    for (int i = 0; i < 2; ++i)
        #pragma unroll
        for (int j = 0; j < 4; ++j)
            { c[i][j][0]=0.f; c[i][j][1]=0.f; c[i][j][2]=0.f; c[i][j][3]=0.f; }
    gemm128(sb, c, lane, wm, wn);          // y1 = zpack @ W1
    __syncthreads();

    // h = gelu(y1 + b1) -> A
    #pragma unroll
    for (int mt = 0; mt < 2; ++mt)
        #pragma unroll
        for (int nt = 0; nt < 4; ++nt) {
            int r0 = wm*32 + mt*16 + g, cb = wn*32 + nt*8 + tq*2;
            float b0 = bias[cb], b1v = bias[cb+1];
            #pragma unroll
            for (int hrow = 0; hrow < 2; ++hrow) {
                float v0 = c[mt][nt][hrow*2+0] + b0;
                float v1 = c[mt][nt][hrow*2+1] + b1v;
                v0 = 0.5f * v0 * (1.0f + erff(v0 * 0.70710678118654752f));
                v1 = 0.5f * v1 * (1.0f + erff(v1 * 0.70710678118654752f));
                wrA(smc, r0 + hrow*8, cb,   v0);
                wrA(smc, r0 + hrow*8, cb+1, v1);
            }
        }
    copy_pair(smc, g_W2h[n], g_W2l[n], t);
    __syncthreads();

    #pragma unroll
    for (int i = 0; i < 2; ++i)
        #pragma unroll
        for (int j = 0; j < 4; ++j)
            { c[i][j][0]=0.f; c[i][j][1]=0.f; c[i][j][2]=0.f; c[i][j][3]=0.f; }
    gemm128(sb, c, lane, wm, wn);          // y2 = h @ W2

    // softshrink(y2 + b2); D = y - z   (z reread from gmem, L2-hot)
    #pragma unroll
    for (int mt = 0; mt < 2; ++mt)
        #pragma unroll
        for (int nt = 0; nt < 4; ++nt) {
            int r0 = wm*32 + mt*16 + g, cb = wn*32 + nt*8 + tq*2;
            float b0 = bias[128 + cb], b1v = bias[128 + cb + 1];
            float* gD = (cb < 64) ? g_Dr : g_Di;
            const float* gZ = (cb < 64) ? g_Zr : g_Zi;
            #pragma unroll
            for (int hrow = 0; hrow < 2; ++hrow) {
                int r = r0 + hrow*8;
                int P = p0 + r, b = P / NPOS, pos = P - b*NPOS;
                size_t gidx = ((size_t)b*NPOS + pos)*CC + n*64 + (cb & 63);
                float v0 = c[mt][nt][hrow*2+0] + b0;
                float v1 = c[mt][nt][hrow*2+1] + b1v;
                float s0 = fabsf(v0) - LAMBDA; v0 = (s0 > 0.f) ? copysignf(s0, v0) : 0.f;
                float s1 = fabsf(v1) - LAMBDA; v1 = (s1 > 0.f) ? copysignf(s1, v1) : 0.f;
                float2 zv = *(const float2*)(gZ + gidx);
                float2 dv = { v0 - zv.x, v1 - zv.y };
                *(float2*)(gD + gidx) = dv;
            }
        }
}

// ---------------------------------------------------------------------------
// K3: u = x + irfft2_ortho(D) per image via 2 HMMA GEMMs -> bf16 hi/lo out.
// ---------------------------------------------------------------------------
__global__ __launch_bounds__(512) void k_inv_mma(const float* __restrict__ x)
{
    extern __shared__ char smc[];
    const uint32_t sb = smem_u32(smc);
    const int t = threadIdx.x, lane = t & 31, wid = t >> 5;
    const int wm = wid >> 2, wn = wid & 3;
    const int g = lane >> 2, tq = lane & 3;
    const int img = blockIdx.x, bimg = img >> 9, ch = img & 511;

    {
        uint4 z = {0,0,0,0};
        uint4* pa = (uint4*)(smc + A_OFF_H);
        for (int i = t; i < 4096; i += 512) pa[i] = z;
    }
    __syncthreads();

    for (int o = t; o < NPOS; o += 512) {
        int k = o / 33, m = o - k*33;
        size_t gidx = ((size_t)bimg*NPOS + o)*CC + ch;
        float a = g_Dr[gidx], b = g_Di[gidx];
        if (m == 0) { a *= 0.5f; b *= 0.5f; }
        wrA(smc, m,    k,    a);
        wrA(smc, m,    64+k, b);
        wrA(smc, m+64, k,    b);
        wrA(smc, m+64, 64+k, -a);
    }
    copy_pair(smc, g_TWh[2], g_TWl[2], t);
    __syncthreads();

    float c[2][4][4];
    #pragma unroll
    for (int i = 0; i < 2; ++i)
        #pragma unroll
        for (int j = 0; j < 4; ++j)
            { c[i][j][0]=0.f; c[i][j][1]=0.f; c[i][j][2]=0.f; c[i][j][3]=0.f; }
    gemm128(sb, c, lane, wm, wn);          // Gpack = dpack @ B3
    __syncthreads();

    #pragma unroll
    for (int mt = 0; mt < 2; ++mt)
        #pragma unroll
        for (int nt = 0; nt < 4; ++nt) {
            int r0 = wm*32 + mt*16 + g, cb = wn*32 + nt*8 + tq*2;
            wrA(smc, cb,   r0,   c[mt][nt][0]);
            wrA(smc, cb+1, r0,   c[mt][nt][1]);
            wrA(smc, cb,   r0+8, c[mt][nt][2]);
            wrA(smc, cb+1, r0+8, c[mt][nt][3]);
        }
    copy_pair(smc, g_TWh[3], g_TWl[3], t);
    __syncthreads();

    #pragma unroll
    for (int i = 0; i < 2; ++i)
        #pragma unroll
        for (int j = 0; j < 4; ++j)
            { c[i][j][0]=0.f; c[i][j][1]=0.f; c[i][j][2]=0.f; c[i][j][3]=0.f; }
    gemm128(sb, c, lane, wm, wn);          // u = Gt @ B4

    const float* xim = x + (size_t)img * 16384;
    __nv_bfloat16* uh = g_uh + (size_t)img * 16384;
    __nv_bfloat16* ul = g_ul + (size_t)img * 16384;
    #pragma unroll
    for (int mt = 0; mt < 2; ++mt)
        #pragma unroll
        for (int nt = 0; nt < 4; ++nt) {
            int r0 = wm*32 + mt*16 + g, cb = wn*32 + nt*8 + tq*2;
            #pragma unroll
            for (int hrow = 0; hrow < 2; ++hrow) {
                int r = r0 + hrow*8;
                float v0 = c[mt][nt][hrow*2 + 0];
                float v1 = c[mt][nt][hrow*2 + 1];
                int o = r*128 + cb;
                float2 xv = *(const float2*)(xim + o);
                float a = fmaf(v0, 0.015625f, xv.x);
                float b = fmaf(v1, 0.015625f, xv.y);
                float ha = bf_hi(a), hb = bf_hi(b);
                *(uint32_t*)(uh + o) = bf2_pack(a, b);
                *(uint32_t*)(ul + o) = bf2_pack(a - ha, b - hb);
            }
        }
}

// ---------------------------------------------------------------------------
// K_fc: fw fp32 -> hi/lo bf16
// ---------------------------------------------------------------------------
__global__ __launch_bounds__(1024) void k_fwconv(const float* __restrict__ fw)
{
    int i = blockIdx.x * 1024 + threadIdx.x;
    float v = fw[i];
    __nv_bfloat16 hv = __float2bfloat16(v);
    g_fwh[i] = hv;
    g_fwl[i] = __float2bfloat16(v - __bfloat162float(hv));
}

// ---------------------------------------------------------------------------
// K4: HMMA bf16 GEMM with hi/lo compensation (fuse conv + residual).
// ---------------------------------------------------------------------------
#define STG_B 32768
#define OFF_AH 0
#define OFF_AL 8192
#define OFF_BH 16384
#define OFF_BL 24576

__global__ __launch_bounds__(256) void k_gemm_mma(
    const float* __restrict__ x, float* __restrict__ out)
{
    extern __shared__ char smc[];
    const uint32_t sb = smem_u32(smc);
    const int t    = threadIdx.x;
    const int lane = t & 31;
    const int wid  = t >> 5;
    const int wm   = wid >> 1;
    const int wn   = wid & 1;
    const int m0   = blockIdx.x * 128;
    const int n0g  = blockIdx.y * 128;
    const int bimg = n0g >> 14;
    const int s0   = n0g & 16383;

    const char* pAh = (const char*)g_fwh;
    const char* pAl = (const char*)g_fwl;
    const char* pBh = (const char*)g_uh;
    const char* pBl = (const char*)g_ul;

    int ar0 = (t + 0)   >> 2, au0 = (t + 0)   & 3;
    int ar1 = (t + 256) >> 2, au1 = (t + 256) & 3;
    uint32_t adst0 = (uint32_t)(ar0*64 + ((au0 ^ ((ar0>>1)&3)) << 4));
    uint32_t adst1 = (uint32_t)(ar1*64 + ((au1 ^ ((ar1>>1)&3)) << 4));
    int br0 = (t + 0)   >> 4, bu0 = (t + 0)   & 15;
    int br1 = (t + 256) >> 4, bu1 = (t + 256) & 15;
    uint32_t bdst0 = (uint32_t)(br0*256 + ((bu0 ^ (br0&7)) << 4));
    uint32_t bdst1 = (uint32_t)(br1*256 + ((bu1 ^ (br1&7)) << 4));

    float c[2][8][4];
    #pragma unroll
    for (int i = 0; i < 2; ++i)
        #pragma unroll
        for (int j = 0; j < 8; ++j) {
            c[i][j][0] = 0.f; c[i][j][1] = 0.f; c[i][j][2] = 0.f; c[i][j][3] = 0.f;
        }

    const int lrow8 = (lane & 7) + 8*((lane >> 3) & 1);
    const int lsel  = lane >> 4;

    #define ISSUE_STAGE(kc, buf) do { \
        uint32_t st_ = sb + (buf)*STG_B; \
        { size_t so = ((size_t)(m0 + ar0)*512 + (kc)*32 + au0*8)*2; \
          CP16(st_ + OFF_AH + adst0, pAh + so); \
          CP16(st_ + OFF_AL + adst0, pAl + so); } \
        { size_t so = ((size_t)(m0 + ar1)*512 + (kc)*32 + au1*8)*2; \
          CP16(st_ + OFF_AH + adst1, pAh + so); \
          CP16(st_ + OFF_AL + adst1, pAl + so); } \
        { size_t so = ((size_t)(bimg*512 + (kc)*32 + br0)*16384 + s0 + bu0*8)*2; \
          CP16(st_ + OFF_BH + bdst0, pBh + so); \
          CP16(st_ + OFF_BL + bdst0, pBl + so); } \
        { size_t so = ((size_t)(bimg*512 + (kc)*32 + br1)*16384 + s0 + bu1*8)*2; \
          CP16(st_ + OFF_BH + bdst1, pBh + so); \
          CP16(st_ + OFF_BL + bdst1, pBl + so); } \
        CP_COMMIT(); \
    } while (0)

    ISSUE_STAGE(0, 0);
    ISSUE_STAGE(1, 1);

    for (int kc = 0; kc < 16; ++kc) {
        const int buf = kc & 1;
        if (kc < 14) { CP_WAIT(1); } else { CP_WAIT(0); }
        __syncthreads();

        const uint32_t st = sb + buf*STG_B;
        #pragma unroll
        for (int ks = 0; ks < 2; ++ks) {
            uint32_t ah[2][4], al[2][4], bh[4][4], bl[4][4];
            #pragma unroll
            for (int mt = 0; mt < 2; ++mt) {
                int row  = wm*32 + mt*16 + lrow8;
                int unit = ks*2 + lsel;
                uint32_t off = (uint32_t)(row*64 + ((unit ^ ((row>>1)&3)) << 4));
                LDSM4(ah[mt], st + OFF_AH + off);
                LDSM4(al[mt], st + OFF_AL + off);
            }
            #pragma unroll
            for (int nq = 0; nq < 4; ++nq) {
                int krow = ks*16 + lrow8;
                int unit = wn*8 + nq*2 + lsel;
                uint32_t off = (uint32_t)(krow*256 + ((unit ^ (krow&7)) << 4));
                LDSM4T(bh[nq], st + OFF_BH + off);
                LDSM4T(bl[nq], st + OFF_BL + off);
            }
            #pragma unroll
            for (int mt = 0; mt < 2; ++mt)
                #pragma unroll
                for (int nt = 0; nt < 8; ++nt) {
                    const int nq = nt >> 1, hb = (nt & 1) * 2;
                    MMA_BF16(c[mt][nt], ah[mt], bh[nq][hb], bh[nq][hb+1]);
                    MMA_BF16(c[mt][nt], ah[mt], bl[nq][hb], bl[nq][hb+1]);
                    MMA_BF16(c[mt][nt], al[mt], bh[nq][hb], bh[nq][hb+1]);
                }
        }
        __syncthreads();
        if (kc + 2 < 16) ISSUE_STAGE(kc + 2, buf);
    }

    const int g  = lane >> 2;
    const int tq = lane & 3;
    const size_t obase = (size_t)(bimg * 512);
    #pragma unroll
    for (int mt = 0; mt < 2; ++mt)
        #pragma unroll
        for (int nt = 0; nt < 8; ++nt) {
            int row0 = m0 + wm*32 + mt*16 + g;
            int col  = s0 + wn*64 + nt*8 + tq*2;
            size_t go = (obase + row0)*16384 + col;
            float2 xv = *(const float2*)(x + go);
            float2 ov = { c[mt][nt][0] + xv.x, c[mt][nt][1] + xv.y };
            *(float2*)(out + go) = ov;
            go += (size_t)8 * 16384;
            xv = *(const float2*)(x + go);
            float2 ov2 = { c[mt][nt][2] + xv.x, c[mt][nt][3] + xv.y };
            *(float2*)(out + go) = ov2;
        }
}

// ---------------------------------------------------------------------------
#define SMEM_GMM (2 * STG_B)

extern "C" void kernel_launch(void* const* d_in, const int* in_sizes, int n_in,
                              void* d_out, int out_size)
{
    const float* x   = (const float*)d_in[0];
    const float* w1r = (const float*)d_in[1];
    const float* w1i = (const float*)d_in[2];
    const float* b1r = (const float*)d_in[3];
    const float* b1i = (const float*)d_in[4];
    const float* w2r = (const float*)d_in[5];
    const float* w2i = (const float*)d_in[6];
    const float* b2r = (const float*)d_in[7];
    const float* b2i = (const float*)d_in[8];
    const float* fw  = (const float*)d_in[9];
    float* out = (float*)d_out;

    cudaFuncSetAttribute(k_fwd_mma, cudaFuncAttributeMaxDynamicSharedMemorySize, SMEM_FI);
    cudaFuncSetAttribute(k_inv_mma, cudaFuncAttributeMaxDynamicSharedMemorySize, SMEM_FI);
    cudaFuncSetAttribute(k_mlp_mma, cudaFuncAttributeMaxDynamicSharedMemorySize, SMEM_FI);
    cudaFuncSetAttribute(k_gemm_mma,cudaFuncAttributeMaxDynamicSharedMemorySize, SMEM_GMM);

    k_twiddle<<<256, 256>>>();
    k_wpack<<<1024, 256>>>(w1r, w1i, w2r, w2i, b1r, b1i, b2r, b2i);
    k_fwconv<<<256, 1024>>>(fw);

    k_fwd_mma<<<BB*CC, 512, SMEM_FI>>>(x);

    dim3 g2((BB*NPOS)/128, NBQ);
    k_mlp_mma<<<g2, 512, SMEM_FI>>>();

    k_inv_mma<<<BB*CC, 512, SMEM_FI>>>(x);

    dim3 gg(4, BB*16384/128);
    k_gemm_mma<<<gg, 256, SMEM_GMM>>>(x, out);
}

// round 8
// speedup vs baseline: 4.8528x; 1.0711x over previous
#include <cuda_runtime.h>
#include <cuda_bf16.h>
#include <math.h>
#include <stdint.h>

// ---------------------------------------------------------------------------
// AFNO2D: out = x + fuse_w @ (x + irfft2(D)),   D = masked_MLP(Z) - Z on the
// 64x33 low-frequency region of Z = rfft2(x, ortho).
// All dense stages on HMMA bf16 hi/lo (3-term compensated).
// Round 6: transpose-free DFT stages (operand-swapped twiddles), preloaded
// fixed matrices, channel-major Z/D for coalesced fwd/inv epilogues.
// ---------------------------------------------------------------------------

#define BB   4
#define CC   512
#define NPOS (64*33)
#define NBQ  8
#define LAMBDA 0.01f
#define TWO_PI 6.28318530717958647692f

// Scratch (allocation-free rule: device globals).  Z/D are CHANNEL-MAJOR:
// g_Zr[(b*512 + ch)*2112 + pos]
__device__ float g_Zr[(size_t)BB*CC*NPOS];
__device__ float g_Zi[(size_t)BB*CC*NPOS];
__device__ float g_Dr[(size_t)BB*CC*NPOS];
__device__ float g_Di[(size_t)BB*CC*NPOS];
__device__ __nv_bfloat16 g_uh[(size_t)BB*CC*128*128];  // u hi [b][c][s]
__device__ __nv_bfloat16 g_ul[(size_t)BB*CC*128*128];  // u lo [b][c][s]
__device__ __nv_bfloat16 g_fwh[(size_t)CC*CC];
__device__ __nv_bfloat16 g_fwl[(size_t)CC*CC];
// twiddle matrices, PRE-SWIZZLED, hi/lo bf16:
//  mat0 = B1   (B-layout [x][j])     mat1 = B2^T (A-layout [c][h])
//  mat2 = B3^T (A-layout [h][kk])    mat3 = B4   (B-layout [j][xx])
__device__ __align__(16) __nv_bfloat16 g_TWh[4][16384];
__device__ __align__(16) __nv_bfloat16 g_TWl[4][16384];
// packed complex MLP weights, PRE-SWIZZLED, per block: [[wr, wi], [-wi, wr]]
__device__ __align__(16) __nv_bfloat16 g_W1h[NBQ][16384];
__device__ __align__(16) __nv_bfloat16 g_W1l[NBQ][16384];
__device__ __align__(16) __nv_bfloat16 g_W2h[NBQ][16384];
__device__ __align__(16) __nv_bfloat16 g_W2l[NBQ][16384];
__device__ float g_Bp[NBQ][256];

// ======================= helpers =============================
__device__ __forceinline__ uint32_t smem_u32(const void* p) {
    uint32_t a;
    asm("{ .reg .u64 t; cvta.to.shared.u64 t, %1; cvt.u32.u64 %0, t; }"
        : "=r"(a) : "l"(p));
    return a;
}
#define CP16(dst, src) \
    asm volatile("cp.async.cg.shared.global [%0], [%1], 16;" \
        :: "r"(dst), "l"(src) : "memory")
#define CP_COMMIT() asm volatile("cp.async.commit_group;" ::: "memory")
#define CP_WAIT(n)  asm volatile("cp.async.wait_group %0;" :: "n"(n) : "memory")

#define LDSM4(R, a) \
    asm volatile("ldmatrix.sync.aligned.m8n8.x4.shared.b16 {%0,%1,%2,%3}, [%4];" \
        : "=r"((R)[0]), "=r"((R)[1]), "=r"((R)[2]), "=r"((R)[3]) : "r"(a))
#define LDSM4T(R, a) \
    asm volatile("ldmatrix.sync.aligned.m8n8.x4.trans.shared.b16 {%0,%1,%2,%3}, [%4];" \
        : "=r"((R)[0]), "=r"((R)[1]), "=r"((R)[2]), "=r"((R)[3]) : "r"(a))
#define MMA_BF16(C, A, B0, B1) \
    asm volatile("mma.sync.aligned.m16n8k16.row.col.f32.bf16.bf16.f32 " \
        "{%0,%1,%2,%3},{%4,%5,%6,%7},{%8,%9},{%0,%1,%2,%3};" \
        : "+f"((C)[0]), "+f"((C)[1]), "+f"((C)[2]), "+f"((C)[3]) \
        : "r"((A)[0]), "r"((A)[1]), "r"((A)[2]), "r"((A)[3]), "r"(B0), "r"(B1))

__device__ __forceinline__ uint32_t bf2_pack(float a, float b) {
    uint16_t ua = __bfloat16_as_ushort(__float2bfloat16(a));
    uint16_t ub = __bfloat16_as_ushort(__float2bfloat16(b));
    return (uint32_t)ua | ((uint32_t)ub << 16);
}
__device__ __forceinline__ float bf_hi(float v) {
    return __bfloat162float(__float2bfloat16(v));
}

// smem regions (bytes).  Each region = 32KB hi + 32KB lo.
#define RA_H 0
#define RA_L 32768
#define RB_H 65536
#define RB_L 98304
#define R3_H 131072
#define R3_L 163840
#define BIAS_OFF 196608
#define SMEM_K 197632
// fp32 staging buffer overlaps RA/RB after final GEMM: 128 x 129 floats

__device__ __forceinline__ uint32_t sw_addr(int r, int c) {
    return (uint32_t)(r*256 + ((((c>>3) ^ (r&7)))<<4) + ((c&7)<<1));
}
// write adjacent-column pair (hi+lo) into region at byte offset H (c even)
__device__ __forceinline__ void wrPair(char* smc, uint32_t H, int r, int c,
                                       float v0, float v1) {
    uint32_t off = sw_addr(r, c);
    float h0 = bf_hi(v0), h1 = bf_hi(v1);
    *(uint32_t*)(smc + H + off)         = bf2_pack(v0, v1);
    *(uint32_t*)(smc + H + 32768 + off) = bf2_pack(v0 - h0, v1 - h1);
}
// scalar single-element write (hi+lo)
__device__ __forceinline__ void wrOne(char* smc, uint32_t H, int r, int c, float v) {
    uint32_t off = sw_addr(r, c);
    __nv_bfloat16 hb = __float2bfloat16(v);
    *(__nv_bfloat16*)(smc + H + off)         = hb;
    *(__nv_bfloat16*)(smc + H + 32768 + off) = __float2bfloat16(v - __bfloat162float(hb));
}

// C = A @ B, 128x128x128, operands bf16 hi/lo swizzled at aH/bH, 16 warps.
__device__ __forceinline__ void gemm128(
    uint32_t sb, float c[2][4][4], int lane, int wm, int wn,
    uint32_t aH, uint32_t bH)
{
    const int lrow8 = (lane & 7) + 8*((lane >> 3) & 1);
    const int lsel  = lane >> 4;
    #pragma unroll
    for (int kc = 0; kc < 8; ++kc) {
        uint32_t ah[2][4], al[2][4], bh[2][4], bl[2][4];
        #pragma unroll
        for (int mt = 0; mt < 2; ++mt) {
            int row  = wm*32 + mt*16 + lrow8;
            int unit = kc*2 + lsel;
            uint32_t off = (uint32_t)(row*256 + ((unit ^ (row&7))<<4));
            LDSM4(ah[mt], sb + aH + off);
            LDSM4(al[mt], sb + aH + 32768 + off);
        }
        #pragma unroll
        for (int nq = 0; nq < 2; ++nq) {
            int krow = kc*16 + lrow8;
            int unit = wn*4 + nq*2 + lsel;
            uint32_t off = (uint32_t)(krow*256 + ((unit ^ (krow&7))<<4));
            LDSM4T(bh[nq], sb + bH + off);
            LDSM4T(bl[nq], sb + bH + 32768 + off);
        }
        #pragma unroll
        for (int mt = 0; mt < 2; ++mt)
            #pragma unroll
            for (int nt = 0; nt < 4; ++nt) {
                int nq = nt >> 1, hb = (nt & 1)*2;
                MMA_BF16(c[mt][nt], ah[mt], bh[nq][hb], bh[nq][hb+1]);
                MMA_BF16(c[mt][nt], ah[mt], bl[nq][hb], bl[nq][hb+1]);
                MMA_BF16(c[mt][nt], al[mt], bh[nq][hb], bh[nq][hb+1]);
            }
    }
}

#define ZERO_C(c) do { \
    _Pragma("unroll") for (int i_ = 0; i_ < 2; ++i_) \
        _Pragma("unroll") for (int j_ = 0; j_ < 4; ++j_) { \
            (c)[i_][j_][0]=0.f; (c)[i_][j_][1]=0.f; \
            (c)[i_][j_][2]=0.f; (c)[i_][j_][3]=0.f; } \
} while (0)

__device__ __forceinline__ void copy64(
    char* smc, uint32_t H, const __nv_bfloat16* srcH, const __nv_bfloat16* srcL, int t)
{
    const uint4* sh = (const uint4*)srcH;
    const uint4* sl = (const uint4*)srcL;
    uint4* dh = (uint4*)(smc + H);
    uint4* dl = (uint4*)(smc + H + 32768);
    for (int i = t; i < 2048; i += 512) { dh[i] = sh[i]; dl[i] = sl[i]; }
}

// ---------------------------------------------------------------------------
// twiddle init
// ---------------------------------------------------------------------------
__global__ __launch_bounds__(256) void k_twiddle(void)
{
    int idx = blockIdx.x*256 + threadIdx.x;      // 0..65535
    int mat = idx >> 14;
    int r   = (idx >> 7) & 127;
    int cq  = idx & 127;
    float v = 0.0f;
    const float W = TWO_PI / 128.0f;
    if (mat == 0) {              // B1 [x][j]
        if (cq < 33)                  v =  cosf(W*((r*cq) & 127));
        else if (cq >= 64 && cq < 97) v = -sinf(W*((r*(cq-64)) & 127));
    } else if (mat == 1) {       // B2^T [c][h]
        if (r < 64) v = cosf(W*((r*cq) & 127));
        else        v = sinf(W*(((r-64)*cq) & 127));
    } else if (mat == 2) {       // B3^T [h][kk]
        if (cq < 64) v =  cosf(W*((r*cq) & 127));
        else         v = -sinf(W*(((cq-64)*r) & 127));
    } else {                     // B4 [j][xx]
        if (r < 33)                 v =  cosf(W*((r*cq) & 127));
        else if (r >= 64 && r < 97) v = -sinf(W*(((r-64)*cq) & 127));
    }
    uint32_t ei = sw_addr(r, cq) >> 1;
    __nv_bfloat16 hb = __float2bfloat16(v);
    g_TWh[mat][ei] = hb;
    g_TWl[mat][ei] = __float2bfloat16(v - __bfloat162float(hb));
}

// ---------------------------------------------------------------------------
// pack MLP weights + biases
// ---------------------------------------------------------------------------
__global__ __launch_bounds__(256) void k_wpack(
    const float* __restrict__ w1r, const float* __restrict__ w1i,
    const float* __restrict__ w2r, const float* __restrict__ w2i,
    const float* __restrict__ b1r, const float* __restrict__ b1i,
    const float* __restrict__ b2r, const float* __restrict__ b2i)
{
    int idx = blockIdx.x*256 + threadIdx.x;      // 0..262143
    int l   = idx >> 17;
    int rem = idx & 131071;
    int n   = rem >> 14;
    int r   = (rem >> 7) & 127;
    int cq  = rem & 127;
    const float* wr;
    const float* wi;
    if (l == 0) { wr = w1r; wi = w1i; } else { wr = w2r; wi = w2i; }
    float v;
    if (r < 64) v = (cq < 64) ?  wr[n*4096 + r*64 + cq]
                              :  wi[n*4096 + r*64 + (cq-64)];
    else        v = (cq < 64) ? -wi[n*4096 + (r-64)*64 + cq]
                              :  wr[n*4096 + (r-64)*64 + (cq-64)];
    uint32_t ei = sw_addr(r, cq) >> 1;
    __nv_bfloat16 hb = __float2bfloat16(v);
    if (l == 0) { g_W1h[n][ei] = hb; g_W1l[n][ei] = __float2bfloat16(v - __bfloat162float(hb)); }
    else        { g_W2h[n][ei] = hb; g_W2l[n][ei] = __float2bfloat16(v - __bfloat162float(hb)); }

    if (idx < NBQ*256) {
        int bn = idx >> 8, j = idx & 255;
        float bv;
        if      (j < 64)  bv = b1r[bn*64 + j];
        else if (j < 128) bv = b1i[bn*64 + j - 64];
        else if (j < 192) bv = b2r[bn*64 + j - 128];
        else              bv = b2i[bn*64 + j - 192];
        g_Bp[bn][j] = bv;
    }
}

// ---------------------------------------------------------------------------
// K1: forward restricted rfft2 per image.
//   stage1: mid = X @ B1            (A=RA(X), B=RB(B1))  -> C into RB
//   stage2: outT = B2^T @ mid       (A=R3(B2T), B=RB)
//   epilogue: Zr/Zi combine -> channel-major coalesced stores
// ---------------------------------------------------------------------------
__global__ __launch_bounds__(512) void k_fwd_mma(const float* __restrict__ x)
{
    extern __shared__ char smc[];
    const uint32_t sb = smem_u32(smc);
    const int t = threadIdx.x, lane = t & 31, wid = t >> 5;
    const int wm = wid >> 2, wn = wid & 3;
    const int g = lane >> 2, tq = lane & 3;
    const int img = blockIdx.x, bimg = img >> 9, ch = img & 511;
    const float* src = x + (size_t)img * 16384;

    for (int i = t*4; i < 16384; i += 2048) {
        float4 v = *(const float4*)(src + i);
        int r = i >> 7, c0 = i & 127;
        uint32_t off = sw_addr(r, c0);
        float hx = bf_hi(v.x), hy = bf_hi(v.y), hz = bf_hi(v.z), hw = bf_hi(v.w);
        uint2 hh = { bf2_pack(v.x, v.y), bf2_pack(v.z, v.w) };
        uint2 ll = { bf2_pack(v.x-hx, v.y-hy), bf2_pack(v.z-hz, v.w-hw) };
        *(uint2*)(smc + RA_H + off) = hh;
        *(uint2*)(smc + RA_L + off) = ll;
    }
    copy64(smc, RB_H, g_TWh[0], g_TWl[0], t);
    copy64(smc, R3_H, g_TWh[1], g_TWl[1], t);
    __syncthreads();

    float c[2][4][4];
    ZERO_C(c);
    gemm128(sb, c, lane, wm, wn, RA_H, RB_H);     // mid = X @ B1
    __syncthreads();

    // mid -> RB (natural layout, packed col-pair stores)
    #pragma unroll
    for (int mt = 0; mt < 2; ++mt)
        #pragma unroll
        for (int nt = 0; nt < 4; ++nt) {
            int r0 = wm*32 + mt*16 + g, cb = wn*32 + nt*8 + tq*2;
            wrPair(smc, RB_H, r0,     cb, c[mt][nt][0], c[mt][nt][1]);
            wrPair(smc, RB_H, r0 + 8, cb, c[mt][nt][2], c[mt][nt][3]);
        }
    __syncthreads();

    ZERO_C(c);
    gemm128(sb, c, lane, wm, wn, R3_H, RB_H);     // outT = B2^T @ mid
    __syncthreads();

    float* fbuf = (float*)smc;                    // [128][129] overlaps RA/RB
    #pragma unroll
    for (int mt = 0; mt < 2; ++mt)
        #pragma unroll
        for (int nt = 0; nt < 4; ++nt) {
            int r0 = wm*32 + mt*16 + g, cb = wn*32 + nt*8 + tq*2;
            fbuf[r0*129 + cb]       = c[mt][nt][0];
            fbuf[r0*129 + cb + 1]   = c[mt][nt][1];
            fbuf[(r0+8)*129 + cb]   = c[mt][nt][2];
            fbuf[(r0+8)*129 + cb+1] = c[mt][nt][3];
        }
    __syncthreads();

    const size_t base = ((size_t)bimg*512 + ch) * NPOS;
    for (int o = t; o < NPOS; o += 512) {
        int k = o / 33, m = o - k*33;
        float zr = (fbuf[k*129 + m]      + fbuf[(64+k)*129 + 64+m]) * 0.0078125f;
        float zi = (fbuf[k*129 + 64+m]   - fbuf[(64+k)*129 + m])    * 0.0078125f;
        g_Zr[base + o] = zr;
        g_Zi[base + o] = zi;
    }
}

// ---------------------------------------------------------------------------
// K2: block-diagonal complex MLP.
//   stage1: y1 = z @ W1    (A=RA(z), B=RB(W1)) -> gelu -> RA
//   stage2: y2 = h @ W2    (A=RA, B=R3(W2))
//   epilogue: softshrink, D = y - z (channel-major)
// ---------------------------------------------------------------------------
__global__ __launch_bounds__(512) void k_mlp_mma(void)
{
    extern __shared__ char smc[];
    const uint32_t sb = smem_u32(smc);
    const int t = threadIdx.x, lane = t & 31, wid = t >> 5;
    const int wm = wid >> 2, wn = wid & 3;
    const int g = lane >> 2, tq = lane & 3;
    const int n  = blockIdx.y;
    const int p0 = blockIdx.x * 128;
    float* bias = (float*)(smc + BIAS_OFF);

    // load z (channel-major gmem) -> RA [pos][chpack]; coalesced along pos
    {
        int posl = t & 127;
        int cg   = (t >> 7) * 32;        // 4 groups of 32 cols
        int P = p0 + posl;
        int b = P / NPOS, pos = P - b*NPOS;
        #pragma unroll
        for (int it = 0; it < 16; ++it) {
            int cc0 = cg + it*2;
            const float* s0 = (cc0 < 64 ? g_Zr : g_Zi)
                + ((size_t)b*512 + n*64 + (cc0 & 63))*NPOS + pos;
            float v0 = s0[0];
            float v1 = s0[NPOS];        // cc0+1 (same half: cc0 even, 64-aligned halves)
            wrPair(smc, RA_H, posl, cc0, v0, v1);
        }
    }
    copy64(smc, RB_H, g_W1h[n], g_W1l[n], t);
    copy64(smc, R3_H, g_W2h[n], g_W2l[n], t);
    if (t < 256) bias[t] = g_Bp[n][t];
    __syncthreads();

    float c[2][4][4];
    ZERO_C(c);
    gemm128(sb, c, lane, wm, wn, RA_H, RB_H);     // y1 = z @ W1
    __syncthreads();

    #pragma unroll
    for (int mt = 0; mt < 2; ++mt)
        #pragma unroll
        for (int nt = 0; nt < 4; ++nt) {
            int r0 = wm*32 + mt*16 + g, cb = wn*32 + nt*8 + tq*2;
            float b0 = bias[cb], b1v = bias[cb+1];
            #pragma unroll
            for (int hrow = 0; hrow < 2; ++hrow) {
                float v0 = c[mt][nt][hrow*2+0] + b0;
                float v1 = c[mt][nt][hrow*2+1] + b1v;
                v0 = 0.5f * v0 * (1.0f + erff(v0 * 0.70710678118654752f));
                v1 = 0.5f * v1 * (1.0f + erff(v1 * 0.70710678118654752f));
                wrPair(smc, RA_H, r0 + hrow*8, cb, v0, v1);
            }
        }
    __syncthreads();

    ZERO_C(c);
    gemm128(sb, c, lane, wm, wn, RA_H, R3_H);     // y2 = h @ W2
    __syncthreads();

    // stage y (bias + softshrink) into fbuf
    float* fbuf = (float*)smc;
    #pragma unroll
    for (int mt = 0; mt < 2; ++mt)
        #pragma unroll
        for (int nt = 0; nt < 4; ++nt) {
            int r0 = wm*32 + mt*16 + g, cb = wn*32 + nt*8 + tq*2;
            float b0 = bias[128 + cb], b1v = bias[128 + cb + 1];
            #pragma unroll
            for (int hrow = 0; hrow < 2; ++hrow) {
                float v0 = c[mt][nt][hrow*2+0] + b0;
                float v1 = c[mt][nt][hrow*2+1] + b1v;
                float s0 = fabsf(v0) - LAMBDA; v0 = (s0 > 0.f) ? copysignf(s0, v0) : 0.f;
                float s1 = fabsf(v1) - LAMBDA; v1 = (s1 > 0.f) ? copysignf(s1, v1) : 0.f;
                fbuf[(r0 + hrow*8)*129 + cb]     = v0;
                fbuf[(r0 + hrow*8)*129 + cb + 1] = v1;
            }
        }
    __syncthreads();

    // D = y - z, coalesced along pos
    {
        int posl = t & 127;
        int cg   = (t >> 7) * 32;
        int P = p0 + posl;
        int b = P / NPOS, pos = P - b*NPOS;
        #pragma unroll
        for (int it = 0; it < 32; ++it) {
            int cc = cg + it;
            size_t gi = ((size_t)b*512 + n*64 + (cc & 63))*NPOS + pos;
            const float* gZ = (cc < 64) ? g_Zr : g_Zi;
            float* gD = (cc < 64) ? g_Dr : g_Di;
            gD[gi] = fbuf[posl*129 + cc] - gZ[gi];
        }
    }
}

// ---------------------------------------------------------------------------
// K3: u = x + irfft2_ortho(D) per image.
//   gather D -> RB = dpack^T (B-layout)
//   stage1: G^T = B3^T @ dpack^T   (A=RA(B3T), B=RB)  -> C into RA
//   stage2: u = G^T @ B4           (A=RA, B=R3(B4))
// ---------------------------------------------------------------------------
__global__ __launch_bounds__(512) void k_inv_mma(const float* __restrict__ x)
{
    extern __shared__ char smc[];
    const uint32_t sb = smem_u32(smc);
    const int t = threadIdx.x, lane = t & 31, wid = t >> 5;
    const int wm = wid >> 2, wn = wid & 3;
    const int g = lane >> 2, tq = lane & 3;
    const int img = blockIdx.x, bimg = img >> 9, ch = img & 511;

    {   // zero RB (hi+lo)
        uint4 z = {0,0,0,0};
        uint4* pb = (uint4*)(smc + RB_H);
        for (int i = t; i < 4096; i += 512) pb[i] = z;
    }
    copy64(smc, RA_H, g_TWh[2], g_TWl[2], t);
    copy64(smc, R3_H, g_TWh[3], g_TWl[3], t);
    __syncthreads();

    // gather D (channel-major, coalesced) -> dpack^T in RB
    const size_t base = ((size_t)bimg*512 + ch) * NPOS;
    for (int o = t; o < NPOS; o += 512) {
        int k = o / 33, m = o - k*33;
        float a = g_Dr[base + o], b = g_Di[base + o];
        if (m == 0) { a *= 0.5f; b *= 0.5f; }
        wrOne(smc, RB_H, k,      m,      a);
        wrOne(smc, RB_H, k,      64 + m, b);
        wrOne(smc, RB_H, 64 + k, m,      b);
        wrOne(smc, RB_H, 64 + k, 64 + m, -a);
    }
    __syncthreads();

    float c[2][4][4];
    ZERO_C(c);
    gemm128(sb, c, lane, wm, wn, RA_H, RB_H);     // G^T = B3^T @ dpack^T
    __syncthreads();

    #pragma unroll
    for (int mt = 0; mt < 2; ++mt)
        #pragma unroll
        for (int nt = 0; nt < 4; ++nt) {
            int r0 = wm*32 + mt*16 + g, cb = wn*32 + nt*8 + tq*2;
            wrPair(smc, RA_H, r0,     cb, c[mt][nt][0], c[mt][nt][1]);
            wrPair(smc, RA_H, r0 + 8, cb, c[mt][nt][2], c[mt][nt][3]);
        }
    __syncthreads();

    ZERO_C(c);
    gemm128(sb, c, lane, wm, wn, RA_H, R3_H);     // u = G^T @ B4

    const float* xim = x + (size_t)img * 16384;
    __nv_bfloat16* uh = g_uh + (size_t)img * 16384;
    __nv_bfloat16* ul = g_ul + (size_t)img * 16384;
    #pragma unroll
    for (int mt = 0; mt < 2; ++mt)
        #pragma unroll
        for (int nt = 0; nt < 4; ++nt) {
            int r0 = wm*32 + mt*16 + g, cb = wn*32 + nt*8 + tq*2;
            #pragma unroll
            for (int hrow = 0; hrow < 2; ++hrow) {
                int r = r0 + hrow*8;
                float v0 = c[mt][nt][hrow*2 + 0];
                float v1 = c[mt][nt][hrow*2 + 1];
                int o = r*128 + cb;
                float2 xv = *(const float2*)(xim + o);
                float a = fmaf(v0, 0.015625f, xv.x);
                float b = fmaf(v1, 0.015625f, xv.y);
                float ha = bf_hi(a), hb = bf_hi(b);
                *(uint32_t*)(uh + o) = bf2_pack(a, b);
                *(uint32_t*)(ul + o) = bf2_pack(a - ha, b - hb);
            }
        }
}

// ---------------------------------------------------------------------------
// K_fc: fw fp32 -> hi/lo bf16
// ---------------------------------------------------------------------------
__global__ __launch_bounds__(1024) void k_fwconv(const float* __restrict__ fw)
{
    int i = blockIdx.x * 1024 + threadIdx.x;
    float v = fw[i];
    __nv_bfloat16 hv = __float2bfloat16(v);
    g_fwh[i] = hv;
    g_fwl[i] = __float2bfloat16(v - __bfloat162float(hv));
}

// ---------------------------------------------------------------------------
// K4: HMMA bf16 GEMM with hi/lo compensation (fuse conv + residual).
// ---------------------------------------------------------------------------
#define STG_B 32768
#define OFF_AH 0
#define OFF_AL 8192
#define OFF_BH 16384
#define OFF_BL 24576

__global__ __launch_bounds__(256) void k_gemm_mma(
    const float* __restrict__ x, float* __restrict__ out)
{
    extern __shared__ char smc[];
    const uint32_t sb = smem_u32(smc);
    const int t    = threadIdx.x;
    const int lane = t & 31;
    const int wid  = t >> 5;
    const int wm   = wid >> 1;
    const int wn   = wid & 1;
    const int m0   = blockIdx.x * 128;
    const int n0g  = blockIdx.y * 128;
    const int bimg = n0g >> 14;
    const int s0   = n0g & 16383;

    const char* pAh = (const char*)g_fwh;
    const char* pAl = (const char*)g_fwl;
    const char* pBh = (const char*)g_uh;
    const char* pBl = (const char*)g_ul;

    int ar0 = (t + 0)   >> 2, au0 = (t + 0)   & 3;
    int ar1 = (t + 256) >> 2, au1 = (t + 256) & 3;
    uint32_t adst0 = (uint32_t)(ar0*64 + ((au0 ^ ((ar0>>1)&3)) << 4));
    uint32_t adst1 = (uint32_t)(ar1*64 + ((au1 ^ ((ar1>>1)&3)) << 4));
    int br0 = (t + 0)   >> 4, bu0 = (t + 0)   & 15;
    int br1 = (t + 256) >> 4, bu1 = (t + 256) & 15;
    uint32_t bdst0 = (uint32_t)(br0*256 + ((bu0 ^ (br0&7)) << 4));
    uint32_t bdst1 = (uint32_t)(br1*256 + ((bu1 ^ (br1&7)) << 4));

    float c[2][8][4];
    #pragma unroll
    for (int i = 0; i < 2; ++i)
        #pragma unroll
        for (int j = 0; j < 8; ++j) {
            c[i][j][0] = 0.f; c[i][j][1] = 0.f; c[i][j][2] = 0.f; c[i][j][3] = 0.f;
        }

    const int lrow8 = (lane & 7) + 8*((lane >> 3) & 1);
    const int lsel  = lane >> 4;

    #define ISSUE_STAGE(kc, buf) do { \
        uint32_t st_ = sb + (buf)*STG_B; \
        { size_t so = ((size_t)(m0 + ar0)*512 + (kc)*32 + au0*8)*2; \
          CP16(st_ + OFF_AH + adst0, pAh + so); \
          CP16(st_ + OFF_AL + adst0, pAl + so); } \
        { size_t so = ((size_t)(m0 + ar1)*512 + (kc)*32 + au1*8)*2; \
          CP16(st_ + OFF_AH + adst1, pAh + so); \
          CP16(st_ + OFF_AL + adst1, pAl + so); } \
        { size_t so = ((size_t)(bimg*512 + (kc)*32 + br0)*16384 + s0 + bu0*8)*2; \
          CP16(st_ + OFF_BH + bdst0, pBh + so); \
          CP16(st_ + OFF_BL + bdst0, pBl + so); } \
        { size_t so = ((size_t)(bimg*512 + (kc)*32 + br1)*16384 + s0 + bu1*8)*2; \
          CP16(st_ + OFF_BH + bdst1, pBh + so); \
          CP16(st_ + OFF_BL + bdst1, pBl + so); } \
        CP_COMMIT(); \
    } while (0)

    ISSUE_STAGE(0, 0);
    ISSUE_STAGE(1, 1);

    for (int kc = 0; kc < 16; ++kc) {
        const int buf = kc & 1;
        if (kc < 14) { CP_WAIT(1); } else { CP_WAIT(0); }
        __syncthreads();

        const uint32_t st = sb + buf*STG_B;
        #pragma unroll
        for (int ks = 0; ks < 2; ++ks) {
            uint32_t ah[2][4], al[2][4], bh[4][4], bl[4][4];
            #pragma unroll
            for (int mt = 0; mt < 2; ++mt) {
                int row  = wm*32 + mt*16 + lrow8;
                int unit = ks*2 + lsel;
                uint32_t off = (uint32_t)(row*64 + ((unit ^ ((row>>1)&3)) << 4));
                LDSM4(ah[mt], st + OFF_AH + off);
                LDSM4(al[mt], st + OFF_AL + off);
            }
            #pragma unroll
            for (int nq = 0; nq < 4; ++nq) {
                int krow = ks*16 + lrow8;
                int unit = wn*8 + nq*2 + lsel;
                uint32_t off = (uint32_t)(krow*256 + ((unit ^ (krow&7)) << 4));
                LDSM4T(bh[nq], st + OFF_BH + off);
                LDSM4T(bl[nq], st + OFF_BL + off);
            }
            #pragma unroll
            for (int mt = 0; mt < 2; ++mt)
                #pragma unroll
                for (int nt = 0; nt < 8; ++nt) {
                    const int nq = nt >> 1, hb = (nt & 1) * 2;
                    MMA_BF16(c[mt][nt], ah[mt], bh[nq][hb], bh[nq][hb+1]);
                    MMA_BF16(c[mt][nt], ah[mt], bl[nq][hb], bl[nq][hb+1]);
                    MMA_BF16(c[mt][nt], al[mt], bh[nq][hb], bh[nq][hb+1]);
                }
        }
        __syncthreads();
        if (kc + 2 < 16) ISSUE_STAGE(kc + 2, buf);
    }

    const int g  = lane >> 2;
    const int tq = lane & 3;
    const size_t obase = (size_t)(bimg * 512);
    #pragma unroll
    for (int mt = 0; mt < 2; ++mt)
        #pragma unroll
        for (int nt = 0; nt < 8; ++nt) {
            int row0 = m0 + wm*32 + mt*16 + g;
            int col  = s0 + wn*64 + nt*8 + tq*2;
            size_t go = (obase + row0)*16384 + col;
            float2 xv = *(const float2*)(x + go);
            float2 ov = { c[mt][nt][0] + xv.x, c[mt][nt][1] + xv.y };
            *(float2*)(out + go) = ov;
            go += (size_t)8 * 16384;
            xv = *(const float2*)(x + go);
            float2 ov2 = { c[mt][nt][2] + xv.x, c[mt][nt][3] + xv.y };
            *(float2*)(out + go) = ov2;
        }
}

// ---------------------------------------------------------------------------
#define SMEM_GMM (2 * STG_B)

extern "C" void kernel_launch(void* const* d_in, const int* in_sizes, int n_in,
                              void* d_out, int out_size)
{
    const float* x   = (const float*)d_in[0];
    const float* w1r = (const float*)d_in[1];
    const float* w1i = (const float*)d_in[2];
    const float* b1r = (const float*)d_in[3];
    const float* b1i = (const float*)d_in[4];
    const float* w2r = (const float*)d_in[5];
    const float* w2i = (const float*)d_in[6];
    const float* b2r = (const float*)d_in[7];
    const float* b2i = (const float*)d_in[8];
    const float* fw  = (const float*)d_in[9];
    float* out = (float*)d_out;

    cudaFuncSetAttribute(k_fwd_mma, cudaFuncAttributeMaxDynamicSharedMemorySize, SMEM_K);
    cudaFuncSetAttribute(k_inv_mma, cudaFuncAttributeMaxDynamicSharedMemorySize, SMEM_K);
    cudaFuncSetAttribute(k_mlp_mma, cudaFuncAttributeMaxDynamicSharedMemorySize, SMEM_K);
    cudaFuncSetAttribute(k_gemm_mma,cudaFuncAttributeMaxDynamicSharedMemorySize, SMEM_GMM);

    k_twiddle<<<256, 256>>>();
    k_wpack<<<1024, 256>>>(w1r, w1i, w2r, w2i, b1r, b1i, b2r, b2i);
    k_fwconv<<<256, 1024>>>(fw);

    k_fwd_mma<<<BB*CC, 512, SMEM_K>>>(x);

    dim3 g2((BB*NPOS)/128, NBQ);
    k_mlp_mma<<<g2, 512, SMEM_K>>>();

    k_inv_mma<<<BB*CC, 512, SMEM_K>>>(x);

    dim3 gg(4, BB*16384/128);
    k_gemm_mma<<<gg, 256, SMEM_GMM>>>(x, out);
}

// round 10
// speedup vs baseline: 7.9074x; 1.6294x over previous
#include <cuda_runtime.h>
#include <cuda_fp16.h>
#include <math.h>
#include <stdint.h>

// ---------------------------------------------------------------------------
// AFNO2D: out = x + fuse_w @ (x + irfft2(D)),   D = masked_MLP(Z) - Z on the
// 64x33 low-frequency region of Z = rfft2(x, ortho).
// All dense stages on HMMA fp16, 2-term compensation: data operand split
// hi+lo fp16, fixed operand (twiddles / weights / u) single fp16.
// DFT/MLP kernels sized for 2 CTAs/SM (97KB smem, 64 regs).
// ---------------------------------------------------------------------------

#define BB   4
#define CC   512
#define NPOS (64*33)
#define NBQ  8
#define LAMBDA 0.01f
#define TWO_PI 6.28318530717958647692f

// Scratch (allocation-free rule).  Z/D channel-major: [(b*512+ch)*2112 + pos]
__device__ float g_Zr[(size_t)BB*CC*NPOS];
__device__ float g_Zi[(size_t)BB*CC*NPOS];
__device__ float g_Dr[(size_t)BB*CC*NPOS];
__device__ float g_Di[(size_t)BB*CC*NPOS];
__device__ __half g_u[(size_t)BB*CC*128*128];          // u single fp16 [b][c][s]
__device__ __half g_fwh[(size_t)CC*CC];                // fw hi [o][c]
__device__ __half g_fwl[(size_t)CC*CC];                // fw lo
// fixed matrices, PRE-SWIZZLED, single fp16:
//  mat0 = B1 [x][j]   mat1 = B2^T [c][h]   mat2 = B3^T [h][kk]   mat3 = B4 [j][xx]
__device__ __align__(16) __half g_TW[4][16384];
__device__ __align__(16) __half g_W1[NBQ][16384];      // [[wr,wi],[-wi,wr]]
__device__ __align__(16) __half g_W2[NBQ][16384];
__device__ float g_Bp[NBQ][256];

// ======================= helpers =============================
__device__ __forceinline__ uint32_t smem_u32(const void* p) {
    uint32_t a;
    asm("{ .reg .u64 t; cvta.to.shared.u64 t, %1; cvt.u32.u64 %0, t; }"
        : "=r"(a) : "l"(p));
    return a;
}
#define CP16(dst, src) \
    asm volatile("cp.async.cg.shared.global [%0], [%1], 16;" \
        :: "r"(dst), "l"(src) : "memory")
#define CP_COMMIT() asm volatile("cp.async.commit_group;" ::: "memory")
#define CP_WAIT(n)  asm volatile("cp.async.wait_group %0;" :: "n"(n) : "memory")

#define LDSM4(R, a) \
    asm volatile("ldmatrix.sync.aligned.m8n8.x4.shared.b16 {%0,%1,%2,%3}, [%4];" \
        : "=r"((R)[0]), "=r"((R)[1]), "=r"((R)[2]), "=r"((R)[3]) : "r"(a))
#define LDSM4T(R, a) \
    asm volatile("ldmatrix.sync.aligned.m8n8.x4.trans.shared.b16 {%0,%1,%2,%3}, [%4];" \
        : "=r"((R)[0]), "=r"((R)[1]), "=r"((R)[2]), "=r"((R)[3]) : "r"(a))
#define MMA_F16(C, A, B0, B1) \
    asm volatile("mma.sync.aligned.m16n8k16.row.col.f32.f16.f16.f32 " \
        "{%0,%1,%2,%3},{%4,%5,%6,%7},{%8,%9},{%0,%1,%2,%3};" \
        : "+f"((C)[0]), "+f"((C)[1]), "+f"((C)[2]), "+f"((C)[3]) \
        : "r"((A)[0]), "r"((A)[1]), "r"((A)[2]), "r"((A)[3]), "r"(B0), "r"(B1))

__device__ __forceinline__ uint32_t hp2(float a, float b) {
    __half2 h = __floats2half2_rn(a, b);
    return *(uint32_t*)&h;
}
__device__ __forceinline__ float h_hi(float v) {
    return __half2float(__float2half_rn(v));
}

// smem regions (bytes): data hi 32K, data lo 32K, fixed 32K, bias 1K
#define RD_H 0
#define RD_L 32768
#define RT_O 65536
#define BIAS_OFF 98304
#define SMEM_K 99328
// fp32 staging buffer (128x129 floats = 66048 B) overlaps RD/RT after GEMMs

__device__ __forceinline__ uint32_t sw_addr(int r, int c) {
    return (uint32_t)(r*256 + ((((c>>3) ^ (r&7)))<<4) + ((c&7)<<1));
}
__device__ __forceinline__ void wrPair(char* smc, int r, int c, float v0, float v1) {
    uint32_t off = sw_addr(r, c);
    float h0 = h_hi(v0), h1 = h_hi(v1);
    *(uint32_t*)(smc + RD_H + off) = hp2(v0, v1);
    *(uint32_t*)(smc + RD_L + off) = hp2(v0 - h0, v1 - h1);
}
__device__ __forceinline__ void wrOne(char* smc, int r, int c, float v) {
    uint32_t off = sw_addr(r, c);
    __half hb = __float2half_rn(v);
    *(__half*)(smc + RD_H + off) = hb;
    *(__half*)(smc + RD_L + off) = __float2half_rn(v - __half2float(hb));
}

// C += A @ B: A = data hi/lo (RD), B = fixed single (RT). 16 warps, 128^3.
__device__ __forceinline__ void gemm_accA(
    uint32_t sb, float c[2][4][4], int lane, int wm, int wn)
{
    const int lrow8 = (lane & 7) + 8*((lane >> 3) & 1);
    const int lsel  = lane >> 4;
    #pragma unroll
    for (int kc = 0; kc < 8; ++kc) {
        uint32_t ah[2][4], al[2][4], bh[2][4];
        #pragma unroll
        for (int mt = 0; mt < 2; ++mt) {
            int row  = wm*32 + mt*16 + lrow8;
            int unit = kc*2 + lsel;
            uint32_t off = (uint32_t)(row*256 + ((unit ^ (row&7))<<4));
            LDSM4(ah[mt], sb + RD_H + off);
            LDSM4(al[mt], sb + RD_L + off);
        }
        #pragma unroll
        for (int nq = 0; nq < 2; ++nq) {
            int krow = kc*16 + lrow8;
            int unit = wn*4 + nq*2 + lsel;
            uint32_t off = (uint32_t)(krow*256 + ((unit ^ (krow&7))<<4));
            LDSM4T(bh[nq], sb + RT_O + off);
        }
        #pragma unroll
        for (int mt = 0; mt < 2; ++mt)
            #pragma unroll
            for (int nt = 0; nt < 4; ++nt) {
                int nq = nt >> 1, hb = (nt & 1)*2;
                MMA_F16(c[mt][nt], ah[mt], bh[nq][hb], bh[nq][hb+1]);
                MMA_F16(c[mt][nt], al[mt], bh[nq][hb], bh[nq][hb+1]);
            }
    }
}

// C += A @ B: A = fixed single (RT), B = data hi/lo (RD).
__device__ __forceinline__ void gemm_accB(
    uint32_t sb, float c[2][4][4], int lane, int wm, int wn)
{
    const int lrow8 = (lane & 7) + 8*((lane >> 3) & 1);
    const int lsel  = lane >> 4;
    #pragma unroll
    for (int kc = 0; kc < 8; ++kc) {
        uint32_t ah[2][4], bh[2][4], bl[2][4];
        #pragma unroll
        for (int mt = 0; mt < 2; ++mt) {
            int row  = wm*32 + mt*16 + lrow8;
            int unit = kc*2 + lsel;
            uint32_t off = (uint32_t)(row*256 + ((unit ^ (row&7))<<4));
            LDSM4(ah[mt], sb + RT_O + off);
        }
        #pragma unroll
        for (int nq = 0; nq < 2; ++nq) {
            int krow = kc*16 + lrow8;
            int unit = wn*4 + nq*2 + lsel;
            uint32_t off = (uint32_t)(krow*256 + ((unit ^ (krow&7))<<4));
            LDSM4T(bh[nq], sb + RD_H + off);
            LDSM4T(bl[nq], sb + RD_L + off);
        }
        #pragma unroll
        for (int mt = 0; mt < 2; ++mt)
            #pragma unroll
            for (int nt = 0; nt < 4; ++nt) {
                int nq = nt >> 1, hb = (nt & 1)*2;
                MMA_F16(c[mt][nt], ah[mt], bh[nq][hb], bh[nq][hb+1]);
                MMA_F16(c[mt][nt], ah[mt], bl[nq][hb], bl[nq][hb+1]);
            }
    }
}

#define ZERO_C(c) do { \
    _Pragma("unroll") for (int i_ = 0; i_ < 2; ++i_) \
        _Pragma("unroll") for (int j_ = 0; j_ < 4; ++j_) { \
            (c)[i_][j_][0]=0.f; (c)[i_][j_][1]=0.f; \
            (c)[i_][j_][2]=0.f; (c)[i_][j_][3]=0.f; } \
} while (0)

// copy one 32KB fixed matrix into RT
__device__ __forceinline__ void copyT(char* smc, const __half* src, int t) {
    const uint4* s = (const uint4*)src;
    uint4* d = (uint4*)(smc + RT_O);
    for (int i = t; i < 2048; i += 512) d[i] = s[i];
}

// ---------------------------------------------------------------------------
// twiddle init (single fp16, pre-swizzled)
// ---------------------------------------------------------------------------
__global__ __launch_bounds__(256) void k_twiddle(void)
{
    int idx = blockIdx.x*256 + threadIdx.x;      // 0..65535
    int mat = idx >> 14;
    int r   = (idx >> 7) & 127;
    int cq  = idx & 127;
    float v = 0.0f;
    const float W = TWO_PI / 128.0f;
    if (mat == 0) {              // B1 [x][j]
        if (cq < 33)                  v =  cosf(W*((r*cq) & 127));
        else if (cq >= 64 && cq < 97) v = -sinf(W*((r*(cq-64)) & 127));
    } else if (mat == 1) {       // B2^T [c][h]
        if (r < 64) v = cosf(W*((r*cq) & 127));
        else        v = sinf(W*(((r-64)*cq) & 127));
    } else if (mat == 2) {       // B3^T [h][kk]
        if (cq < 64) v =  cosf(W*((r*cq) & 127));
        else         v = -sinf(W*(((cq-64)*r) & 127));
    } else {                     // B4 [j][xx]
        if (r < 33)                 v =  cosf(W*((r*cq) & 127));
        else if (r >= 64 && r < 97) v = -sinf(W*(((r-64)*cq) & 127));
    }
    g_TW[mat][sw_addr(r, cq) >> 1] = __float2half_rn(v);
}

// ---------------------------------------------------------------------------
// pack MLP weights (single fp16, pre-swizzled) + biases
// ---------------------------------------------------------------------------
__global__ __launch_bounds__(256) void k_wpack(
    const float* __restrict__ w1r, const float* __restrict__ w1i,
    const float* __restrict__ w2r, const float* __restrict__ w2i,
    const float* __restrict__ b1r, const float* __restrict__ b1i,
    const float* __restrict__ b2r, const float* __restrict__ b2i)
{
    int idx = blockIdx.x*256 + threadIdx.x;      // 0..262143
    int l   = idx >> 17;
    int rem = idx & 131071;
    int n   = rem >> 14;
    int r   = (rem >> 7) & 127;
    int cq  = rem & 127;
    const float* wr;
    const float* wi;
    if (l == 0) { wr = w1r; wi = w1i; } else { wr = w2r; wi = w2i; }
    float v;
    if (r < 64) v = (cq < 64) ?  wr[n*4096 + r*64 + cq]
                              :  wi[n*4096 + r*64 + (cq-64)];
    else        v = (cq < 64) ? -wi[n*4096 + (r-64)*64 + cq]
                              :  wr[n*4096 + (r-64)*64 + (cq-64)];
    uint32_t ei = sw_addr(r, cq) >> 1;
    if (l == 0) g_W1[n][ei] = __float2half_rn(v);
    else        g_W2[n][ei] = __float2half_rn(v);

    if (idx < NBQ*256) {
        int bn = idx >> 8, j = idx & 255;
        float bv;
        if      (j < 64)  bv = b1r[bn*64 + j];
        else if (j < 128) bv = b1i[bn*64 + j - 64];
        else if (j < 192) bv = b2r[bn*64 + j - 128];
        else              bv = b2i[bn*64 + j - 192];
        g_Bp[bn][j] = bv;
    }
}

// ---------------------------------------------------------------------------
// K1: forward restricted rfft2 per image.
//   stage1: mid = X @ B1      (A=RD(X hi/lo), B=RT(B1))       -> C into RD
//   stage2: outT = B2^T @ mid (A=RT(B2T), B=RD(mid hi/lo))
// ---------------------------------------------------------------------------
__global__ __launch_bounds__(512, 2) void k_fwd_mma(const float* __restrict__ x)
{
    extern __shared__ char smc[];
    const uint32_t sb = smem_u32(smc);
    const int t = threadIdx.x, lane = t & 31, wid = t >> 5;
    const int wm = wid >> 2, wn = wid & 3;
    const int g = lane >> 2, tq = lane & 3;
    const int img = blockIdx.x, bimg = img >> 9, ch = img & 511;
    const float* src = x + (size_t)img * 16384;

    for (int i = t*4; i < 16384; i += 2048) {
        float4 v = *(const float4*)(src + i);
        int r = i >> 7, c0 = i & 127;
        uint32_t off = sw_addr(r, c0);
        float hx = h_hi(v.x), hy = h_hi(v.y), hz = h_hi(v.z), hw = h_hi(v.w);
        uint2 hh = { hp2(v.x, v.y), hp2(v.z, v.w) };
        uint2 ll = { hp2(v.x-hx, v.y-hy), hp2(v.z-hz, v.w-hw) };
        *(uint2*)(smc + RD_H + off) = hh;
        *(uint2*)(smc + RD_L + off) = ll;
    }
    copyT(smc, g_TW[0], t);
    __syncthreads();

    float c[2][4][4];
    ZERO_C(c);
    gemm_accA(sb, c, lane, wm, wn);               // mid = X @ B1
    __syncthreads();

    #pragma unroll
    for (int mt = 0; mt < 2; ++mt)
        #pragma unroll
        for (int nt = 0; nt < 4; ++nt) {
            int r0 = wm*32 + mt*16 + g, cb = wn*32 + nt*8 + tq*2;
            wrPair(smc, r0,     cb, c[mt][nt][0], c[mt][nt][1]);
            wrPair(smc, r0 + 8, cb, c[mt][nt][2], c[mt][nt][3]);
        }
    copyT(smc, g_TW[1], t);
    __syncthreads();

    ZERO_C(c);
    gemm_accB(sb, c, lane, wm, wn);               // outT = B2^T @ mid
    __syncthreads();

    float* fbuf = (float*)smc;                    // [128][129]
    #pragma unroll
    for (int mt = 0; mt < 2; ++mt)
        #pragma unroll
        for (int nt = 0; nt < 4; ++nt) {
            int r0 = wm*32 + mt*16 + g, cb = wn*32 + nt*8 + tq*2;
            fbuf[r0*129 + cb]       = c[mt][nt][0];
            fbuf[r0*129 + cb + 1]   = c[mt][nt][1];
            fbuf[(r0+8)*129 + cb]   = c[mt][nt][2];
            fbuf[(r0+8)*129 + cb+1] = c[mt][nt][3];
        }
    __syncthreads();

    const size_t base = ((size_t)bimg*512 + ch) * NPOS;
    for (int o = t; o < NPOS; o += 512) {
        int k = o / 33, m = o - k*33;
        float zr = (fbuf[k*129 + m]      + fbuf[(64+k)*129 + 64+m]) * 0.0078125f;
        float zi = (fbuf[k*129 + 64+m]   - fbuf[(64+k)*129 + m])    * 0.0078125f;
        g_Zr[base + o] = zr;
        g_Zi[base + o] = zi;
    }
}

// ---------------------------------------------------------------------------
// K2: block-diagonal complex MLP.
// ---------------------------------------------------------------------------
__global__ __launch_bounds__(512, 2) void k_mlp_mma(void)
{
    extern __shared__ char smc[];
    const uint32_t sb = smem_u32(smc);
    const int t = threadIdx.x, lane = t & 31, wid = t >> 5;
    const int wm = wid >> 2, wn = wid & 3;
    const int g = lane >> 2, tq = lane & 3;
    const int n  = blockIdx.y;
    const int p0 = blockIdx.x * 128;
    float* bias = (float*)(smc + BIAS_OFF);

    {   // load z (channel-major) -> RD hi/lo, coalesced along pos
        int posl = t & 127;
        int cg   = (t >> 7) * 32;
        int P = p0 + posl;
        int b = P / NPOS, pos = P - b*NPOS;
        #pragma unroll
        for (int it = 0; it < 16; ++it) {
            int cc0 = cg + it*2;
            const float* s0 = (cc0 < 64 ? g_Zr : g_Zi)
                + ((size_t)b*512 + n*64 + (cc0 & 63))*NPOS + pos;
            float v0 = s0[0];
            float v1 = s0[NPOS];
            wrPair(smc, posl, cc0, v0, v1);
        }
    }
    copyT(smc, g_W1[n], t);
    if (t < 256) bias[t] = g_Bp[n][t];
    __syncthreads();

    float c[2][4][4];
    ZERO_C(c);
    gemm_accA(sb, c, lane, wm, wn);               // y1 = z @ W1
    __syncthreads();

    #pragma unroll
    for (int mt = 0; mt < 2; ++mt)
        #pragma unroll
        for (int nt = 0; nt < 4; ++nt) {
            int r0 = wm*32 + mt*16 + g, cb = wn*32 + nt*8 + tq*2;
            float b0 = bias[cb], b1v = bias[cb+1];
            #pragma unroll
            for (int hrow = 0; hrow < 2; ++hrow) {
                float v0 = c[mt][nt][hrow*2+0] + b0;
                float v1 = c[mt][nt][hrow*2+1] + b1v;
                v0 = 0.5f * v0 * (1.0f + erff(v0 * 0.70710678118654752f));
                v1 = 0.5f * v1 * (1.0f + erff(v1 * 0.70710678118654752f));
                wrPair(smc, r0 + hrow*8, cb, v0, v1);
            }
        }
    copyT(smc, g_W2[n], t);
    __syncthreads();

    ZERO_C(c);
    gemm_accA(sb, c, lane, wm, wn);               // y2 = h @ W2
    __syncthreads();

    float* fbuf = (float*)smc;
    #pragma unroll
    for (int mt = 0; mt < 2; ++mt)
        #pragma unroll
        for (int nt = 0; nt < 4; ++nt) {
            int r0 = wm*32 + mt*16 + g, cb = wn*32 + nt*8 + tq*2;
            float b0 = bias[128 + cb], b1v = bias[128 + cb + 1];
            #pragma unroll
            for (int hrow = 0; hrow < 2; ++hrow) {
                float v0 = c[mt][nt][hrow*2+0] + b0;
                float v1 = c[mt][nt][hrow*2+1] + b1v;
                float s0 = fabsf(v0) - LAMBDA; v0 = (s0 > 0.f) ? copysignf(s0, v0) : 0.f;
                float s1 = fabsf(v1) - LAMBDA; v1 = (s1 > 0.f) ? copysignf(s1, v1) : 0.f;
                fbuf[(r0 + hrow*8)*129 + cb]     = v0;
                fbuf[(r0 + hrow*8)*129 + cb + 1] = v1;
            }
        }
    __syncthreads();

    {   // D = y - z, coalesced along pos
        int posl = t & 127;
        int cg   = (t >> 7) * 32;
        int P = p0 + posl;
        int b = P / NPOS, pos = P - b*NPOS;
        #pragma unroll
        for (int it = 0; it < 32; ++it) {
            int cc = cg + it;
            size_t gi = ((size_t)b*512 + n*64 + (cc & 63))*NPOS + pos;
            const float* gZ = (cc < 64) ? g_Zr : g_Zi;
            float* gD = (cc < 64) ? g_Dr : g_Di;
            gD[gi] = fbuf[posl*129 + cc] - gZ[gi];
        }
    }
}

// ---------------------------------------------------------------------------
// K3: u = x + irfft2_ortho(D) per image -> single fp16 u.
//   stage1: G^T = B3^T @ dpack^T  (A=RT(B3T), B=RD(dpackT hi/lo)) -> RD
//   stage2: u = G^T @ B4          (A=RD(GT hi/lo), B=RT(B4))
// ---------------------------------------------------------------------------
__global__ __launch_bounds__(512, 2) void k_inv_mma(const float* __restrict__ x)
{
    extern __shared__ char smc[];
    const uint32_t sb = smem_u32(smc);
    const int t = threadIdx.x, lane = t & 31, wid = t >> 5;
    const int wm = wid >> 2, wn = wid & 3;
    const int g = lane >> 2, tq = lane & 3;
    const int img = blockIdx.x, bimg = img >> 9, ch = img & 511;

    {   // zero RD (hi+lo = 64KB)
        uint4 z = {0,0,0,0};
        uint4* pd = (uint4*)(smc + RD_H);
        for (int i = t; i < 4096; i += 512) pd[i] = z;
    }
    copyT(smc, g_TW[2], t);
    __syncthreads();

    const size_t base = ((size_t)bimg*512 + ch) * NPOS;
    for (int o = t; o < NPOS; o += 512) {
        int k = o / 33, m = o - k*33;
        float a = g_Dr[base + o], b = g_Di[base + o];
        if (m == 0) { a *= 0.5f; b *= 0.5f; }
        wrOne(smc, k,      m,      a);
        wrOne(smc, k,      64 + m, b);
        wrOne(smc, 64 + k, m,      b);
        wrOne(smc, 64 + k, 64 + m, -a);
    }
    __syncthreads();

    float c[2][4][4];
    ZERO_C(c);
    gemm_accB(sb, c, lane, wm, wn);               // G^T = B3^T @ dpack^T
    __syncthreads();

    #pragma unroll
    for (int mt = 0; mt < 2; ++mt)
        #pragma unroll
        for (int nt = 0; nt < 4; ++nt) {
            int r0 = wm*32 + mt*16 + g, cb = wn*32 + nt*8 + tq*2;
            wrPair(smc, r0,     cb, c[mt][nt][0], c[mt][nt][1]);
            wrPair(smc, r0 + 8, cb, c[mt][nt][2], c[mt][nt][3]);
        }
    copyT(smc, g_TW[3], t);
    __syncthreads();

    ZERO_C(c);
    gemm_accA(sb, c, lane, wm, wn);               // u = G^T @ B4

    const float* xim = x + (size_t)img * 16384;
    __half* up = g_u + (size_t)img * 16384;
    #pragma unroll
    for (int mt = 0; mt < 2; ++mt)
        #pragma unroll
        for (int nt = 0; nt < 4; ++nt) {
            int r0 = wm*32 + mt*16 + g, cb = wn*32 + nt*8 + tq*2;
            #pragma unroll
            for (int hrow = 0; hrow < 2; ++hrow) {
                int r = r0 + hrow*8;
                float v0 = c[mt][nt][hrow*2 + 0];
                float v1 = c[mt][nt][hrow*2 + 1];
                int o = r*128 + cb;
                float2 xv = *(const float2*)(xim + o);
                float a = fmaf(v0, 0.015625f, xv.x);
                float b = fmaf(v1, 0.015625f, xv.y);
                *(uint32_t*)(up + o) = hp2(a, b);
            }
        }
}

// ---------------------------------------------------------------------------
// K_fc: fw fp32 -> hi/lo fp16
// ---------------------------------------------------------------------------
__global__ __launch_bounds__(1024) void k_fwconv(const float* __restrict__ fw)
{
    int i = blockIdx.x * 1024 + threadIdx.x;
    float v = fw[i];
    __half hv = __float2half_rn(v);
    g_fwh[i] = hv;
    g_fwl[i] = __float2half_rn(v - __half2float(hv));
}

// ---------------------------------------------------------------------------
// K4: HMMA fp16 GEMM: A = fw hi/lo (compensated), B = u single fp16.
// out = x + fw @ u.  CTA 128x128, 8 warps, K-chunk 32, cp.async 2 stages.
// ---------------------------------------------------------------------------
#define STG_B 24576
#define OFF_AH 0
#define OFF_AL 8192
#define OFF_B  16384

__global__ __launch_bounds__(256, 2) void k_gemm_mma(
    const float* __restrict__ x, float* __restrict__ out)
{
    extern __shared__ char smc[];
    const uint32_t sb = smem_u32(smc);
    const int t    = threadIdx.x;
    const int lane = t & 31;
    const int wid  = t >> 5;
    const int wm   = wid >> 1;
    const int wn   = wid & 1;
    const int m0   = blockIdx.x * 128;
    const int n0g  = blockIdx.y * 128;
    const int bimg = n0g >> 14;
    const int s0   = n0g & 16383;

    const char* pAh = (const char*)g_fwh;
    const char* pAl = (const char*)g_fwl;
    const char* pB  = (const char*)g_u;

    int ar0 = (t + 0)   >> 2, au0 = (t + 0)   & 3;
    int ar1 = (t + 256) >> 2, au1 = (t + 256) & 3;
    uint32_t adst0 = (uint32_t)(ar0*64 + ((au0 ^ ((ar0>>1)&3)) << 4));
    uint32_t adst1 = (uint32_t)(ar1*64 + ((au1 ^ ((ar1>>1)&3)) << 4));
    int br0 = (t + 0)   >> 4, bu0 = (t + 0)   & 15;
    int br1 = (t + 256) >> 4, bu1 = (t + 256) & 15;
    uint32_t bdst0 = (uint32_t)(br0*256 + ((bu0 ^ (br0&7)) << 4));
    uint32_t bdst1 = (uint32_t)(br1*256 + ((bu1 ^ (br1&7)) << 4));

    float c[2][8][4];
    #pragma unroll
    for (int i = 0; i < 2; ++i)
        #pragma unroll
        for (int j = 0; j < 8; ++j) {
            c[i][j][0] = 0.f; c[i][j][1] = 0.f; c[i][j][2] = 0.f; c[i][j][3] = 0.f;
        }

    const int lrow8 = (lane & 7) + 8*((lane >> 3) & 1);
    const int lsel  = lane >> 4;

    #define ISSUE_STAGE(kc, buf) do { \
        uint32_t st_ = sb + (buf)*STG_B; \
        { size_t so = ((size_t)(m0 + ar0)*512 + (kc)*32 + au0*8)*2; \
          CP16(st_ + OFF_AH + adst0, pAh + so); \
          CP16(st_ + OFF_AL + adst0, pAl + so); } \
        { size_t so = ((size_t)(m0 + ar1)*512 + (kc)*32 + au1*8)*2; \
          CP16(st_ + OFF_AH + adst1, pAh + so); \
          CP16(st_ + OFF_AL + adst1, pAl + so); } \
        { size_t so = ((size_t)(bimg*512 + (kc)*32 + br0)*16384 + s0 + bu0*8)*2; \
          CP16(st_ + OFF_B + bdst0, pB + so); } \
        { size_t so = ((size_t)(bimg*512 + (kc)*32 + br1)*16384 + s0 + bu1*8)*2; \
          CP16(st_ + OFF_B + bdst1, pB + so); } \
        CP_COMMIT(); \
    } while (0)

    ISSUE_STAGE(0, 0);
    ISSUE_STAGE(1, 1);

    for (int kc = 0; kc < 16; ++kc) {
        const int buf = kc & 1;
        if (kc < 14) { CP_WAIT(1); } else { CP_WAIT(0); }
        __syncthreads();

        const uint32_t st = sb + buf*STG_B;
        #pragma unroll
        for (int ks = 0; ks < 2; ++ks) {
            uint32_t ah[2][4], al[2][4], bh[4][4];
            #pragma unroll
            for (int mt = 0; mt < 2; ++mt) {
                int row  = wm*32 + mt*16 + lrow8;
                int unit = ks*2 + lsel;
                uint32_t off = (uint32_t)(row*64 + ((unit ^ ((row>>1)&3)) << 4));
                LDSM4(ah[mt], st + OFF_AH + off);
                LDSM4(al[mt], st + OFF_AL + off);
            }
            #pragma unroll
            for (int nq = 0; nq < 4; ++nq) {
                int krow = ks*16 + lrow8;
                int unit = wn*8 + nq*2 + lsel;
                uint32_t off = (uint32_t)(krow*256 + ((unit ^ (krow&7)) << 4));
                LDSM4T(bh[nq], st + OFF_B + off);
            }
            #pragma unroll
            for (int mt = 0; mt < 2; ++mt)
                #pragma unroll
                for (int nt = 0; nt < 8; ++nt) {
                    const int nq = nt >> 1, hb = (nt & 1) * 2;
                    MMA_F16(c[mt][nt], ah[mt], bh[nq][hb], bh[nq][hb+1]);
                    MMA_F16(c[mt][nt], al[mt], bh[nq][hb], bh[nq][hb+1]);
                }
        }
        __syncthreads();
        if (kc + 2 < 16) ISSUE_STAGE(kc + 2, buf);
    }

    const int g  = lane >> 2;
    const int tq = lane & 3;
    const size_t obase = (size_t)(bimg * 512);
    #pragma unroll
    for (int mt = 0; mt < 2; ++mt)
        #pragma unroll
        for (int nt = 0; nt < 8; ++nt) {
            int row0 = m0 + wm*32 + mt*16 + g;
            int col  = s0 + wn*64 + nt*8 + tq*2;
            size_t go = (obase + row0)*16384 + col;
            float2 xv = *(const float2*)(x + go);
            float2 ov = { c[mt][nt][0] + xv.x, c[mt][nt][1] + xv.y };
            *(float2*)(out + go) = ov;
            go += (size_t)8 * 16384;
            xv = *(const float2*)(x + go);
            float2 ov2 = { c[mt][nt][2] + xv.x, c[mt][nt][3] + xv.y };
            *(float2*)(out + go) = ov2;
        }
}

// ---------------------------------------------------------------------------
#define SMEM_GMM (2 * STG_B)

extern "C" void kernel_launch(void* const* d_in, const int* in_sizes, int n_in,
                              void* d_out, int out_size)
{
    const float* x   = (const float*)d_in[0];
    const float* w1r = (const float*)d_in[1];
    const float* w1i = (const float*)d_in[2];
    const float* b1r = (const float*)d_in[3];
    const float* b1i = (const float*)d_in[4];
    const float* w2r = (const float*)d_in[5];
    const float* w2i = (const float*)d_in[6];
    const float* b2r = (const float*)d_in[7];
    const float* b2i = (const float*)d_in[8];
    const float* fw  = (const float*)d_in[9];
    float* out = (float*)d_out;

    cudaFuncSetAttribute(k_fwd_mma, cudaFuncAttributeMaxDynamicSharedMemorySize, SMEM_K);
    cudaFuncSetAttribute(k_inv_mma, cudaFuncAttributeMaxDynamicSharedMemorySize, SMEM_K);
    cudaFuncSetAttribute(k_mlp_mma, cudaFuncAttributeMaxDynamicSharedMemorySize, SMEM_K);
    cudaFuncSetAttribute(k_gemm_mma,cudaFuncAttributeMaxDynamicSharedMemorySize, SMEM_GMM);

    k_twiddle<<<256, 256>>>();
    k_wpack<<<1024, 256>>>(w1r, w1i, w2r, w2i, b1r, b1i, b2r, b2i);
    k_fwconv<<<256, 1024>>>(fw);

    k_fwd_mma<<<BB*CC, 512, SMEM_K>>>(x);

    dim3 g2((BB*NPOS)/128, NBQ);
    k_mlp_mma<<<g2, 512, SMEM_K>>>();

    k_inv_mma<<<BB*CC, 512, SMEM_K>>>(x);

    dim3 gg(4, BB*16384/128);
    k_gemm_mma<<<gg, 256, SMEM_GMM>>>(x, out);
}

// round 12
// speedup vs baseline: 9.6577x; 1.2213x over previous
#include <cuda_runtime.h>
#include <cuda_fp16.h>
#include <math.h>
#include <stdint.h>

// ---------------------------------------------------------------------------
// AFNO2D: out = x + fuse_w @ (x + irfft2(D)),   D = masked_MLP(Z) - Z on the
// 64x33 low-frequency region of Z = rfft2(x, ortho).
// HMMA fp16; data operands hi/lo compensated, fixed operands single fp16.
// Round 11: compact twiddle packing (cols/rows 0..65) -> warp/K-chunk skips
// of exact zeros; K4 fw single fp16 + 3-stage cp.async pipeline.
// ---------------------------------------------------------------------------

#define BB   4
#define CC   512
#define NPOS (64*33)
#define NBQ  8
#define LAMBDA 0.01f
#define TWO_PI 6.28318530717958647692f

// Scratch.  Z/D channel-major: [(b*512+ch)*2112 + pos]
__device__ float g_Zr[(size_t)BB*CC*NPOS];
__device__ float g_Zi[(size_t)BB*CC*NPOS];
__device__ float g_Dr[(size_t)BB*CC*NPOS];
__device__ float g_Di[(size_t)BB*CC*NPOS];
__device__ __half g_u[(size_t)BB*CC*128*128];          // u fp16 [b][c][s]
__device__ __half g_fw[(size_t)CC*CC];                 // fw fp16 [o][c]
// fixed matrices, PRE-SWIZZLED, single fp16 (compact packing, cols/rows 0..65):
//  mat0 = B1 [x][j]: j<33 cos(xj), 33<=j<66 -sin(x(j-33))
//  mat1 = B2^T [c][h]: c<64 cos(ch), c>=64 sin((c-64)h)
//  mat2 = B3^T [h][kk]: kk<64 cos(h kk), kk>=64 -sin(h(kk-64))
//  mat3 = B4 [j][xx]: j<33 cos(j xx), 33<=j<66 -sin((j-33)xx)
__device__ __align__(16) __half g_TW[4][16384];
__device__ __align__(16) __half g_W1[NBQ][16384];      // [[wr,wi],[-wi,wr]]
__device__ __align__(16) __half g_W2[NBQ][16384];
__device__ float g_Bp[NBQ][256];

// ======================= helpers =============================
__device__ __forceinline__ uint32_t smem_u32(const void* p) {
    uint32_t a;
    asm("{ .reg .u64 t; cvta.to.shared.u64 t, %1; cvt.u32.u64 %0, t; }"
        : "=r"(a) : "l"(p));
    return a;
}
#define CP16(dst, src) \
    asm volatile("cp.async.cg.shared.global [%0], [%1], 16;" \
        :: "r"(dst), "l"(src) : "memory")
#define CP_COMMIT() asm volatile("cp.async.commit_group;" ::: "memory")
#define CP_WAIT(n)  asm volatile("cp.async.wait_group %0;" :: "n"(n) : "memory")

#define LDSM4(R, a) \
    asm volatile("ldmatrix.sync.aligned.m8n8.x4.shared.b16 {%0,%1,%2,%3}, [%4];" \
        : "=r"((R)[0]), "=r"((R)[1]), "=r"((R)[2]), "=r"((R)[3]) : "r"(a))
#define LDSM4T(R, a) \
    asm volatile("ldmatrix.sync.aligned.m8n8.x4.trans.shared.b16 {%0,%1,%2,%3}, [%4];" \
        : "=r"((R)[0]), "=r"((R)[1]), "=r"((R)[2]), "=r"((R)[3]) : "r"(a))
#define MMA_F16(C, A, B0, B1) \
    asm volatile("mma.sync.aligned.m16n8k16.row.col.f32.f16.f16.f32 " \
        "{%0,%1,%2,%3},{%4,%5,%6,%7},{%8,%9},{%0,%1,%2,%3};" \
        : "+f"((C)[0]), "+f"((C)[1]), "+f"((C)[2]), "+f"((C)[3]) \
        : "r"((A)[0]), "r"((A)[1]), "r"((A)[2]), "r"((A)[3]), "r"(B0), "r"(B1))

__device__ __forceinline__ uint32_t hp2(float a, float b) {
    __half2 h = __floats2half2_rn(a, b);
    return *(uint32_t*)&h;
}
__device__ __forceinline__ float h_hi(float v) {
    return __half2float(__float2half_rn(v));
}

// smem regions: data hi 32K, data lo 32K, fixed 32K, bias 1K
#define RD_H 0
#define RD_L 32768
#define RT_O 65536
#define BIAS_OFF 98304
#define SMEM_K 99328

__device__ __forceinline__ uint32_t sw_addr(int r, int c) {
    return (uint32_t)(r*256 + ((((c>>3) ^ (r&7)))<<4) + ((c&7)<<1));
}
__device__ __forceinline__ void wrPair(char* smc, int r, int c, float v0, float v1) {
    uint32_t off = sw_addr(r, c);
    float h0 = h_hi(v0), h1 = h_hi(v1);
    *(uint32_t*)(smc + RD_H + off) = hp2(v0, v1);
    *(uint32_t*)(smc + RD_L + off) = hp2(v0 - h0, v1 - h1);
}
__device__ __forceinline__ void wrOne(char* smc, int r, int c, float v) {
    uint32_t off = sw_addr(r, c);
    __half hb = __float2half_rn(v);
    *(__half*)(smc + RD_H + off) = hb;
    *(__half*)(smc + RD_L + off) = __float2half_rn(v - __half2float(hb));
}

// C += A @ B: A = data hi/lo (RD), B = fixed single (RT). kcN K-chunks.
__device__ __forceinline__ void gemm_accA(
    uint32_t sb, float c[2][4][4], int lane, int wm, int wn, int kcN)
{
    const int lrow8 = (lane & 7) + 8*((lane >> 3) & 1);
    const int lsel  = lane >> 4;
    #pragma unroll
    for (int kc = 0; kc < kcN; ++kc) {
        uint32_t ah[2][4], al[2][4], bh[2][4];
        #pragma unroll
        for (int mt = 0; mt < 2; ++mt) {
            int row  = wm*32 + mt*16 + lrow8;
            int unit = kc*2 + lsel;
            uint32_t off = (uint32_t)(row*256 + ((unit ^ (row&7))<<4));
            LDSM4(ah[mt], sb + RD_H + off);
            LDSM4(al[mt], sb + RD_L + off);
        }
        #pragma unroll
        for (int nq = 0; nq < 2; ++nq) {
            int krow = kc*16 + lrow8;
            int unit = wn*4 + nq*2 + lsel;
            uint32_t off = (uint32_t)(krow*256 + ((unit ^ (krow&7))<<4));
            LDSM4T(bh[nq], sb + RT_O + off);
        }
        #pragma unroll
        for (int mt = 0; mt < 2; ++mt)
            #pragma unroll
            for (int nt = 0; nt < 4; ++nt) {
                int nq = nt >> 1, hb = (nt & 1)*2;
                MMA_F16(c[mt][nt], ah[mt], bh[nq][hb], bh[nq][hb+1]);
                MMA_F16(c[mt][nt], al[mt], bh[nq][hb], bh[nq][hb+1]);
            }
    }
}

// C += A @ B: A = fixed single (RT), B = data hi/lo (RD).
__device__ __forceinline__ void gemm_accB(
    uint32_t sb, float c[2][4][4], int lane, int wm, int wn, int kcN)
{
    const int lrow8 = (lane & 7) + 8*((lane >> 3) & 1);
    const int lsel  = lane >> 4;
    #pragma unroll
    for (int kc = 0; kc < kcN; ++kc) {
        uint32_t ah[2][4], bh[2][4], bl[2][4];
        #pragma unroll
        for (int mt = 0; mt < 2; ++mt) {
            int row  = wm*32 + mt*16 + lrow8;
            int unit = kc*2 + lsel;
            uint32_t off = (uint32_t)(row*256 + ((unit ^ (row&7))<<4));
            LDSM4(ah[mt], sb + RT_O + off);
        }
        #pragma unroll
        for (int nq = 0; nq < 2; ++nq) {
            int krow = kc*16 + lrow8;
            int unit = wn*4 + nq*2 + lsel;
            uint32_t off = (uint32_t)(krow*256 + ((unit ^ (krow&7))<<4));
            LDSM4T(bh[nq], sb + RD_H + off);
            LDSM4T(bl[nq], sb + RD_L + off);
        }
        #pragma unroll
        for (int mt = 0; mt < 2; ++mt)
            #pragma unroll
            for (int nt = 0; nt < 4; ++nt) {
                int nq = nt >> 1, hb = (nt & 1)*2;
                MMA_F16(c[mt][nt], ah[mt], bh[nq][hb], bh[nq][hb+1]);
                MMA_F16(c[mt][nt], ah[mt], bl[nq][hb], bl[nq][hb+1]);
            }
    }
}

#define ZERO_C(c) do { \
    _Pragma("unroll") for (int i_ = 0; i_ < 2; ++i_) \
        _Pragma("unroll") for (int j_ = 0; j_ < 4; ++j_) { \
            (c)[i_][j_][0]=0.f; (c)[i_][j_][1]=0.f; \
            (c)[i_][j_][2]=0.f; (c)[i_][j_][3]=0.f; } \
} while (0)

__device__ __forceinline__ void copyT(char* smc, const __half* src, int t) {
    const uint4* s = (const uint4*)src;
    uint4* d = (uint4*)(smc + RT_O);
    for (int i = t; i < 2048; i += 512) d[i] = s[i];
}

// ---------------------------------------------------------------------------
// twiddle init (compact packing)
// ---------------------------------------------------------------------------
__global__ __launch_bounds__(256) void k_twiddle(void)
{
    int idx = blockIdx.x*256 + threadIdx.x;      // 0..65535
    int mat = idx >> 14;
    int r   = (idx >> 7) & 127;
    int cq  = idx & 127;
    float v = 0.0f;
    const float W = TWO_PI / 128.0f;
    if (mat == 0) {              // B1 [x][j]
        if (cq < 33)                  v =  cosf(W*((r*cq) & 127));
        else if (cq < 66)             v = -sinf(W*((r*(cq-33)) & 127));
    } else if (mat == 1) {       // B2^T [c][h]
        if (r < 64) v = cosf(W*((r*cq) & 127));
        else        v = sinf(W*(((r-64)*cq) & 127));
    } else if (mat == 2) {       // B3^T [h][kk]
        if (cq < 64) v =  cosf(W*((r*cq) & 127));
        else         v = -sinf(W*(((cq-64)*r) & 127));
    } else {                     // B4 [j][xx]
        if (r < 33)                 v =  cosf(W*((r*cq) & 127));
        else if (r < 66)            v = -sinf(W*(((r-33)*cq) & 127));
    }
    g_TW[mat][sw_addr(r, cq) >> 1] = __float2half_rn(v);
}

// ---------------------------------------------------------------------------
// pack MLP weights (single fp16, pre-swizzled) + biases
// ---------------------------------------------------------------------------
__global__ __launch_bounds__(256) void k_wpack(
    const float* __restrict__ w1r, const float* __restrict__ w1i,
    const float* __restrict__ w2r, const float* __restrict__ w2i,
    const float* __restrict__ b1r, const float* __restrict__ b1i,
    const float* __restrict__ b2r, const float* __restrict__ b2i)
{
    int idx = blockIdx.x*256 + threadIdx.x;      // 0..262143
    int l   = idx >> 17;
    int rem = idx & 131071;
    int n   = rem >> 14;
    int r   = (rem >> 7) & 127;
    int cq  = rem & 127;
    const float* wr;
    const float* wi;
    if (l == 0) { wr = w1r; wi = w1i; } else { wr = w2r; wi = w2i; }
    float v;
    if (r < 64) v = (cq < 64) ?  wr[n*4096 + r*64 + cq]
                              :  wi[n*4096 + r*64 + (cq-64)];
    else        v = (cq < 64) ? -wi[n*4096 + (r-64)*64 + cq]
                              :  wr[n*4096 + (r-64)*64 + (cq-64)];
    uint32_t ei = sw_addr(r, cq) >> 1;
    if (l == 0) g_W1[n][ei] = __float2half_rn(v);
    else        g_W2[n][ei] = __float2half_rn(v);

    if (idx < NBQ*256) {
        int bn = idx >> 8, j = idx & 255;
        float bv;
        if      (j < 64)  bv = b1r[bn*64 + j];
        else if (j < 128) bv = b1i[bn*64 + j - 64];
        else if (j < 192) bv = b2r[bn*64 + j - 128];
        else              bv = b2i[bn*64 + j - 192];
        g_Bp[bn][j] = bv;
    }
}

// ---------------------------------------------------------------------------
// K1: forward restricted rfft2.  Compact packing => cols 66..127 of both
// stage outputs are exactly zero => wn==3 warps skip both GEMMs.
// ---------------------------------------------------------------------------
__global__ __launch_bounds__(512, 2) void k_fwd_mma(const float* __restrict__ x)
{
    extern __shared__ char smc[];
    const uint32_t sb = smem_u32(smc);
    const int t = threadIdx.x, lane = t & 31, wid = t >> 5;
    const int wm = wid >> 2, wn = wid & 3;
    const int g = lane >> 2, tq = lane & 3;
    const int img = blockIdx.x, bimg = img >> 9, ch = img & 511;
    const float* src = x + (size_t)img * 16384;

    for (int i = t*4; i < 16384; i += 2048) {
        float4 v = *(const float4*)(src + i);
        int r = i >> 7, c0 = i & 127;
        uint32_t off = sw_addr(r, c0);
        float hx = h_hi(v.x), hy = h_hi(v.y), hz = h_hi(v.z), hw = h_hi(v.w);
        uint2 hh = { hp2(v.x, v.y), hp2(v.z, v.w) };
        uint2 ll = { hp2(v.x-hx, v.y-hy), hp2(v.z-hz, v.w-hw) };
        *(uint2*)(smc + RD_H + off) = hh;
        *(uint2*)(smc + RD_L + off) = ll;
    }
    copyT(smc, g_TW[0], t);
    __syncthreads();

    float c[2][4][4];
    ZERO_C(c);
    if (wn != 3) gemm_accA(sb, c, lane, wm, wn, 8);   // mid = X @ B1
    __syncthreads();

    #pragma unroll
    for (int mt = 0; mt < 2; ++mt)
        #pragma unroll
        for (int nt = 0; nt < 4; ++nt) {
            int r0 = wm*32 + mt*16 + g, cb = wn*32 + nt*8 + tq*2;
            wrPair(smc, r0,     cb, c[mt][nt][0], c[mt][nt][1]);
            wrPair(smc, r0 + 8, cb, c[mt][nt][2], c[mt][nt][3]);
        }
    copyT(smc, g_TW[1], t);
    __syncthreads();

    ZERO_C(c);
    if (wn != 3) gemm_accB(sb, c, lane, wm, wn, 8);   // outT = B2^T @ mid
    __syncthreads();

    float* fbuf = (float*)smc;                        // [128][129]
    #pragma unroll
    for (int mt = 0; mt < 2; ++mt)
        #pragma unroll
        for (int nt = 0; nt < 4; ++nt) {
            int r0 = wm*32 + mt*16 + g, cb = wn*32 + nt*8 + tq*2;
            fbuf[r0*129 + cb]       = c[mt][nt][0];
            fbuf[r0*129 + cb + 1]   = c[mt][nt][1];
            fbuf[(r0+8)*129 + cb]   = c[mt][nt][2];
            fbuf[(r0+8)*129 + cb+1] = c[mt][nt][3];
        }
    __syncthreads();

    const size_t base = ((size_t)bimg*512 + ch) * NPOS;
    for (int o = t; o < NPOS; o += 512) {
        int k = o / 33, m = o - k*33;
        float zr = (fbuf[k*129 + m]        + fbuf[(64+k)*129 + 33+m]) * 0.0078125f;
        float zi = (fbuf[k*129 + 33+m]     - fbuf[(64+k)*129 + m])    * 0.0078125f;
        g_Zr[base + o] = zr;
        g_Zi[base + o] = zi;
    }
}

// ---------------------------------------------------------------------------
// K2: block-diagonal complex MLP (unchanged math).
// ---------------------------------------------------------------------------
__global__ __launch_bounds__(512, 2) void k_mlp_mma(void)
{
    extern __shared__ char smc[];
    const uint32_t sb = smem_u32(smc);
    const int t = threadIdx.x, lane = t & 31, wid = t >> 5;
    const int wm = wid >> 2, wn = wid & 3;
    const int g = lane >> 2, tq = lane & 3;
    const int n  = blockIdx.y;
    const int p0 = blockIdx.x * 128;
    float* bias = (float*)(smc + BIAS_OFF);

    {   // load z (channel-major) -> RD hi/lo, coalesced along pos
        int posl = t & 127;
        int cg   = (t >> 7) * 32;
        int P = p0 + posl;
        int b = P / NPOS, pos = P - b*NPOS;
        #pragma unroll
        for (int it = 0; it < 16; ++it) {
            int cc0 = cg + it*2;
            const float* s0 = (cc0 < 64 ? g_Zr : g_Zi)
                + ((size_t)b*512 + n*64 + (cc0 & 63))*NPOS + pos;
            float v0 = s0[0];
            float v1 = s0[NPOS];
            wrPair(smc, posl, cc0, v0, v1);
        }
    }
    copyT(smc, g_W1[n], t);
    if (t < 256) bias[t] = g_Bp[n][t];
    __syncthreads();

    float c[2][4][4];
    ZERO_C(c);
    gemm_accA(sb, c, lane, wm, wn, 8);               // y1 = z @ W1
    __syncthreads();

    #pragma unroll
    for (int mt = 0; mt < 2; ++mt)
        #pragma unroll
        for (int nt = 0; nt < 4; ++nt) {
            int r0 = wm*32 + mt*16 + g, cb = wn*32 + nt*8 + tq*2;
            float b0 = bias[cb], b1v = bias[cb+1];
            #pragma unroll
            for (int hrow = 0; hrow < 2; ++hrow) {
                float v0 = c[mt][nt][hrow*2+0] + b0;
                float v1 = c[mt][nt][hrow*2+1] + b1v;
                v0 = 0.5f * v0 * (1.0f + erff(v0 * 0.70710678118654752f));
                v1 = 0.5f * v1 * (1.0f + erff(v1 * 0.70710678118654752f));
                wrPair(smc, r0 + hrow*8, cb, v0, v1);
            }
        }
    copyT(smc, g_W2[n], t);
    __syncthreads();

    ZERO_C(c);
    gemm_accA(sb, c, lane, wm, wn, 8);               // y2 = h @ W2
    __syncthreads();

    float* fbuf = (float*)smc;
    #pragma unroll
    for (int mt = 0; mt < 2; ++mt)
        #pragma unroll
        for (int nt = 0; nt < 4; ++nt) {
            int r0 = wm*32 + mt*16 + g, cb = wn*32 + nt*8 + tq*2;
            float b0 = bias[128 + cb], b1v = bias[128 + cb + 1];
            #pragma unroll
            for (int hrow = 0; hrow < 2; ++hrow) {
                float v0 = c[mt][nt][hrow*2+0] + b0;
                float v1 = c[mt][nt][hrow*2+1] + b1v;
                float s0 = fabsf(v0) - LAMBDA; v0 = (s0 > 0.f) ? copysignf(s0, v0) : 0.f;
                float s1 = fabsf(v1) - LAMBDA; v1 = (s1 > 0.f) ? copysignf(s1, v1) : 0.f;
                fbuf[(r0 + hrow*8)*129 + cb]     = v0;
                fbuf[(r0 + hrow*8)*129 + cb + 1] = v1;
            }
        }
    __syncthreads();

    {   // D = y - z, coalesced along pos
        int posl = t & 127;
        int cg   = (t >> 7) * 32;
        int P = p0 + posl;
        int b = P / NPOS, pos = P - b*NPOS;
        #pragma unroll
        for (int it = 0; it < 32; ++it) {
            int cc = cg + it;
            size_t gi = ((size_t)b*512 + n*64 + (cc & 63))*NPOS + pos;
            const float* gZ = (cc < 64) ? g_Zr : g_Zi;
            float* gD = (cc < 64) ? g_Dr : g_Di;
            gD[gi] = fbuf[posl*129 + cc] - gZ[gi];
        }
    }
}

// ---------------------------------------------------------------------------
// K3: u = x + irfft2_ortho(D) -> single fp16 u.
// Compact dpack rows (0..65) => stage1 wn==3 skip; stage2 K-chunks 0..4 only.
// ---------------------------------------------------------------------------
__global__ __launch_bounds__(512, 2) void k_inv_mma(const float* __restrict__ x)
{
    extern __shared__ char smc[];
    const uint32_t sb = smem_u32(smc);
    const int t = threadIdx.x, lane = t & 31, wid = t >> 5;
    const int wm = wid >> 2, wn = wid & 3;
    const int g = lane >> 2, tq = lane & 3;
    const int img = blockIdx.x, bimg = img >> 9, ch = img & 511;

    {   // zero RD (hi+lo = 64KB)
        uint4 z = {0,0,0,0};
        uint4* pd = (uint4*)(smc + RD_H);
        for (int i = t; i < 4096; i += 512) pd[i] = z;
    }
    copyT(smc, g_TW[2], t);
    __syncthreads();

    // gather D -> dpack^T in RD: rows kk = k|64+k, cols = m | 33+m
    const size_t base = ((size_t)bimg*512 + ch) * NPOS;
    for (int o = t; o < NPOS; o += 512) {
        int k = o / 33, m = o - k*33;
        float a = g_Dr[base + o], b = g_Di[base + o];
        if (m == 0) { a *= 0.5f; b *= 0.5f; }
        wrOne(smc, k,      m,      a);
        wrOne(smc, k,      33 + m, b);
        wrOne(smc, 64 + k, m,      b);
        wrOne(smc, 64 + k, 33 + m, -a);
    }
    __syncthreads();

    float c[2][4][4];
    ZERO_C(c);
    if (wn != 3) gemm_accB(sb, c, lane, wm, wn, 8);   // G^T = B3^T @ dpack^T
    __syncthreads();

    #pragma unroll
    for (int mt = 0; mt < 2; ++mt)
        #pragma unroll
        for (int nt = 0; nt < 4; ++nt) {
            int r0 = wm*32 + mt*16 + g, cb = wn*32 + nt*8 + tq*2;
            wrPair(smc, r0,     cb, c[mt][nt][0], c[mt][nt][1]);
            wrPair(smc, r0 + 8, cb, c[mt][nt][2], c[mt][nt][3]);
        }
    copyT(smc, g_TW[3], t);
    __syncthreads();

    ZERO_C(c);
    gemm_accA(sb, c, lane, wm, wn, 5);                // u = G^T @ B4 (K<=80)

    const float* xim = x + (size_t)img * 16384;
    __half* up = g_u + (size_t)img * 16384;
    #pragma unroll
    for (int mt = 0; mt < 2; ++mt)
        #pragma unroll
        for (int nt = 0; nt < 4; ++nt) {
            int r0 = wm*32 + mt*16 + g, cb = wn*32 + nt*8 + tq*2;
            #pragma unroll
            for (int hrow = 0; hrow < 2; ++hrow) {
                int r = r0 + hrow*8;
                float v0 = c[mt][nt][hrow*2 + 0];
                float v1 = c[mt][nt][hrow*2 + 1];
                int o = r*128 + cb;
                float2 xv = *(const float2*)(xim + o);
                float a = fmaf(v0, 0.015625f, xv.x);
                float b = fmaf(v1, 0.015625f, xv.y);
                *(uint32_t*)(up + o) = hp2(a, b);
            }
        }
}

// ---------------------------------------------------------------------------
// K_fc: fw fp32 -> single fp16
// ---------------------------------------------------------------------------
__global__ __launch_bounds__(1024) void k_fwconv(const float* __restrict__ fw)
{
    int i = blockIdx.x * 1024 + threadIdx.x;
    g_fw[i] = __float2half_rn(fw[i]);
}

// ---------------------------------------------------------------------------
// K4: HMMA fp16 GEMM: A = fw single, B = u single.  out = x + fw @ u.
// CTA 128x128, 8 warps, K-chunk 32, cp.async 3 stages.
// ---------------------------------------------------------------------------
#define STG_B 16384
#define OFF_A 0
#define OFF_B 8192

__global__ __launch_bounds__(256, 2) void k_gemm_mma(
    const float* __restrict__ x, float* __restrict__ out)
{
    extern __shared__ char smc[];
    const uint32_t sb = smem_u32(smc);
    const int t    = threadIdx.x;
    const int lane = t & 31;
    const int wid  = t >> 5;
    const int wm   = wid >> 1;
    const int wn   = wid & 1;
    const int m0   = blockIdx.x * 128;
    const int n0g  = blockIdx.y * 128;
    const int bimg = n0g >> 14;
    const int s0   = n0g & 16383;

    const char* pA = (const char*)g_fw;
    const char* pB = (const char*)g_u;

    int ar0 = (t + 0)   >> 2, au0 = (t + 0)   & 3;
    int ar1 = (t + 256) >> 2, au1 = (t + 256) & 3;
    uint32_t adst0 = (uint32_t)(ar0*64 + ((au0 ^ ((ar0>>1)&3)) << 4));
    uint32_t adst1 = (uint32_t)(ar1*64 + ((au1 ^ ((ar1>>1)&3)) << 4));
    int br0 = (t + 0)   >> 4, bu0 = (t + 0)   & 15;
    int br1 = (t + 256) >> 4, bu1 = (t + 256) & 15;
    uint32_t bdst0 = (uint32_t)(br0*256 + ((bu0 ^ (br0&7)) << 4));
    uint32_t bdst1 = (uint32_t)(br1*256 + ((bu1 ^ (br1&7)) << 4));

    float c[2][8][4];
    #pragma unroll
    for (int i = 0; i < 2; ++i)
        #pragma unroll
        for (int j = 0; j < 8; ++j) {
            c[i][j][0] = 0.f; c[i][j][1] = 0.f; c[i][j][2] = 0.f; c[i][j][3] = 0.f;
        }

    const int lrow8 = (lane & 7) + 8*((lane >> 3) & 1);
    const int lsel  = lane >> 4;

    #define ISSUE_STAGE(kc, buf) do { \
        uint32_t st_ = sb + (buf)*STG_B; \
        { size_t so = ((size_t)(m0 + ar0)*512 + (kc)*32 + au0*8)*2; \
          CP16(st_ + OFF_A + adst0, pA + so); } \
        { size_t so = ((size_t)(m0 + ar1)*512 + (kc)*32 + au1*8)*2; \
          CP16(st_ + OFF_A + adst1, pA + so); } \
        { size_t so = ((size_t)(bimg*512 + (kc)*32 + br0)*16384 + s0 + bu0*8)*2; \
          CP16(st_ + OFF_B + bdst0, pB + so); } \
        { size_t so = ((size_t)(bimg*512 + (kc)*32 + br1)*16384 + s0 + bu1*8)*2; \
          CP16(st_ + OFF_B + bdst1, pB + so); } \
        CP_COMMIT(); \
    } while (0)

    ISSUE_STAGE(0, 0);
    ISSUE_STAGE(1, 1);
    ISSUE_STAGE(2, 2);

    for (int kc = 0; kc < 16; ++kc) {
        const int buf = kc % 3;
        if (kc < 14)      { CP_WAIT(2); }
        else if (kc == 14){ CP_WAIT(1); }
        else              { CP_WAIT(0); }
        __syncthreads();

        const uint32_t st = sb + buf*STG_B;
        #pragma unroll
        for (int ks = 0; ks < 2; ++ks) {
            uint32_t ah[2][4], bh[4][4];
            #pragma unroll
            for (int mt = 0; mt < 2; ++mt) {
                int row  = wm*32 + mt*16 + lrow8;
                int unit = ks*2 + lsel;
                uint32_t off = (uint32_t)(row*64 + ((unit ^ ((row>>1)&3)) << 4));
                LDSM4(ah[mt], st + OFF_A + off);
            }
            #pragma unroll
            for (int nq = 0; nq < 4; ++nq) {
                int krow = ks*16 + lrow8;
                int unit = wn*8 + nq*2 + lsel;
                uint32_t off = (uint32_t)(krow*256 + ((unit ^ (krow&7)) << 4));
                LDSM4T(bh[nq], st + OFF_B + off);
            }
            #pragma unroll
            for (int mt = 0; mt < 2; ++mt)
                #pragma unroll
                for (int nt = 0; nt < 8; ++nt) {
                    const int nq = nt >> 1, hb = (nt & 1) * 2;
                    MMA_F16(c[mt][nt], ah[mt], bh[nq][hb], bh[nq][hb+1]);
                }
        }
        __syncthreads();
        if (kc + 3 < 16) ISSUE_STAGE(kc + 3, (kc + 3) % 3);
    }

    const int g  = lane >> 2;
    const int tq = lane & 3;
    const size_t obase = (size_t)(bimg * 512);
    #pragma unroll
    for (int mt = 0; mt < 2; ++mt)
        #pragma unroll
        for (int nt = 0; nt < 8; ++nt) {
            int row0 = m0 + wm*32 + mt*16 + g;
            int col  = s0 + wn*64 + nt*8 + tq*2;
            size_t go = (obase + row0)*16384 + col;
            float2 xv = *(const float2*)(x + go);
            float2 ov = { c[mt][nt][0] + xv.x, c[mt][nt][1] + xv.y };
            *(float2*)(out + go) = ov;
            go += (size_t)8 * 16384;
            xv = *(const float2*)(x + go);
            float2 ov2 = { c[mt][nt][2] + xv.x, c[mt][nt][3] + xv.y };
            *(float2*)(out + go) = ov2;
        }
}

// ---------------------------------------------------------------------------
#define SMEM_GMM (3 * STG_B)

extern "C" void kernel_launch(void* const* d_in, const int* in_sizes, int n_in,
                              void* d_out, int out_size)
{
    const float* x   = (const float*)d_in[0];
    const float* w1r = (const float*)d_in[1];
    const float* w1i = (const float*)d_in[2];
    const float* b1r = (const float*)d_in[3];
    const float* b1i = (const float*)d_in[4];
    const float* w2r = (const float*)d_in[5];
    const float* w2i = (const float*)d_in[6];
    const float* b2r = (const float*)d_in[7];
    const float* b2i = (const float*)d_in[8];
    const float* fw  = (const float*)d_in[9];
    float* out = (float*)d_out;

    cudaFuncSetAttribute(k_fwd_mma, cudaFuncAttributeMaxDynamicSharedMemorySize, SMEM_K);
    cudaFuncSetAttribute(k_inv_mma, cudaFuncAttributeMaxDynamicSharedMemorySize, SMEM_K);
    cudaFuncSetAttribute(k_mlp_mma, cudaFuncAttributeMaxDynamicSharedMemorySize, SMEM_K);
    cudaFuncSetAttribute(k_gemm_mma,cudaFuncAttributeMaxDynamicSharedMemorySize, SMEM_GMM);

    k_twiddle<<<256, 256>>>();
    k_wpack<<<1024, 256>>>(w1r, w1i, w2r, w2i, b1r, b1i, b2r, b2i);
    k_fwconv<<<256, 1024>>>(fw);

    k_fwd_mma<<<BB*CC, 512, SMEM_K>>>(x);

    dim3 g2((BB*NPOS)/128, NBQ);
    k_mlp_mma<<<g2, 512, SMEM_K>>>();

    k_inv_mma<<<BB*CC, 512, SMEM_K>>>(x);

    dim3 gg(4, BB*16384/128);
    k_gemm_mma<<<gg, 256, SMEM_GMM>>>(x, out);
}

// round 13
// speedup vs baseline: 11.6170x; 1.2029x over previous
#include <cuda_runtime.h>
#include <cuda_fp16.h>
#include <math.h>
#include <stdint.h>

// ---------------------------------------------------------------------------
// AFNO2D: out = x + fuse_w @ (x + irfft2(D)),   D = masked_MLP(Z) - Z on the
// 64x33 low-frequency region of Z = rfft2(x, ortho).
// HMMA fp16, single-precision-fp16 data AND fixed operands in the frequency
// path (error budget validated r12); K4 single fp16 both sides.
// DFT/MLP kernels: 66KB smem, 2 CTAs/SM, cp.async'd fixed-matrix loads.
// ---------------------------------------------------------------------------

#define BB   4
#define CC   512
#define NPOS (64*33)
#define NBQ  8
#define LAMBDA 0.01f
#define TWO_PI 6.28318530717958647692f

// Scratch.  Z/D channel-major: [(b*512+ch)*2112 + pos]
__device__ float g_Zr[(size_t)BB*CC*NPOS];
__device__ float g_Zi[(size_t)BB*CC*NPOS];
__device__ float g_Dr[(size_t)BB*CC*NPOS];
__device__ float g_Di[(size_t)BB*CC*NPOS];
__device__ __half g_u[(size_t)BB*CC*128*128];          // u fp16 [b][c][s]
__device__ __half g_fw[(size_t)CC*CC];                 // fw fp16 [o][c]
// fixed matrices, PRE-SWIZZLED, single fp16 (compact packing, cols/rows 0..65):
//  mat0 = B1 [x][j]: j<33 cos(xj), 33<=j<66 -sin(x(j-33))
//  mat1 = B2^T [c][h]: c<64 cos(ch), c>=64 sin((c-64)h)
//  mat2 = B3^T [h][kk]: kk<64 cos(h kk), kk>=64 -sin(h(kk-64))
//  mat3 = B4 [j][xx]: j<33 cos(j xx), 33<=j<66 -sin((j-33)xx)
__device__ __align__(16) __half g_TW[4][16384];
__device__ __align__(16) __half g_W1[NBQ][16384];      // [[wr,wi],[-wi,wr]]
__device__ __align__(16) __half g_W2[NBQ][16384];
__device__ float g_Bp[NBQ][256];

// ======================= helpers =============================
__device__ __forceinline__ uint32_t smem_u32(const void* p) {
    uint32_t a;
    asm("{ .reg .u64 t; cvta.to.shared.u64 t, %1; cvt.u32.u64 %0, t; }"
        : "=r"(a) : "l"(p));
    return a;
}
#define CP16(dst, src) \
    asm volatile("cp.async.cg.shared.global [%0], [%1], 16;" \
        :: "r"(dst), "l"(src) : "memory")
#define CP_COMMIT() asm volatile("cp.async.commit_group;" ::: "memory")
#define CP_WAIT(n)  asm volatile("cp.async.wait_group %0;" :: "n"(n) : "memory")

#define LDSM4(R, a) \
    asm volatile("ldmatrix.sync.aligned.m8n8.x4.shared.b16 {%0,%1,%2,%3}, [%4];" \
        : "=r"((R)[0]), "=r"((R)[1]), "=r"((R)[2]), "=r"((R)[3]) : "r"(a))
#define LDSM4T(R, a) \
    asm volatile("ldmatrix.sync.aligned.m8n8.x4.trans.shared.b16 {%0,%1,%2,%3}, [%4];" \
        : "=r"((R)[0]), "=r"((R)[1]), "=r"((R)[2]), "=r"((R)[3]) : "r"(a))
#define MMA_F16(C, A, B0, B1) \
    asm volatile("mma.sync.aligned.m16n8k16.row.col.f32.f16.f16.f32 " \
        "{%0,%1,%2,%3},{%4,%5,%6,%7},{%8,%9},{%0,%1,%2,%3};" \
        : "+f"((C)[0]), "+f"((C)[1]), "+f"((C)[2]), "+f"((C)[3]) \
        : "r"((A)[0]), "r"((A)[1]), "r"((A)[2]), "r"((A)[3]), "r"(B0), "r"(B1))

__device__ __forceinline__ uint32_t hp2(float a, float b) {
    __half2 h = __floats2half2_rn(a, b);
    return *(uint32_t*)&h;
}

// smem: data single 32K @0, fixed single 32K @32768; fp32 staging buffer
// (128x129 floats = 66048B) overlays both; bias at 66560 (1KB), clear of fbuf.
#define RD_O 0
#define RT_O 32768
#define BIAS_OFF 66560
#define SMEM_K 67584

__device__ __forceinline__ uint32_t sw_addr(int r, int c) {
    return (uint32_t)(r*256 + ((((c>>3) ^ (r&7)))<<4) + ((c&7)<<1));
}
__device__ __forceinline__ void wr2(char* smc, int r, int c, float v0, float v1) {
    *(uint32_t*)(smc + RD_O + sw_addr(r, c)) = hp2(v0, v1);
}
__device__ __forceinline__ void wr1(char* smc, int r, int c, float v) {
    *(__half*)(smc + RD_O + sw_addr(r, c)) = __float2half_rn(v);
}

// C += A @ B: A = data (RD), B = fixed (RT). kcN K-chunks of 16.
__device__ __forceinline__ void gemm_ssA(
    uint32_t sb, float c[2][4][4], int lane, int wm, int wn, int kcN)
{
    const int lrow8 = (lane & 7) + 8*((lane >> 3) & 1);
    const int lsel  = lane >> 4;
    #pragma unroll
    for (int kc = 0; kc < kcN; ++kc) {
        uint32_t ah[2][4], bh[2][4];
        #pragma unroll
        for (int mt = 0; mt < 2; ++mt) {
            int row  = wm*32 + mt*16 + lrow8;
            int unit = kc*2 + lsel;
            uint32_t off = (uint32_t)(row*256 + ((unit ^ (row&7))<<4));
            LDSM4(ah[mt], sb + RD_O + off);
        }
        #pragma unroll
        for (int nq = 0; nq < 2; ++nq) {
            int krow = kc*16 + lrow8;
            int unit = wn*4 + nq*2 + lsel;
            uint32_t off = (uint32_t)(krow*256 + ((unit ^ (krow&7))<<4));
            LDSM4T(bh[nq], sb + RT_O + off);
        }
        #pragma unroll
        for (int mt = 0; mt < 2; ++mt)
            #pragma unroll
            for (int nt = 0; nt < 4; ++nt) {
                int nq = nt >> 1, hb = (nt & 1)*2;
                MMA_F16(c[mt][nt], ah[mt], bh[nq][hb], bh[nq][hb+1]);
            }
    }
}

// C += A @ B: A = fixed (RT), B = data (RD).
__device__ __forceinline__ void gemm_ssB(
    uint32_t sb, float c[2][4][4], int lane, int wm, int wn, int kcN)
{
    const int lrow8 = (lane & 7) + 8*((lane >> 3) & 1);
    const int lsel  = lane >> 4;
    #pragma unroll
    for (int kc = 0; kc < kcN; ++kc) {
        uint32_t ah[2][4], bh[2][4];
        #pragma unroll
        for (int mt = 0; mt < 2; ++mt) {
            int row  = wm*32 + mt*16 + lrow8;
            int unit = kc*2 + lsel;
            uint32_t off = (uint32_t)(row*256 + ((unit ^ (row&7))<<4));
            LDSM4(ah[mt], sb + RT_O + off);
        }
        #pragma unroll
        for (int nq = 0; nq < 2; ++nq) {
            int krow = kc*16 + lrow8;
            int unit = wn*4 + nq*2 + lsel;
            uint32_t off = (uint32_t)(krow*256 + ((unit ^ (krow&7))<<4));
            LDSM4T(bh[nq], sb + RD_O + off);
        }
        #pragma unroll
        for (int mt = 0; mt < 2; ++mt)
            #pragma unroll
            for (int nt = 0; nt < 4; ++nt) {
                int nq = nt >> 1, hb = (nt & 1)*2;
                MMA_F16(c[mt][nt], ah[mt], bh[nq][hb], bh[nq][hb+1]);
            }
    }
}

#define ZERO_C(c) do { \
    _Pragma("unroll") for (int i_ = 0; i_ < 2; ++i_) \
        _Pragma("unroll") for (int j_ = 0; j_ < 4; ++j_) { \
            (c)[i_][j_][0]=0.f; (c)[i_][j_][1]=0.f; \
            (c)[i_][j_][2]=0.f; (c)[i_][j_][3]=0.f; } \
} while (0)

// async copy of one 32KB fixed matrix into RT (caller: CP_WAIT(0)+sync later)
__device__ __forceinline__ void cpT(uint32_t sb, const __half* src, int t) {
    const char* s = (const char*)src;
    for (int i = t; i < 2048; i += 512)
        CP16(sb + RT_O + i*16, s + i*16);
    CP_COMMIT();
}

// ---------------------------------------------------------------------------
// k_prep: fused prologue — twiddles + MLP weight pack + biases + fw convert
// ---------------------------------------------------------------------------
__global__ __launch_bounds__(256) void k_prep(
    const float* __restrict__ w1r, const float* __restrict__ w1i,
    const float* __restrict__ w2r, const float* __restrict__ w2i,
    const float* __restrict__ b1r, const float* __restrict__ b1i,
    const float* __restrict__ b2r, const float* __restrict__ b2i,
    const float* __restrict__ fw)
{
    int idx = blockIdx.x*256 + threadIdx.x;      // 0..262143

    // --- twiddles (idx < 65536) ---
    if (idx < 65536) {
        int mat = idx >> 14;
        int r   = (idx >> 7) & 127;
        int cq  = idx & 127;
        float v = 0.0f;
        const float W = TWO_PI / 128.0f;
        if (mat == 0) {
            if (cq < 33)       v =  cosf(W*((r*cq) & 127));
            else if (cq < 66)  v = -sinf(W*((r*(cq-33)) & 127));
        } else if (mat == 1) {
            if (r < 64) v = cosf(W*((r*cq) & 127));
            else        v = sinf(W*(((r-64)*cq) & 127));
        } else if (mat == 2) {
            if (cq < 64) v =  cosf(W*((r*cq) & 127));
            else         v = -sinf(W*(((cq-64)*r) & 127));
        } else {
            if (r < 33)       v =  cosf(W*((r*cq) & 127));
            else if (r < 66)  v = -sinf(W*(((r-33)*cq) & 127));
        }
        g_TW[mat][sw_addr(r, cq) >> 1] = __float2half_rn(v);
    }

    // --- MLP weight pack (all idx; two layers folded by half-range) ---
    {
        int l   = idx >> 17;
        int rem = idx & 131071;
        int n   = rem >> 14;
        int r   = (rem >> 7) & 127;
        int cq  = rem & 127;
        const float* wr;
        const float* wi;
        if (l == 0) { wr = w1r; wi = w1i; } else { wr = w2r; wi = w2i; }
        float v;
        if (r < 64) v = (cq < 64) ?  wr[n*4096 + r*64 + cq]
                                  :  wi[n*4096 + r*64 + (cq-64)];
        else        v = (cq < 64) ? -wi[n*4096 + (r-64)*64 + cq]
                                  :  wr[n*4096 + (r-64)*64 + (cq-64)];
        uint32_t ei = sw_addr(r, cq) >> 1;
        if (l == 0) g_W1[n][ei] = __float2half_rn(v);
        else        g_W2[n][ei] = __float2half_rn(v);
    }

    // --- biases (idx < 2048) ---
    if (idx < NBQ*256) {
        int bn = idx >> 8, j = idx & 255;
        float bv;
        if      (j < 64)  bv = b1r[bn*64 + j];
        else if (j < 128) bv = b1i[bn*64 + j - 64];
        else if (j < 192) bv = b2r[bn*64 + j - 128];
        else              bv = b2i[bn*64 + j - 192];
        g_Bp[bn][j] = bv;
    }

    // --- fw convert (all idx) ---
    g_fw[idx] = __float2half_rn(fw[idx]);
}

// ---------------------------------------------------------------------------
// K1: forward restricted rfft2.  Cols 66..127 of both stage outputs exactly
// zero => wn==3 warps skip both GEMMs.
// ---------------------------------------------------------------------------
__global__ __launch_bounds__(512, 2) void k_fwd_mma(const float* __restrict__ x)
{
    extern __shared__ char smc[];
    const uint32_t sb = smem_u32(smc);
    const int t = threadIdx.x, lane = t & 31, wid = t >> 5;
    const int wm = wid >> 2, wn = wid & 3;
    const int g = lane >> 2, tq = lane & 3;
    const int img = blockIdx.x, bimg = img >> 9, ch = img & 511;
    const float* src = x + (size_t)img * 16384;

    cpT(sb, g_TW[0], t);                          // B1 -> RT (async)
    for (int i = t*4; i < 16384; i += 2048) {
        float4 v = *(const float4*)(src + i);
        int r = i >> 7, c0 = i & 127;
        uint32_t off = sw_addr(r, c0);
        uint2 hh = { hp2(v.x, v.y), hp2(v.z, v.w) };
        *(uint2*)(smc + RD_O + off) = hh;
    }
    CP_WAIT(0);
    __syncthreads();

    float c[2][4][4];
    ZERO_C(c);
    if (wn != 3) gemm_ssA(sb, c, lane, wm, wn, 8);   // mid = X @ B1
    __syncthreads();

    #pragma unroll
    for (int mt = 0; mt < 2; ++mt)
        #pragma unroll
        for (int nt = 0; nt < 4; ++nt) {
            int r0 = wm*32 + mt*16 + g, cb = wn*32 + nt*8 + tq*2;
            wr2(smc, r0,     cb, c[mt][nt][0], c[mt][nt][1]);
            wr2(smc, r0 + 8, cb, c[mt][nt][2], c[mt][nt][3]);
        }
    cpT(sb, g_TW[1], t);                          // B2^T -> RT (async)
    CP_WAIT(0);
    __syncthreads();

    ZERO_C(c);
    if (wn != 3) gemm_ssB(sb, c, lane, wm, wn, 8);   // outT = B2^T @ mid
    __syncthreads();

    float* fbuf = (float*)smc;                        // [128][129]
    #pragma unroll
    for (int mt = 0; mt < 2; ++mt)
        #pragma unroll
        for (int nt = 0; nt < 4; ++nt) {
            int r0 = wm*32 + mt*16 + g, cb = wn*32 + nt*8 + tq*2;
            fbuf[r0*129 + cb]       = c[mt][nt][0];
            fbuf[r0*129 + cb + 1]   = c[mt][nt][1];
            fbuf[(r0+8)*129 + cb]   = c[mt][nt][2];
            fbuf[(r0+8)*129 + cb+1] = c[mt][nt][3];
        }
    __syncthreads();

    const size_t base = ((size_t)bimg*512 + ch) * NPOS;
    for (int o = t; o < NPOS; o += 512) {
        int k = o / 33, m = o - k*33;
        float zr = (fbuf[k*129 + m]      + fbuf[(64+k)*129 + 33+m]) * 0.0078125f;
        float zi = (fbuf[k*129 + 33+m]   - fbuf[(64+k)*129 + m])    * 0.0078125f;
        g_Zr[base + o] = zr;
        g_Zi[base + o] = zi;
    }
}

// ---------------------------------------------------------------------------
// K2: block-diagonal complex MLP.
// ---------------------------------------------------------------------------
__global__ __launch_bounds__(512, 2) void k_mlp_mma(void)
{
    extern __shared__ char smc[];
    const uint32_t sb = smem_u32(smc);
    const int t = threadIdx.x, lane = t & 31, wid = t >> 5;
    const int wm = wid >> 2, wn = wid & 3;
    const int g = lane >> 2, tq = lane & 3;
    const int n  = blockIdx.y;
    const int p0 = blockIdx.x * 128;
    float* bias = (float*)(smc + BIAS_OFF);

    cpT(sb, g_W1[n], t);                          // W1 -> RT (async)
    {   // load z (channel-major) -> RD, coalesced along pos
        int posl = t & 127;
        int cg   = (t >> 7) * 32;
        int P = p0 + posl;
        int b = P / NPOS, pos = P - b*NPOS;
        #pragma unroll
        for (int it = 0; it < 16; ++it) {
            int cc0 = cg + it*2;
            const float* s0 = (cc0 < 64 ? g_Zr : g_Zi)
                + ((size_t)b*512 + n*64 + (cc0 & 63))*NPOS + pos;
            float v0 = s0[0];
            float v1 = s0[NPOS];
            wr2(smc, posl, cc0, v0, v1);
        }
    }
    if (t < 256) bias[t] = g_Bp[n][t];
    CP_WAIT(0);
    __syncthreads();

    float c[2][4][4];
    ZERO_C(c);
    gemm_ssA(sb, c, lane, wm, wn, 8);               // y1 = z @ W1
    __syncthreads();

    #pragma unroll
    for (int mt = 0; mt < 2; ++mt)
        #pragma unroll
        for (int nt = 0; nt < 4; ++nt) {
            int r0 = wm*32 + mt*16 + g, cb = wn*32 + nt*8 + tq*2;
            float b0 = bias[cb], b1v = bias[cb+1];
            #pragma unroll
            for (int hrow = 0; hrow < 2; ++hrow) {
                float v0 = c[mt][nt][hrow*2+0] + b0;
                float v1 = c[mt][nt][hrow*2+1] + b1v;
                v0 = 0.5f * v0 * (1.0f + erff(v0 * 0.70710678118654752f));
                v1 = 0.5f * v1 * (1.0f + erff(v1 * 0.70710678118654752f));
                wr2(smc, r0 + hrow*8, cb, v0, v1);
            }
        }
    cpT(sb, g_W2[n], t);                          // W2 -> RT (async)
    CP_WAIT(0);
    __syncthreads();

    ZERO_C(c);
    gemm_ssA(sb, c, lane, wm, wn, 8);               // y2 = h @ W2
    __syncthreads();

    float* fbuf = (float*)smc;
    #pragma unroll
    for (int mt = 0; mt < 2; ++mt)
        #pragma unroll
        for (int nt = 0; nt < 4; ++nt) {
            int r0 = wm*32 + mt*16 + g, cb = wn*32 + nt*8 + tq*2;
            float b0 = bias[128 + cb], b1v = bias[128 + cb + 1];
            #pragma unroll
            for (int hrow = 0; hrow < 2; ++hrow) {
                float v0 = c[mt][nt][hrow*2+0] + b0;
                float v1 = c[mt][nt][hrow*2+1] + b1v;
                float s0 = fabsf(v0) - LAMBDA; v0 = (s0 > 0.f) ? copysignf(s0, v0) : 0.f;
                float s1 = fabsf(v1) - LAMBDA; v1 = (s1 > 0.f) ? copysignf(s1, v1) : 0.f;
                fbuf[(r0 + hrow*8)*129 + cb]     = v0;
                fbuf[(r0 + hrow*8)*129 + cb + 1] = v1;
            }
        }
    __syncthreads();

    {   // D = y - z, coalesced along pos
        int posl = t & 127;
        int cg   = (t >> 7) * 32;
        int P = p0 + posl;
        int b = P / NPOS, pos = P - b*NPOS;
        #pragma unroll
        for (int it = 0; it < 32; ++it) {
            int cc = cg + it;
            size_t gi = ((size_t)b*512 + n*64 + (cc & 63))*NPOS + pos;
            const float* gZ = (cc < 64) ? g_Zr : g_Zi;
            float* gD = (cc < 64) ? g_Dr : g_Di;
            gD[gi] = fbuf[posl*129 + cc] - gZ[gi];
        }
    }
}

// ---------------------------------------------------------------------------
// K3: u = x + irfft2_ortho(D) -> single fp16 u.
// Compact dpack (rows/cols 0..65) => stage1 wn==3 skip; stage2 K-chunks 0..4.
// ---------------------------------------------------------------------------
__global__ __launch_bounds__(512, 2) void k_inv_mma(const float* __restrict__ x)
{
    extern __shared__ char smc[];
    const uint32_t sb = smem_u32(smc);
    const int t = threadIdx.x, lane = t & 31, wid = t >> 5;
    const int wm = wid >> 2, wn = wid & 3;
    const int g = lane >> 2, tq = lane & 3;
    const int img = blockIdx.x, bimg = img >> 9, ch = img & 511;

    cpT(sb, g_TW[2], t);                          // B3^T -> RT (async)
    {   // zero RD (32KB)
        uint4 z = {0,0,0,0};
        uint4* pd = (uint4*)(smc + RD_O);
        for (int i = t; i < 2048; i += 512) pd[i] = z;
    }
    __syncthreads();

    // gather D -> dpack^T in RD: rows kk = k|64+k, cols = m | 33+m
    const size_t base = ((size_t)bimg*512 + ch) * NPOS;
    for (int o = t; o < NPOS; o += 512) {
        int k = o / 33, m = o - k*33;
        float a = g_Dr[base + o], b = g_Di[base + o];
        if (m == 0) { a *= 0.5f; b *= 0.5f; }
        wr1(smc, k,      m,      a);
        wr1(smc, k,      33 + m, b);
        wr1(smc, 64 + k, m,      b);
        wr1(smc, 64 + k, 33 + m, -a);
    }
    CP_WAIT(0);
    __syncthreads();

    float c[2][4][4];
    ZERO_C(c);
    if (wn != 3) gemm_ssB(sb, c, lane, wm, wn, 8);   // G^T = B3^T @ dpack^T
    __syncthreads();

    #pragma unroll
    for (int mt = 0; mt < 2; ++mt)
        #pragma unroll
        for (int nt = 0; nt < 4; ++nt) {
            int r0 = wm*32 + mt*16 + g, cb = wn*32 + nt*8 + tq*2;
            wr2(smc, r0,     cb, c[mt][nt][0], c[mt][nt][1]);
            wr2(smc, r0 + 8, cb, c[mt][nt][2], c[mt][nt][3]);
        }
    cpT(sb, g_TW[3], t);                          // B4 -> RT (async)
    CP_WAIT(0);
    __syncthreads();

    ZERO_C(c);
    gemm_ssA(sb, c, lane, wm, wn, 5);                // u = G^T @ B4 (K<=80)

    const float* xim = x + (size_t)img * 16384;
    __half* up = g_u + (size_t)img * 16384;
    #pragma unroll
    for (int mt = 0; mt < 2; ++mt)
        #pragma unroll
        for (int nt = 0; nt < 4; ++nt) {
            int r0 = wm*32 + mt*16 + g, cb = wn*32 + nt*8 + tq*2;
            #pragma unroll
            for (int hrow = 0; hrow < 2; ++hrow) {
                int r = r0 + hrow*8;
                float v0 = c[mt][nt][hrow*2 + 0];
                float v1 = c[mt][nt][hrow*2 + 1];
                int o = r*128 + cb;
                float2 xv = *(const float2*)(xim + o);
                float a = fmaf(v0, 0.015625f, xv.x);
                float b = fmaf(v1, 0.015625f, xv.y);
                *(uint32_t*)(up + o) = hp2(a, b);
            }
        }
}

// ---------------------------------------------------------------------------
// K4: HMMA fp16 GEMM: A = fw single, B = u single.  out = x + fw @ u.
// CTA 128x128, 8 warps, K-chunk 32, cp.async 3 stages.
// ---------------------------------------------------------------------------
#define STG_B 16384
#define OFF_A 0
#define OFF_B 8192

__global__ __launch_bounds__(256, 2) void k_gemm_mma(
    const float* __restrict__ x, float* __restrict__ out)
{
    extern __shared__ char smc[];
    const uint32_t sb = smem_u32(smc);
    const int t    = threadIdx.x;
    const int lane = t & 31;
    const int wid  = t >> 5;
    const int wm   = wid >> 1;
    const int wn   = wid & 1;
    const int m0   = blockIdx.x * 128;
    const int n0g  = blockIdx.y * 128;
    const int bimg = n0g >> 14;
    const int s0   = n0g & 16383;

    const char* pA = (const char*)g_fw;
    const char* pB = (const char*)g_u;

    int ar0 = (t + 0)   >> 2, au0 = (t + 0)   & 3;
    int ar1 = (t + 256) >> 2, au1 = (t + 256) & 3;
    uint32_t adst0 = (uint32_t)(ar0*64 + ((au0 ^ ((ar0>>1)&3)) << 4));
    uint32_t adst1 = (uint32_t)(ar1*64 + ((au1 ^ ((ar1>>1)&3)) << 4));
    int br0 = (t + 0)   >> 4, bu0 = (t + 0)   & 15;
    int br1 = (t + 256) >> 4, bu1 = (t + 256) & 15;
    uint32_t bdst0 = (uint32_t)(br0*256 + ((bu0 ^ (br0&7)) << 4));
    uint32_t bdst1 = (uint32_t)(br1*256 + ((bu1 ^ (br1&7)) << 4));

    float c[2][8][4];
    #pragma unroll
    for (int i = 0; i < 2; ++i)
        #pragma unroll
        for (int j = 0; j < 8; ++j) {
            c[i][j][0] = 0.f; c[i][j][1] = 0.f; c[i][j][2] = 0.f; c[i][j][3] = 0.f;
        }

    const int lrow8 = (lane & 7) + 8*((lane >> 3) & 1);
    const int lsel  = lane >> 4;

    #define ISSUE_STAGE(kc, buf) do { \
        uint32_t st_ = sb + (buf)*STG_B; \
        { size_t so = ((size_t)(m0 + ar0)*512 + (kc)*32 + au0*8)*2; \
          CP16(st_ + OFF_A + adst0, pA + so); } \
        { size_t so = ((size_t)(m0 + ar1)*512 + (kc)*32 + au1*8)*2; \
          CP16(st_ + OFF_A + adst1, pA + so); } \
        { size_t so = ((size_t)(bimg*512 + (kc)*32 + br0)*16384 + s0 + bu0*8)*2; \
          CP16(st_ + OFF_B + bdst0, pB + so); } \
        { size_t so = ((size_t)(bimg*512 + (kc)*32 + br1)*16384 + s0 + bu1*8)*2; \
          CP16(st_ + OFF_B + bdst1, pB + so); } \
        CP_COMMIT(); \
    } while (0)

    ISSUE_STAGE(0, 0);
    ISSUE_STAGE(1, 1);
    ISSUE_STAGE(2, 2);

    for (int kc = 0; kc < 16; ++kc) {
        const int buf = kc % 3;
        if (kc < 14)      { CP_WAIT(2); }
        else if (kc == 14){ CP_WAIT(1); }
        else              { CP_WAIT(0); }
        __syncthreads();

        const uint32_t st = sb + buf*STG_B;
        #pragma unroll
        for (int ks = 0; ks < 2; ++ks) {
            uint32_t ah[2][4], bh[4][4];
            #pragma unroll
            for (int mt = 0; mt < 2; ++mt) {
                int row  = wm*32 + mt*16 + lrow8;
                int unit = ks*2 + lsel;
                uint32_t off = (uint32_t)(row*64 + ((unit ^ ((row>>1)&3)) << 4));
                LDSM4(ah[mt], st + OFF_A + off);
            }
            #pragma unroll
            for (int nq = 0; nq < 4; ++nq) {
                int krow = ks*16 + lrow8;
                int unit = wn*8 + nq*2 + lsel;
                uint32_t off = (uint32_t)(krow*256 + ((unit ^ (krow&7)) << 4));
                LDSM4T(bh[nq], st + OFF_B + off);
            }
            #pragma unroll
            for (int mt = 0; mt < 2; ++mt)
                #pragma unroll
                for (int nt = 0; nt < 8; ++nt) {
                    const int nq = nt >> 1, hb = (nt & 1) * 2;
                    MMA_F16(c[mt][nt], ah[mt], bh[nq][hb], bh[nq][hb+1]);
                }
        }
        __syncthreads();
        if (kc + 3 < 16) ISSUE_STAGE(kc + 3, (kc + 3) % 3);
    }

    const int g  = lane >> 2;
    const int tq = lane & 3;
    const size_t obase = (size_t)(bimg * 512);
    #pragma unroll
    for (int mt = 0; mt < 2; ++mt)
        #pragma unroll
        for (int nt = 0; nt < 8; ++nt) {
            int row0 = m0 + wm*32 + mt*16 + g;
            int col  = s0 + wn*64 + nt*8 + tq*2;
            size_t go = (obase + row0)*16384 + col;
            float2 xv = *(const float2*)(x + go);
            float2 ov = { c[mt][nt][0] + xv.x, c[mt][nt][1] + xv.y };
            *(float2*)(out + go) = ov;
            go += (size_t)8 * 16384;
            xv = *(const float2*)(x + go);
            float2 ov2 = { c[mt][nt][2] + xv.x, c[mt][nt][3] + xv.y };
            *(float2*)(out + go) = ov2;
        }
}

// ---------------------------------------------------------------------------
#define SMEM_GMM (3 * STG_B)

extern "C" void kernel_launch(void* const* d_in, const int* in_sizes, int n_in,
                              void* d_out, int out_size)
{
    const float* x   = (const float*)d_in[0];
    const float* w1r = (const float*)d_in[1];
    const float* w1i = (const float*)d_in[2];
    const float* b1r = (const float*)d_in[3];
    const float* b1i = (const float*)d_in[4];
    const float* w2r = (const float*)d_in[5];
    const float* w2i = (const float*)d_in[6];
    const float* b2r = (const float*)d_in[7];
    const float* b2i = (const float*)d_in[8];
    const float* fw  = (const float*)d_in[9];
    float* out = (float*)d_out;

    cudaFuncSetAttribute(k_fwd_mma, cudaFuncAttributeMaxDynamicSharedMemorySize, SMEM_K);
    cudaFuncSetAttribute(k_inv_mma, cudaFuncAttributeMaxDynamicSharedMemorySize, SMEM_K);
    cudaFuncSetAttribute(k_mlp_mma, cudaFuncAttributeMaxDynamicSharedMemorySize, SMEM_K);
    cudaFuncSetAttribute(k_gemm_mma,cudaFuncAttributeMaxDynamicSharedMemorySize, SMEM_GMM);

    k_prep<<<1024, 256>>>(w1r, w1i, w2r, w2i, b1r, b1i, b2r, b2i, fw);

    k_fwd_mma<<<BB*CC, 512, SMEM_K>>>(x);

    dim3 g2((BB*NPOS)/128, NBQ);
    k_mlp_mma<<<g2, 512, SMEM_K>>>();

    k_inv_mma<<<BB*CC, 512, SMEM_K>>>(x);

    dim3 gg(4, BB*16384/128);
    k_gemm_mma<<<gg, 256, SMEM_GMM>>>(x, out);
}

// round 14
// speedup vs baseline: 11.9983x; 1.0328x over previous
#include <cuda_runtime.h>
#include <cuda_fp16.h>
#include <math.h>
#include <stdint.h>

// ---------------------------------------------------------------------------
// AFNO2D: out = x + fuse_w @ (x + irfft2(D)),   D = masked_MLP(Z) - Z on the
// 64x33 low-frequency region of Z = rfft2(x, ortho).
// HMMA fp16 single-precision everywhere in the frequency path (error model
// validated r12/r13).  Z and D stored as packed half2 (r,i), channel-major.
// DFT/MLP kernels: 66KB smem, 2 CTAs/SM, cp.async'd fixed-matrix loads.
// ---------------------------------------------------------------------------

#define BB   4
#define CC   512
#define NPOS (64*33)
#define NBQ  8
#define LAMBDA 0.01f
#define TWO_PI 6.28318530717958647692f

// Scratch.  Z/D channel-major packed: g_Z[(b*512+ch)*2112 + pos] = (zr, zi)
__device__ __half2 g_Z[(size_t)BB*CC*NPOS];
__device__ __half2 g_D[(size_t)BB*CC*NPOS];
__device__ __half g_u[(size_t)BB*CC*128*128];          // u fp16 [b][c][s]
__device__ __half g_fw[(size_t)CC*CC];                 // fw fp16 [o][c]
// fixed matrices, PRE-SWIZZLED, single fp16 (compact packing, cols/rows 0..65):
//  mat0 = B1 [x][j]: j<33 cos(xj), 33<=j<66 -sin(x(j-33))
//  mat1 = B2^T [c][h]: c<64 cos(ch), c>=64 sin((c-64)h)
//  mat2 = B3^T [h][kk]: kk<64 cos(h kk), kk>=64 -sin(h(kk-64))
//  mat3 = B4 [j][xx]: j<33 cos(j xx), 33<=j<66 -sin((j-33)xx)
__device__ __align__(16) __half g_TW[4][16384];
__device__ __align__(16) __half g_W1[NBQ][16384];      // [[wr,wi],[-wi,wr]]
__device__ __align__(16) __half g_W2[NBQ][16384];
__device__ float g_Bp[NBQ][256];

// ======================= helpers =============================
__device__ __forceinline__ uint32_t smem_u32(const void* p) {
    uint32_t a;
    asm("{ .reg .u64 t; cvta.to.shared.u64 t, %1; cvt.u32.u64 %0, t; }"
        : "=r"(a) : "l"(p));
    return a;
}
#define CP16(dst, src) \
    asm volatile("cp.async.cg.shared.global [%0], [%1], 16;" \
        :: "r"(dst), "l"(src) : "memory")
#define CP_COMMIT() asm volatile("cp.async.commit_group;" ::: "memory")
#define CP_WAIT(n)  asm volatile("cp.async.wait_group %0;" :: "n"(n) : "memory")

#define LDSM4(R, a) \
    asm volatile("ldmatrix.sync.aligned.m8n8.x4.shared.b16 {%0,%1,%2,%3}, [%4];" \
        : "=r"((R)[0]), "=r"((R)[1]), "=r"((R)[2]), "=r"((R)[3]) : "r"(a))
#define LDSM4T(R, a) \
    asm volatile("ldmatrix.sync.aligned.m8n8.x4.trans.shared.b16 {%0,%1,%2,%3}, [%4];" \
        : "=r"((R)[0]), "=r"((R)[1]), "=r"((R)[2]), "=r"((R)[3]) : "r"(a))
#define MMA_F16(C, A, B0, B1) \
    asm volatile("mma.sync.aligned.m16n8k16.row.col.f32.f16.f16.f32 " \
        "{%0,%1,%2,%3},{%4,%5,%6,%7},{%8,%9},{%0,%1,%2,%3};" \
        : "+f"((C)[0]), "+f"((C)[1]), "+f"((C)[2]), "+f"((C)[3]) \
        : "r"((A)[0]), "r"((A)[1]), "r"((A)[2]), "r"((A)[3]), "r"(B0), "r"(B1))

__device__ __forceinline__ uint32_t hp2(float a, float b) {
    __half2 h = __floats2half2_rn(a, b);
    return *(uint32_t*)&h;
}

// smem: data single 32K @0, fixed single 32K @32768; fp32 staging buffer
// (128x129 floats = 66048B) overlays both; bias at 66560 (1KB).
#define RD_O 0
#define RT_O 32768
#define BIAS_OFF 66560
#define SMEM_K 67584

__device__ __forceinline__ uint32_t sw_addr(int r, int c) {
    return (uint32_t)(r*256 + ((((c>>3) ^ (r&7)))<<4) + ((c&7)<<1));
}
__device__ __forceinline__ void wr2(char* smc, int r, int c, float v0, float v1) {
    *(uint32_t*)(smc + RD_O + sw_addr(r, c)) = hp2(v0, v1);
}
__device__ __forceinline__ void wr1(char* smc, int r, int c, float v) {
    *(__half*)(smc + RD_O + sw_addr(r, c)) = __float2half_rn(v);
}

// C += A @ B: A = data (RD), B = fixed (RT). kcN K-chunks of 16.
__device__ __forceinline__ void gemm_ssA(
    uint32_t sb, float c[2][4][4], int lane, int wm, int wn, int kcN)
{
    const int lrow8 = (lane & 7) + 8*((lane >> 3) & 1);
    const int lsel  = lane >> 4;
    #pragma unroll
    for (int kc = 0; kc < kcN; ++kc) {
        uint32_t ah[2][4], bh[2][4];
        #pragma unroll
        for (int mt = 0; mt < 2; ++mt) {
            int row  = wm*32 + mt*16 + lrow8;
            int unit = kc*2 + lsel;
            uint32_t off = (uint32_t)(row*256 + ((unit ^ (row&7))<<4));
            LDSM4(ah[mt], sb + RD_O + off);
        }
        #pragma unroll
        for (int nq = 0; nq < 2; ++nq) {
            int krow = kc*16 + lrow8;
            int unit = wn*4 + nq*2 + lsel;
            uint32_t off = (uint32_t)(krow*256 + ((unit ^ (krow&7))<<4));
            LDSM4T(bh[nq], sb + RT_O + off);
        }
        #pragma unroll
        for (int mt = 0; mt < 2; ++mt)
            #pragma unroll
            for (int nt = 0; nt < 4; ++nt) {
                int nq = nt >> 1, hb = (nt & 1)*2;
                MMA_F16(c[mt][nt], ah[mt], bh[nq][hb], bh[nq][hb+1]);
            }
    }
}

// C += A @ B: A = fixed (RT), B = data (RD).
__device__ __forceinline__ void gemm_ssB(
    uint32_t sb, float c[2][4][4], int lane, int wm, int wn, int kcN)
{
    const int lrow8 = (lane & 7) + 8*((lane >> 3) & 1);
    const int lsel  = lane >> 4;
    #pragma unroll
    for (int kc = 0; kc < kcN; ++kc) {
        uint32_t ah[2][4], bh[2][4];
        #pragma unroll
        for (int mt = 0; mt < 2; ++mt) {
            int row  = wm*32 + mt*16 + lrow8;
            int unit = kc*2 + lsel;
            uint32_t off = (uint32_t)(row*256 + ((unit ^ (row&7))<<4));
            LDSM4(ah[mt], sb + RT_O + off);
        }
        #pragma unroll
        for (int nq = 0; nq < 2; ++nq) {
            int krow = kc*16 + lrow8;
            int unit = wn*4 + nq*2 + lsel;
            uint32_t off = (uint32_t)(krow*256 + ((unit ^ (krow&7))<<4));
            LDSM4T(bh[nq], sb + RD_O + off);
        }
        #pragma unroll
        for (int mt = 0; mt < 2; ++mt)
            #pragma unroll
            for (int nt = 0; nt < 4; ++nt) {
                int nq = nt >> 1, hb = (nt & 1)*2;
                MMA_F16(c[mt][nt], ah[mt], bh[nq][hb], bh[nq][hb+1]);
            }
    }
}

#define ZERO_C(c) do { \
    _Pragma("unroll") for (int i_ = 0; i_ < 2; ++i_) \
        _Pragma("unroll") for (int j_ = 0; j_ < 4; ++j_) { \
            (c)[i_][j_][0]=0.f; (c)[i_][j_][1]=0.f; \
            (c)[i_][j_][2]=0.f; (c)[i_][j_][3]=0.f; } \
} while (0)

// async copy of one 32KB fixed matrix into RT
__device__ __forceinline__ void cpT(uint32_t sb, const __half* src, int t) {
    const char* s = (const char*)src;
    for (int i = t; i < 2048; i += 512)
        CP16(sb + RT_O + i*16, s + i*16);
    CP_COMMIT();
}

// ---------------------------------------------------------------------------
// k_prep: fused prologue — twiddles + MLP weight pack + biases + fw convert
// ---------------------------------------------------------------------------
__global__ __launch_bounds__(256) void k_prep(
    const float* __restrict__ w1r, const float* __restrict__ w1i,
    const float* __restrict__ w2r, const float* __restrict__ w2i,
    const float* __restrict__ b1r, const float* __restrict__ b1i,
    const float* __restrict__ b2r, const float* __restrict__ b2i,
    const float* __restrict__ fw)
{
    int idx = blockIdx.x*256 + threadIdx.x;      // 0..262143

    if (idx < 65536) {
        int mat = idx >> 14;
        int r   = (idx >> 7) & 127;
        int cq  = idx & 127;
        float v = 0.0f;
        const float W = TWO_PI / 128.0f;
        if (mat == 0) {
            if (cq < 33)       v =  cosf(W*((r*cq) & 127));
            else if (cq < 66)  v = -sinf(W*((r*(cq-33)) & 127));
        } else if (mat == 1) {
            if (r < 64) v = cosf(W*((r*cq) & 127));
            else        v = sinf(W*(((r-64)*cq) & 127));
        } else if (mat == 2) {
            if (cq < 64) v =  cosf(W*((r*cq) & 127));
            else         v = -sinf(W*(((cq-64)*r) & 127));
        } else {
            if (r < 33)       v =  cosf(W*((r*cq) & 127));
            else if (r < 66)  v = -sinf(W*(((r-33)*cq) & 127));
        }
        g_TW[mat][sw_addr(r, cq) >> 1] = __float2half_rn(v);
    }

    {
        int l   = idx >> 17;
        int rem = idx & 131071;
        int n   = rem >> 14;
        int r   = (rem >> 7) & 127;
        int cq  = rem & 127;
        const float* wr;
        const float* wi;
        if (l == 0) { wr = w1r; wi = w1i; } else { wr = w2r; wi = w2i; }
        float v;
        if (r < 64) v = (cq < 64) ?  wr[n*4096 + r*64 + cq]
                                  :  wi[n*4096 + r*64 + (cq-64)];
        else        v = (cq < 64) ? -wi[n*4096 + (r-64)*64 + cq]
                                  :  wr[n*4096 + (r-64)*64 + (cq-64)];
        uint32_t ei = sw_addr(r, cq) >> 1;
        if (l == 0) g_W1[n][ei] = __float2half_rn(v);
        else        g_W2[n][ei] = __float2half_rn(v);
    }

    if (idx < NBQ*256) {
        int bn = idx >> 8, j = idx & 255;
        float bv;
        if      (j < 64)  bv = b1r[bn*64 + j];
        else if (j < 128) bv = b1i[bn*64 + j - 64];
        else if (j < 192) bv = b2r[bn*64 + j - 128];
        else              bv = b2i[bn*64 + j - 192];
        g_Bp[bn][j] = bv;
    }

    g_fw[idx] = __float2half_rn(fw[idx]);
}

// ---------------------------------------------------------------------------
// K1: forward restricted rfft2.  Cols 66..127 of both stage outputs exactly
// zero => wn==3 warps skip both GEMMs.  Z written as packed half2.
// ---------------------------------------------------------------------------
__global__ __launch_bounds__(512, 2) void k_fwd_mma(const float* __restrict__ x)
{
    extern __shared__ char smc[];
    const uint32_t sb = smem_u32(smc);
    const int t = threadIdx.x, lane = t & 31, wid = t >> 5;
    const int wm = wid >> 2, wn = wid & 3;
    const int g = lane >> 2, tq = lane & 3;
    const int img = blockIdx.x, bimg = img >> 9, ch = img & 511;
    const float* src = x + (size_t)img * 16384;

    cpT(sb, g_TW[0], t);                          // B1 -> RT (async)
    for (int i = t*4; i < 16384; i += 2048) {
        float4 v = *(const float4*)(src + i);
        int r = i >> 7, c0 = i & 127;
        uint32_t off = sw_addr(r, c0);
        uint2 hh = { hp2(v.x, v.y), hp2(v.z, v.w) };
        *(uint2*)(smc + RD_O + off) = hh;
    }
    CP_WAIT(0);
    __syncthreads();

    float c[2][4][4];
    ZERO_C(c);
    if (wn != 3) gemm_ssA(sb, c, lane, wm, wn, 8);   // mid = X @ B1
    __syncthreads();

    #pragma unroll
    for (int mt = 0; mt < 2; ++mt)
        #pragma unroll
        for (int nt = 0; nt < 4; ++nt) {
            int r0 = wm*32 + mt*16 + g, cb = wn*32 + nt*8 + tq*2;
            wr2(smc, r0,     cb, c[mt][nt][0], c[mt][nt][1]);
            wr2(smc, r0 + 8, cb, c[mt][nt][2], c[mt][nt][3]);
        }
    cpT(sb, g_TW[1], t);                          // B2^T -> RT (async)
    CP_WAIT(0);
    __syncthreads();

    ZERO_C(c);
    if (wn != 3) gemm_ssB(sb, c, lane, wm, wn, 8);   // outT = B2^T @ mid
    __syncthreads();

    float* fbuf = (float*)smc;                        // [128][129]
    #pragma unroll
    for (int mt = 0; mt < 2; ++mt)
        #pragma unroll
        for (int nt = 0; nt < 4; ++nt) {
            int r0 = wm*32 + mt*16 + g, cb = wn*32 + nt*8 + tq*2;
            fbuf[r0*129 + cb]       = c[mt][nt][0];
            fbuf[r0*129 + cb + 1]   = c[mt][nt][1];
            fbuf[(r0+8)*129 + cb]   = c[mt][nt][2];
            fbuf[(r0+8)*129 + cb+1] = c[mt][nt][3];
        }
    __syncthreads();

    const size_t base = ((size_t)bimg*512 + ch) * NPOS;
    for (int o = t; o < NPOS; o += 512) {
        int k = o / 33, m = o - k*33;
        float zr = (fbuf[k*129 + m]      + fbuf[(64+k)*129 + 33+m]) * 0.0078125f;
        float zi = (fbuf[k*129 + 33+m]   - fbuf[(64+k)*129 + m])    * 0.0078125f;
        g_Z[base + o] = __floats2half2_rn(zr, zi);
    }
}

// ---------------------------------------------------------------------------
// K2: block-diagonal complex MLP.  Z/D packed half2.
// ---------------------------------------------------------------------------
__global__ __launch_bounds__(512, 2) void k_mlp_mma(void)
{
    extern __shared__ char smc[];
    const uint32_t sb = smem_u32(smc);
    const int t = threadIdx.x, lane = t & 31, wid = t >> 5;
    const int wm = wid >> 2, wn = wid & 3;
    const int g = lane >> 2, tq = lane & 3;
    const int n  = blockIdx.y;
    const int p0 = blockIdx.x * 128;
    float* bias = (float*)(smc + BIAS_OFF);

    const int posl = t & 127;
    const int gq   = t >> 7;          // 0..3, each handles 16 channels
    const int Pg   = p0 + posl;
    const int bg   = Pg / NPOS, posg = Pg - bg*NPOS;

    cpT(sb, g_W1[n], t);                          // W1 -> RT (async)
    {   // load z packed -> RD [pos][ zr cols 0..63 | zi cols 64..127 ]
        const __half2* zb = g_Z + ((size_t)bg*512 + n*64 + gq*16)*NPOS + posg;
        #pragma unroll
        for (int it = 0; it < 8; ++it) {
            __half2 a  = zb[(size_t)(2*it)*NPOS];
            __half2 bq = zb[(size_t)(2*it+1)*NPOS];
            __half2 lo = __lows2half2(a, bq);     // (zr0, zr1)
            __half2 hi = __highs2half2(a, bq);    // (zi0, zi1)
            int cc = gq*16 + 2*it;
            *(uint32_t*)(smc + RD_O + sw_addr(posl, cc))      = *(uint32_t*)&lo;
            *(uint32_t*)(smc + RD_O + sw_addr(posl, 64 + cc)) = *(uint32_t*)&hi;
        }
    }
    if (t < 256) bias[t] = g_Bp[n][t];
    CP_WAIT(0);
    __syncthreads();

    float c[2][4][4];
    ZERO_C(c);
    gemm_ssA(sb, c, lane, wm, wn, 8);               // y1 = z @ W1
    __syncthreads();

    #pragma unroll
    for (int mt = 0; mt < 2; ++mt)
        #pragma unroll
        for (int nt = 0; nt < 4; ++nt) {
            int r0 = wm*32 + mt*16 + g, cb = wn*32 + nt*8 + tq*2;
            float b0 = bias[cb], b1v = bias[cb+1];
            #pragma unroll
            for (int hrow = 0; hrow < 2; ++hrow) {
                float v0 = c[mt][nt][hrow*2+0] + b0;
                float v1 = c[mt][nt][hrow*2+1] + b1v;
                v0 = 0.5f * v0 * (1.0f + erff(v0 * 0.70710678118654752f));
                v1 = 0.5f * v1 * (1.0f + erff(v1 * 0.70710678118654752f));
                wr2(smc, r0 + hrow*8, cb, v0, v1);
            }
        }
    cpT(sb, g_W2[n], t);                          // W2 -> RT (async)
    CP_WAIT(0);
    __syncthreads();

    float cc2[2][4][4];
    ZERO_C(cc2);
    gemm_ssA(sb, cc2, lane, wm, wn, 8);             // y2 = h @ W2
    __syncthreads();

    float* fbuf = (float*)smc;
    #pragma unroll
    for (int mt = 0; mt < 2; ++mt)
        #pragma unroll
        for (int nt = 0; nt < 4; ++nt) {
            int r0 = wm*32 + mt*16 + g, cb = wn*32 + nt*8 + tq*2;
            float b0 = bias[128 + cb], b1v = bias[128 + cb + 1];
            #pragma unroll
            for (int hrow = 0; hrow < 2; ++hrow) {
                float v0 = cc2[mt][nt][hrow*2+0] + b0;
                float v1 = cc2[mt][nt][hrow*2+1] + b1v;
                float s0 = fabsf(v0) - LAMBDA; v0 = (s0 > 0.f) ? copysignf(s0, v0) : 0.f;
                float s1 = fabsf(v1) - LAMBDA; v1 = (s1 > 0.f) ? copysignf(s1, v1) : 0.f;
                fbuf[(r0 + hrow*8)*129 + cb]     = v0;
                fbuf[(r0 + hrow*8)*129 + cb + 1] = v1;
            }
        }
    __syncthreads();

    {   // D = y - z (packed), coalesced along pos
        const size_t zoff = ((size_t)bg*512 + n*64 + gq*16)*NPOS + posg;
        #pragma unroll
        for (int it = 0; it < 16; ++it) {
            int cc = gq*16 + it;
            float yr = fbuf[posl*129 + cc];
            float yi = fbuf[posl*129 + 64 + cc];
            float2 zf = __half22float2(g_Z[zoff + (size_t)it*NPOS]);
            g_D[zoff + (size_t)it*NPOS] = __floats2half2_rn(yr - zf.x, yi - zf.y);
        }
    }
}

// ---------------------------------------------------------------------------
// K3: u = x + irfft2_ortho(D) -> single fp16 u.  D packed half2.
// Compact dpack (rows/cols 0..65) => stage1 wn==3 skip; stage2 K-chunks 0..4.
// ---------------------------------------------------------------------------
__global__ __launch_bounds__(512, 2) void k_inv_mma(const float* __restrict__ x)
{
    extern __shared__ char smc[];
    const uint32_t sb = smem_u32(smc);
    const int t = threadIdx.x, lane = t & 31, wid = t >> 5;
    const int wm = wid >> 2, wn = wid & 3;
    const int g = lane >> 2, tq = lane & 3;
    const int img = blockIdx.x, bimg = img >> 9, ch = img & 511;

    cpT(sb, g_TW[2], t);                          // B3^T -> RT (async)
    {   // zero RD (32KB)
        uint4 z = {0,0,0,0};
        uint4* pd = (uint4*)(smc + RD_O);
        for (int i = t; i < 2048; i += 512) pd[i] = z;
    }
    __syncthreads();

    // gather D -> dpack^T in RD: rows kk = k|64+k, cols = m | 33+m
    const size_t base = ((size_t)bimg*512 + ch) * NPOS;
    for (int o = t; o < NPOS; o += 512) {
        int k = o / 33, m = o - k*33;
        float2 df = __half22float2(g_D[base + o]);
        float a = df.x, b = df.y;
        if (m == 0) { a *= 0.5f; b *= 0.5f; }
        wr1(smc, k,      m,      a);
        wr1(smc, k,      33 + m, b);
        wr1(smc, 64 + k, m,      b);
        wr1(smc, 64 + k, 33 + m, -a);
    }
    CP_WAIT(0);
    __syncthreads();

    float c[2][4][4];
    ZERO_C(c);
    if (wn != 3) gemm_ssB(sb, c, lane, wm, wn, 8);   // G^T = B3^T @ dpack^T
    __syncthreads();

    #pragma unroll
    for (int mt = 0; mt < 2; ++mt)
        #pragma unroll
        for (int nt = 0; nt < 4; ++nt) {
            int r0 = wm*32 + mt*16 + g, cb = wn*32 + nt*8 + tq*2;
            wr2(smc, r0,     cb, c[mt][nt][0], c[mt][nt][1]);
            wr2(smc, r0 + 8, cb, c[mt][nt][2], c[mt][nt][3]);
        }
    cpT(sb, g_TW[3], t);                          // B4 -> RT (async)
    CP_WAIT(0);
    __syncthreads();

    ZERO_C(c);
    gemm_ssA(sb, c, lane, wm, wn, 5);                // u = G^T @ B4 (K<=80)

    const float* xim = x + (size_t)img * 16384;
    __half* up = g_u + (size_t)img * 16384;
    #pragma unroll
    for (int mt = 0; mt < 2; ++mt)
        #pragma unroll
        for (int nt = 0; nt < 4; ++nt) {
            int r0 = wm*32 + mt*16 + g, cb = wn*32 + nt*8 + tq*2;
            #pragma unroll
            for (int hrow = 0; hrow < 2; ++hrow) {
                int r = r0 + hrow*8;
                float v0 = c[mt][nt][hrow*2 + 0];
                float v1 = c[mt][nt][hrow*2 + 1];
                int o = r*128 + cb;
                float2 xv = *(const float2*)(xim + o);
                float a = fmaf(v0, 0.015625f, xv.x);
                float b = fmaf(v1, 0.015625f, xv.y);
                *(uint32_t*)(up + o) = hp2(a, b);
            }
        }
}

// ---------------------------------------------------------------------------
// K4: HMMA fp16 GEMM: A = fw single, B = u single.  out = x + fw @ u.
// CTA 128x128, 8 warps, K-chunk 32, cp.async 3 stages.
// ---------------------------------------------------------------------------
#define STG_B 16384
#define OFF_A 0
#define OFF_B 8192

__global__ __launch_bounds__(256, 2) void k_gemm_mma(
    const float* __restrict__ x, float* __restrict__ out)
{
    extern __shared__ char smc[];
    const uint32_t sb = smem_u32(smc);
    const int t    = threadIdx.x;
    const int lane = t & 31;
    const int wid  = t >> 5;
    const int wm   = wid >> 1;
    const int wn   = wid & 1;
    const int m0   = blockIdx.x * 128;
    const int n0g  = blockIdx.y * 128;
    const int bimg = n0g >> 14;
    const int s0   = n0g & 16383;

    const char* pA = (const char*)g_fw;
    const char* pB = (const char*)g_u;

    int ar0 = (t + 0)   >> 2, au0 = (t + 0)   & 3;
    int ar1 = (t + 256) >> 2, au1 = (t + 256) & 3;
    uint32_t adst0 = (uint32_t)(ar0*64 + ((au0 ^ ((ar0>>1)&3)) << 4));
    uint32_t adst1 = (uint32_t)(ar1*64 + ((au1 ^ ((ar1>>1)&3)) << 4));
    int br0 = (t + 0)   >> 4, bu0 = (t + 0)   & 15;
    int br1 = (t + 256) >> 4, bu1 = (t + 256) & 15;
    uint32_t bdst0 = (uint32_t)(br0*256 + ((bu0 ^ (br0&7)) << 4));
    uint32_t bdst1 = (uint32_t)(br1*256 + ((bu1 ^ (br1&7)) << 4));

    float c[2][8][4];
    #pragma unroll
    for (int i = 0; i < 2; ++i)
        #pragma unroll
        for (int j = 0; j < 8; ++j) {
            c[i][j][0] = 0.f; c[i][j][1] = 0.f; c[i][j][2] = 0.f; c[i][j][3] = 0.f;
        }

    const int lrow8 = (lane & 7) + 8*((lane >> 3) & 1);
    const int lsel  = lane >> 4;

    #define ISSUE_STAGE(kc, buf) do { \
        uint32_t st_ = sb + (buf)*STG_B; \
        { size_t so = ((size_t)(m0 + ar0)*512 + (kc)*32 + au0*8)*2; \
          CP16(st_ + OFF_A + adst0, pA + so); } \
        { size_t so = ((size_t)(m0 + ar1)*512 + (kc)*32 + au1*8)*2; \
          CP16(st_ + OFF_A + adst1, pA + so); } \
        { size_t so = ((size_t)(bimg*512 + (kc)*32 + br0)*16384 + s0 + bu0*8)*2; \
          CP16(st_ + OFF_B + bdst0, pB + so); } \
        { size_t so = ((size_t)(bimg*512 + (kc)*32 + br1)*16384 + s0 + bu1*8)*2; \
          CP16(st_ + OFF_B + bdst1, pB + so); } \
        CP_COMMIT(); \
    } while (0)

    ISSUE_STAGE(0, 0);
    ISSUE_STAGE(1, 1);
    ISSUE_STAGE(2, 2);

    for (int kc = 0; kc < 16; ++kc) {
        const int buf = kc % 3;
        if (kc < 14)      { CP_WAIT(2); }
        else if (kc == 14){ CP_WAIT(1); }
        else              { CP_WAIT(0); }
        __syncthreads();

        const uint32_t st = sb + buf*STG_B;
        #pragma unroll
        for (int ks = 0; ks < 2; ++ks) {
            uint32_t ah[2][4], bh[4][4];
            #pragma unroll
            for (int mt = 0; mt < 2; ++mt) {
                int row  = wm*32 + mt*16 + lrow8;
                int unit = ks*2 + lsel;
                uint32_t off = (uint32_t)(row*64 + ((unit ^ ((row>>1)&3)) << 4));
                LDSM4(ah[mt], st + OFF_A + off);
            }
            #pragma unroll
            for (int nq = 0; nq < 4; ++nq) {
                int krow = ks*16 + lrow8;
                int unit = wn*8 + nq*2 + lsel;
                uint32_t off = (uint32_t)(krow*256 + ((unit ^ (krow&7)) << 4));
                LDSM4T(bh[nq], st + OFF_B + off);
            }
            #pragma unroll
            for (int mt = 0; mt < 2; ++mt)
                #pragma unroll
                for (int nt = 0; nt < 8; ++nt) {
                    const int nq = nt >> 1, hb = (nt & 1) * 2;
                    MMA_F16(c[mt][nt], ah[mt], bh[nq][hb], bh[nq][hb+1]);
                }
        }
        __syncthreads();
        if (kc + 3 < 16) ISSUE_STAGE(kc + 3, (kc + 3) % 3);
    }

    const int g  = lane >> 2;
    const int tq = lane & 3;
    const size_t obase = (size_t)(bimg * 512);
    #pragma unroll
    for (int mt = 0; mt < 2; ++mt)
        #pragma unroll
        for (int nt = 0; nt < 8; ++nt) {
            int row0 = m0 + wm*32 + mt*16 + g;
            int col  = s0 + wn*64 + nt*8 + tq*2;
            size_t go = (obase + row0)*16384 + col;
            float2 xv = *(const float2*)(x + go);
            float2 ov = { c[mt][nt][0] + xv.x, c[mt][nt][1] + xv.y };
            *(float2*)(out + go) = ov;
            go += (size_t)8 * 16384;
            xv = *(const float2*)(x + go);
            float2 ov2 = { c[mt][nt][2] + xv.x, c[mt][nt][3] + xv.y };
            *(float2*)(out + go) = ov2;
        }
}

// ---------------------------------------------------------------------------
#define SMEM_GMM (3 * STG_B)

extern "C" void kernel_launch(void* const* d_in, const int* in_sizes, int n_in,
                              void* d_out, int out_size)
{
    const float* x   = (const float*)d_in[0];
    const float* w1r = (const float*)d_in[1];
    const float* w1i = (const float*)d_in[2];
    const float* b1r = (const float*)d_in[3];
    const float* b1i = (const float*)d_in[4];
    const float* w2r = (const float*)d_in[5];
    const float* w2i = (const float*)d_in[6];
    const float* b2r = (const float*)d_in[7];
    const float* b2i = (const float*)d_in[8];
    const float* fw  = (const float*)d_in[9];
    float* out = (float*)d_out;

    cudaFuncSetAttribute(k_fwd_mma, cudaFuncAttributeMaxDynamicSharedMemorySize, SMEM_K);
    cudaFuncSetAttribute(k_inv_mma, cudaFuncAttributeMaxDynamicSharedMemorySize, SMEM_K);
    cudaFuncSetAttribute(k_mlp_mma, cudaFuncAttributeMaxDynamicSharedMemorySize, SMEM_K);
    cudaFuncSetAttribute(k_gemm_mma,cudaFuncAttributeMaxDynamicSharedMemorySize, SMEM_GMM);

    k_prep<<<1024, 256>>>(w1r, w1i, w2r, w2i, b1r, b1i, b2r, b2i, fw);

    k_fwd_mma<<<BB*CC, 512, SMEM_K>>>(x);

    dim3 g2((BB*NPOS)/128, NBQ);
    k_mlp_mma<<<g2, 512, SMEM_K>>>();

    k_inv_mma<<<BB*CC, 512, SMEM_K>>>(x);

    dim3 gg(4, BB*16384/128);
    k_gemm_mma<<<gg, 256, SMEM_GMM>>>(x, out);
}